// round 3
// baseline (speedup 1.0000x reference)
#include <cuda_runtime.h>
#include <math.h>

#define NB     4
#define SEQ    2048
#define DMODEL 1024
#define NHEADS 16
#define DH     64
#define MROWS  (NB*SEQ)       // 8192
#define NEGINF -1e30f

// Scratch (static device arrays are the only legal scratch).
// g_Q doubles as the attention-output buffer: each attention block consumes
// its own Q tile (into smem) before overwriting those same rows with A.
__device__ float g_Q[MROWS*DMODEL];
__device__ float g_K[MROWS*DMODEL];
__device__ float g_V[MROWS*DMODEL];

// ---------------------------------------------------------------------------
// GEMM: C[M,N] = A[M,K] @ B[K,N] + bias[N]   (all row-major fp32)
// 128x128 block, 8x8 per-thread microtile, BK=8, 256 threads.
// src_sel: 0 -> A = Aext (harness input x), 1 -> A = g_Q (attention output)
// dst_sel: 0 -> g_Q, 1 -> g_K, 2 -> g_V, 3 -> Cext (harness d_out)
// ---------------------------------------------------------------------------
__global__ __launch_bounds__(256) void gemm_bias_kernel(
    const float* __restrict__ Aext, const float* __restrict__ B,
    const float* __restrict__ bias, float* __restrict__ Cext,
    int src_sel, int dst_sel, int M, int N, int K)
{
    const float* A = (src_sel == 0) ? Aext : (const float*)g_Q;
    float* C = (dst_sel == 0) ? g_Q
             : (dst_sel == 1) ? g_K
             : (dst_sel == 2) ? g_V
             : Cext;

    const int BM = 128, BN = 128, BK = 8;
    __shared__ float As[BK][BM];   // transposed: As[k][m]
    __shared__ float Bs[BK][BN];

    const int tid = threadIdx.x;
    const int bm = blockIdx.y * BM;
    const int bn = blockIdx.x * BN;
    const int tx = tid & 15;       // 0..15  (output col group)
    const int ty = tid >> 4;       // 0..15  (output row group)

    // global-load assignments
    const int arow = tid >> 1;            // 0..127
    const int acol = (tid & 1) << 2;      // 0 or 4
    const int brow = tid >> 5;            // 0..7
    const int bcol = (tid & 31) << 2;     // 0..124

    const float* Aptr = A + (size_t)(bm + arow) * K + acol;
    const float* Bptr = B + (size_t)brow * N + bn + bcol;

    float acc[8][8];
#pragma unroll
    for (int i = 0; i < 8; i++)
#pragma unroll
        for (int j = 0; j < 8; j++) acc[i][j] = 0.f;

    for (int k0 = 0; k0 < K; k0 += BK) {
        float4 av = *(const float4*)(Aptr + k0);
        float4 bv = *(const float4*)(Bptr + (size_t)k0 * N);
        __syncthreads();    // previous compute done before smem overwrite
        As[acol + 0][arow] = av.x;
        As[acol + 1][arow] = av.y;
        As[acol + 2][arow] = av.z;
        As[acol + 3][arow] = av.w;
        *(float4*)&Bs[brow][bcol] = bv;
        __syncthreads();

#pragma unroll
        for (int kk = 0; kk < BK; kk++) {
            float4 a0 = *(const float4*)&As[kk][ty * 8];
            float4 a1 = *(const float4*)&As[kk][ty * 8 + 4];
            float4 b0 = *(const float4*)&Bs[kk][tx * 8];
            float4 b1 = *(const float4*)&Bs[kk][tx * 8 + 4];
            float ra[8] = {a0.x, a0.y, a0.z, a0.w, a1.x, a1.y, a1.z, a1.w};
            float rb[8] = {b0.x, b0.y, b0.z, b0.w, b1.x, b1.y, b1.z, b1.w};
#pragma unroll
            for (int i = 0; i < 8; i++)
#pragma unroll
                for (int j = 0; j < 8; j++)
                    acc[i][j] += ra[i] * rb[j];
        }
    }

#pragma unroll
    for (int i = 0; i < 8; i++) {
        const int row = bm + ty * 8 + i;
#pragma unroll
        for (int j = 0; j < 8; j += 4) {
            const int col = bn + tx * 8 + j;
            float4 o;
            o.x = acc[i][j + 0] + bias[col + 0];
            o.y = acc[i][j + 1] + bias[col + 1];
            o.z = acc[i][j + 2] + bias[col + 2];
            o.w = acc[i][j + 3] + bias[col + 3];
            *(float4*)&C[(size_t)row * N + col] = o;
        }
    }
}

// ---------------------------------------------------------------------------
// Flash attention over contiguous (SEQ, DH) head slabs.
// grid = (SEQ/64, NB*NHEADS), block = 128 threads (4 warps).
// Each warp owns 16 query rows; each thread a 4x8 (row x key-col) microtile.
// Online softmax; PAD=65 avoids bank conflicts on column reads.
// Output is written IN PLACE over this block's Q rows (consumed at start).
// ---------------------------------------------------------------------------
#define BQ  64
#define BKC 64
#define PAD 65

__global__ __launch_bounds__(128) void attn_kernel(const int* __restrict__ mask)
{
    extern __shared__ float sm[];
    float* Qs = sm;                  // BQ  * PAD
    float* Ks = Qs + BQ  * PAD;      // BKC * PAD
    float* Vs = Ks + BKC * PAD;      // BKC * PAD
    float* Ps = Vs + BKC * PAD;      // BQ  * PAD

    const int tid  = threadIdx.x;
    const int warp = tid >> 5;
    const int lane = tid & 31;

    const int nh = blockIdx.y;           // 0..63 == n*16 + h
    const int n  = nh >> 4;
    const int qt = blockIdx.x;           // 0..31
    const size_t hb = (size_t)nh * SEQ * DH;

    const float* Qb = g_Q + hb + (size_t)qt * BQ * DH;
    const float* Kb = g_K + hb;
    const float* Vb = g_V + hb;
    float*       Ab = g_Q + hb + (size_t)qt * BQ * DH;   // in-place over Q tile
    const int*   mk = mask + n * SEQ;

    // load Q tile (64x64) into smem (after this, the rows may be overwritten)
    for (int v = tid; v < BQ * DH / 4; v += 128) {
        int r = v >> 4, c = (v & 15) << 2;
        float4 q = *(const float4*)(Qb + r * DH + c);
        float* dst = Qs + r * PAD + c;
        dst[0] = q.x; dst[1] = q.y; dst[2] = q.z; dst[3] = q.w;
    }

    const int tr   = lane >> 3;          // 0..3
    const int tc   = lane & 7;           // 0..7
    const int row0 = warp * 16 + tr * 4; // local Q row base
    const int col0 = tc * 8;             // local key col base

    float m_i[4], l_i[4], O[4][8];
#pragma unroll
    for (int i = 0; i < 4; i++) {
        m_i[i] = -INFINITY; l_i[i] = 0.f;
#pragma unroll
        for (int j = 0; j < 8; j++) O[i][j] = 0.f;
    }

    const float* qp[4];
#pragma unroll
    for (int i = 0; i < 4; i++) qp[i] = Qs + (row0 + i) * PAD;
    const float* kc[8];
#pragma unroll
    for (int j = 0; j < 8; j++) kc[j] = Ks + (col0 + j) * PAD;

    for (int kb = 0; kb < SEQ / BKC; kb++) {
        __syncthreads();   // prior iteration's Ps/Ks/Vs reads done
        for (int v = tid; v < BKC * DH / 4; v += 128) {
            int r = v >> 4, c = (v & 15) << 2;
            float4 kq = *(const float4*)(Kb + (size_t)(kb * BKC + r) * DH + c);
            float4 vq = *(const float4*)(Vb + (size_t)(kb * BKC + r) * DH + c);
            float* kd = Ks + r * PAD + c;
            kd[0] = kq.x; kd[1] = kq.y; kd[2] = kq.z; kd[3] = kq.w;
            float* vd = Vs + r * PAD + c;
            vd[0] = vq.x; vd[1] = vq.y; vd[2] = vq.z; vd[3] = vq.w;
        }
        __syncthreads();

        // ---- S = Q K^T (4x8 per thread) ----
        float s[4][8];
#pragma unroll
        for (int i = 0; i < 4; i++)
#pragma unroll
            for (int j = 0; j < 8; j++) s[i][j] = 0.f;

#pragma unroll 16
        for (int d = 0; d < DH; d++) {
            float q0 = qp[0][d], q1 = qp[1][d], q2 = qp[2][d], q3 = qp[3][d];
            float kv[8];
#pragma unroll
            for (int j = 0; j < 8; j++) kv[j] = kc[j][d];
#pragma unroll
            for (int j = 0; j < 8; j++) {
                s[0][j] += q0 * kv[j];
                s[1][j] += q1 * kv[j];
                s[2][j] += q2 * kv[j];
                s[3][j] += q3 * kv[j];
            }
        }

        // ---- scale + mask ----
        int mv[8];
#pragma unroll
        for (int j = 0; j < 8; j++) mv[j] = mk[kb * BKC + col0 + j];
#pragma unroll
        for (int i = 0; i < 4; i++)
#pragma unroll
            for (int j = 0; j < 8; j++)
                s[i][j] = (mv[j] != 0) ? s[i][j] * 0.125f : NEGINF;

        // ---- online softmax (row reductions across the 8 lanes sharing tr) ----
#pragma unroll
        for (int i = 0; i < 4; i++) {
            float mx = s[i][0];
#pragma unroll
            for (int j = 1; j < 8; j++) mx = fmaxf(mx, s[i][j]);
            mx = fmaxf(mx, __shfl_xor_sync(0xffffffffu, mx, 1));
            mx = fmaxf(mx, __shfl_xor_sync(0xffffffffu, mx, 2));
            mx = fmaxf(mx, __shfl_xor_sync(0xffffffffu, mx, 4));
            float mnew = fmaxf(m_i[i], mx);
            float sum = 0.f;
            float* pr = Ps + (row0 + i) * PAD + col0;
#pragma unroll
            for (int j = 0; j < 8; j++) {
                float p = __expf(s[i][j] - mnew);
                pr[j] = p;
                sum += p;
            }
            sum += __shfl_xor_sync(0xffffffffu, sum, 1);
            sum += __shfl_xor_sync(0xffffffffu, sum, 2);
            sum += __shfl_xor_sync(0xffffffffu, sum, 4);
            float corr = __expf(m_i[i] - mnew);
            l_i[i] = l_i[i] * corr + sum;
            m_i[i] = mnew;
#pragma unroll
            for (int j = 0; j < 8; j++) O[i][j] *= corr;
        }
        __syncwarp();   // Ps rows are warp-private; warp sync suffices

        // ---- O += P @ V ----
        const float* pp0 = Ps + (row0 + 0) * PAD;
        const float* pp1 = Ps + (row0 + 1) * PAD;
        const float* pp2 = Ps + (row0 + 2) * PAD;
        const float* pp3 = Ps + (row0 + 3) * PAD;
#pragma unroll 4
        for (int k = 0; k < BKC; k++) {
            float p0 = pp0[k], p1 = pp1[k], p2 = pp2[k], p3 = pp3[k];
            const float* vp = Vs + k * PAD + col0;
            float vv[8];
#pragma unroll
            for (int j = 0; j < 8; j++) vv[j] = vp[j];
#pragma unroll
            for (int j = 0; j < 8; j++) {
                O[0][j] += p0 * vv[j];
                O[1][j] += p1 * vv[j];
                O[2][j] += p2 * vv[j];
                O[3][j] += p3 * vv[j];
            }
        }
        __syncwarp();
    }

    // ---- epilogue: normalize and store in place over the Q tile ----
#pragma unroll
    for (int i = 0; i < 4; i++) {
        float inv = 1.f / l_i[i];
        float* op = Ab + (size_t)(row0 + i) * DH + col0;
#pragma unroll
        for (int j = 0; j < 8; j++) op[j] = O[i][j] * inv;
    }
}

// ---------------------------------------------------------------------------
extern "C" void kernel_launch(void* const* d_in, const int* in_sizes, int n_in,
                              void* d_out, int out_size)
{
    const float* x   = (const float*)d_in[0];
    const int*  mask = (const int*)  d_in[1];
    const float* wq  = (const float*)d_in[2];
    const float* bq  = (const float*)d_in[3];
    const float* wk  = (const float*)d_in[4];
    const float* bk  = (const float*)d_in[5];
    const float* wv  = (const float*)d_in[6];
    const float* bv  = (const float*)d_in[7];
    const float* wo  = (const float*)d_in[8];
    const float* bo  = (const float*)d_in[9];
    float* out = (float*)d_out;

    dim3 gblk(256);
    dim3 ggrd(DMODEL / 128, MROWS / 128);   // (8, 64)

    gemm_bias_kernel<<<ggrd, gblk>>>(x, wq, bq, out, 0, 0, MROWS, DMODEL, DMODEL);
    gemm_bias_kernel<<<ggrd, gblk>>>(x, wk, bk, out, 0, 1, MROWS, DMODEL, DMODEL);
    gemm_bias_kernel<<<ggrd, gblk>>>(x, wv, bv, out, 0, 2, MROWS, DMODEL, DMODEL);

    size_t smem = (size_t)(BQ * PAD + 2 * BKC * PAD + BQ * PAD) * sizeof(float); // 66,560 B
    cudaFuncSetAttribute(attn_kernel, cudaFuncAttributeMaxDynamicSharedMemorySize, (int)smem);
    attn_kernel<<<dim3(SEQ / BQ, NB * NHEADS), 128, smem>>>(mask);

    gemm_bias_kernel<<<ggrd, gblk>>>(x, wo, bo, out, 1, 3, MROWS, DMODEL, DMODEL);
}

// round 6
// speedup vs baseline: 1.2617x; 1.2617x over previous
#include <cuda_runtime.h>
#include <cuda_bf16.h>
#include <math.h>
#include <stdint.h>

#define NB     4
#define SEQ    2048
#define DMODEL 1024
#define NHEADS 16
#define DH     64
#define MROWS  8192
#define NEGINF -1e30f

// ---------------------------------------------------------------------------
// Static scratch
// ---------------------------------------------------------------------------
__device__ float g_Q[MROWS*DMODEL];
__device__ float g_K[MROWS*DMODEL];
__device__ float g_V[MROWS*DMODEL];
__device__ __nv_bfloat16 g_xh[MROWS*DMODEL];    // activation hi
__device__ __nv_bfloat16 g_xl[MROWS*DMODEL];    // activation lo
__device__ __nv_bfloat16 g_wth[DMODEL*DMODEL];  // weight^T hi  [N][K]
__device__ __nv_bfloat16 g_wtl[DMODEL*DMODEL];  // weight^T lo  [N][K]

// ---------------------------------------------------------------------------
// PTX helpers (sm_100 base target: mma.sync / ldmatrix / cp.async only)
// ---------------------------------------------------------------------------
__device__ __forceinline__ uint32_t smem_u32(const void* p) {
    uint32_t a;
    asm("{ .reg .u64 t; cvta.to.shared.u64 t, %1; cvt.u32.u64 %0, t; }" : "=r"(a) : "l"(p));
    return a;
}
#define CP_ASYNC16(saddr, gptr) \
    asm volatile("cp.async.cg.shared.global [%0], [%1], 16;" :: "r"(saddr), "l"(gptr))
#define CP_COMMIT() asm volatile("cp.async.commit_group;" ::: "memory")
#define CP_WAIT1()  asm volatile("cp.async.wait_group 1;" ::: "memory")
#define CP_WAIT0()  asm volatile("cp.async.wait_group 0;" ::: "memory")

#define LDSM_X4(r0, r1, r2, r3, addr) \
    asm volatile("ldmatrix.sync.aligned.m8n8.x4.shared.b16 {%0,%1,%2,%3}, [%4];" \
        : "=r"(r0), "=r"(r1), "=r"(r2), "=r"(r3) : "r"(addr))

__device__ __forceinline__ void mma_bf16(float* c, const uint32_t* a,
                                         uint32_t b0, uint32_t b1) {
    asm volatile(
        "mma.sync.aligned.m16n8k16.row.col.f32.bf16.bf16.f32 "
        "{%0,%1,%2,%3}, {%4,%5,%6,%7}, {%8,%9}, {%0,%1,%2,%3};"
        : "+f"(c[0]), "+f"(c[1]), "+f"(c[2]), "+f"(c[3])
        : "r"(a[0]), "r"(a[1]), "r"(a[2]), "r"(a[3]), "r"(b0), "r"(b1));
}

// ---------------------------------------------------------------------------
// fp32 -> bf16 hi/lo split.  src_sel: 0 = ext (input x), 1 = g_Q (attn out)
// ---------------------------------------------------------------------------
__global__ __launch_bounds__(256) void split_bf16(const float* __restrict__ ext,
                                                  int src_sel) {
    const float* src = src_sel ? (const float*)g_Q : ext;
    size_t i4 = ((size_t)blockIdx.x * 256 + threadIdx.x) * 4;
    if (i4 >= (size_t)MROWS * DMODEL) return;
    float4 v = *(const float4*)(src + i4);
    float a[4] = {v.x, v.y, v.z, v.w};
#pragma unroll
    for (int j = 0; j < 4; j++) {
        __nv_bfloat16 hi = __float2bfloat16(a[j]);
        __nv_bfloat16 lo = __float2bfloat16(a[j] - __bfloat162float(hi));
        g_xh[i4 + j] = hi;
        g_xl[i4 + j] = lo;
    }
}

// ---------------------------------------------------------------------------
// Weight transpose + split: w [K][N] fp32 -> g_wth/g_wtl [N][K] bf16
// ---------------------------------------------------------------------------
__global__ __launch_bounds__(256) void transpose_split(const float* __restrict__ w) {
    __shared__ float t[32][33];
    const int tx = threadIdx.x, ty = threadIdx.y;    // 32 x 8
    const int n0 = blockIdx.x * 32, k0 = blockIdx.y * 32;
#pragma unroll
    for (int i = 0; i < 4; i++)
        t[ty + i * 8][tx] = w[(size_t)(k0 + ty + i * 8) * DMODEL + n0 + tx];
    __syncthreads();
#pragma unroll
    for (int i = 0; i < 4; i++) {
        float v = t[tx][ty + i * 8];                 // = w[k0+tx][n0+ty+i*8]
        __nv_bfloat16 hi = __float2bfloat16(v);
        __nv_bfloat16 lo = __float2bfloat16(v - __bfloat162float(hi));
        size_t o = (size_t)(n0 + ty + i * 8) * DMODEL + (k0 + tx);
        g_wth[o] = hi;
        g_wtl[o] = lo;
    }
}

// ---------------------------------------------------------------------------
// mma.sync bf16-split GEMM: C[8192,1024] = split(A) @ split(W^T)^T + bias
// 128x128 CTA tile, 256 threads (8 warps, each 32x64). BK=32, 2-stage
// cp.async pipeline. 3 terms: Ah*Bh + Ah*Bl + Al*Bh, fp32 accumulate.
// B stored [N][K] row-major == col-major B: plain (non-trans) ldmatrix
// yields the m16n8k16 B fragment directly.
// dst_sel: 0 -> g_Q, 1 -> g_K, 2 -> g_V, 3 -> Cext
// ---------------------------------------------------------------------------
#define MAT_BYTES   10240      // 128 * 80
#define STG_BYTES   40960      // 4 mats
#define ROW_B       80         // padded row stride in bytes (32 bf16 + 8 pad)
#define NCHUNK      32         // 1024 / 32

__global__ __launch_bounds__(256) void gemm_mma(const float* __restrict__ bias,
                                                float* __restrict__ Cext,
                                                int dst_sel) {
    extern __shared__ char smem[];
    const uint32_t sb = smem_u32(smem);
    const int tid  = threadIdx.x;
    const int wid  = tid >> 5;
    const int lane = tid & 31;
    const int wm = wid & 3;          // 0..3 -> m offset wm*32
    const int wn = wid >> 2;         // 0..1 -> n offset wn*64
    const int bn = blockIdx.x * 128;
    const int bm = blockIdx.y * 128;

    float c[2][8][4];
#pragma unroll
    for (int mt = 0; mt < 2; mt++)
#pragma unroll
        for (int nt = 0; nt < 8; nt++)
#pragma unroll
            for (int r = 0; r < 4; r++) c[mt][nt][r] = 0.f;

    // cp.async issue assignment: 2048 16B ops per chunk, 8 per thread
    auto issue = [&](int chunk, int stage) {
        const int k0 = chunk * 32;
        const uint32_t stg = sb + stage * STG_BYTES;
#pragma unroll
        for (int i = 0; i < 8; i++) {
            const int idx = i * 256 + tid;
            const int mat = idx >> 9;
            const int row = (idx >> 2) & 127;
            const int seg = idx & 3;
            const uint32_t sa = stg + mat * MAT_BYTES + row * ROW_B + seg * 16;
            const __nv_bfloat16* gp;
            if (mat == 0)      gp = g_xh  + (size_t)(bm + row) * DMODEL + k0 + seg * 8;
            else if (mat == 1) gp = g_xl  + (size_t)(bm + row) * DMODEL + k0 + seg * 8;
            else if (mat == 2) gp = g_wth + (size_t)(bn + row) * DMODEL + k0 + seg * 8;
            else               gp = g_wtl + (size_t)(bn + row) * DMODEL + k0 + seg * 8;
            CP_ASYNC16(sa, gp);
        }
        CP_COMMIT();
    };

    issue(0, 0);

    // ldmatrix lane-address components
    const int lr  = lane & 7;
    const int lh8 = (lane >> 3) & 1;
    const int lh16 = lane >> 4;

    for (int chunk = 0; chunk < NCHUNK; chunk++) {
        if (chunk + 1 < NCHUNK) issue(chunk + 1, (chunk + 1) & 1);
        if (chunk + 1 < NCHUNK) { CP_WAIT1(); } else { CP_WAIT0(); }
        __syncthreads();

        const uint32_t stg = sb + (chunk & 1) * STG_BYTES;
        const uint32_t Ah = stg;
        const uint32_t Al = stg + MAT_BYTES;
        const uint32_t Bh = stg + 2 * MAT_BYTES;
        const uint32_t Bl = stg + 3 * MAT_BYTES;

#pragma unroll
        for (int term = 0; term < 3; term++) {
            const uint32_t aB = (term == 2) ? Al : Ah;
            const uint32_t bB = (term == 1) ? Bl : Bh;
#pragma unroll
            for (int ks = 0; ks < 2; ks++) {
                const int kb = ks * 32;   // 16 bf16 = 32 bytes
                uint32_t a[2][4];
#pragma unroll
                for (int mt = 0; mt < 2; mt++) {
                    const uint32_t addr = aB
                        + (uint32_t)(wm * 32 + mt * 16 + lr + 8 * lh8) * ROW_B
                        + kb + 16 * lh16;
                    LDSM_X4(a[mt][0], a[mt][1], a[mt][2], a[mt][3], addr);
                }
#pragma unroll
                for (int np = 0; np < 4; np++) {   // n-tile pairs (16 n each)
                    uint32_t b0, b1, b2, b3;
                    // B rows are n; m0/m1 = n0-7 x (k0-7, k8-15), m2/m3 = n8-15
                    const uint32_t addr = bB
                        + (uint32_t)(wn * 64 + np * 16 + lr + 8 * lh16) * ROW_B
                        + kb + 16 * lh8;
                    LDSM_X4(b0, b1, b2, b3, addr);
#pragma unroll
                    for (int mt = 0; mt < 2; mt++) {
                        mma_bf16(c[mt][np * 2 + 0], a[mt], b0, b1);
                        mma_bf16(c[mt][np * 2 + 1], a[mt], b2, b3);
                    }
                }
            }
        }
        __syncthreads();
    }

    float* C = (dst_sel == 0) ? g_Q
             : (dst_sel == 1) ? g_K
             : (dst_sel == 2) ? g_V
             : Cext;

    const int rg = lane >> 2;            // 0..7
    const int cg = (lane & 3) * 2;       // 0,2,4,6
#pragma unroll
    for (int mt = 0; mt < 2; mt++) {
#pragma unroll
        for (int nt = 0; nt < 8; nt++) {
            const int row = bm + wm * 32 + mt * 16 + rg;
            const int col = bn + wn * 64 + nt * 8 + cg;
            const float b0 = bias[col], b1 = bias[col + 1];
            float2 v0 = make_float2(c[mt][nt][0] + b0, c[mt][nt][1] + b1);
            float2 v1 = make_float2(c[mt][nt][2] + b0, c[mt][nt][3] + b1);
            *(float2*)&C[(size_t)row * DMODEL + col] = v0;
            *(float2*)&C[(size_t)(row + 8) * DMODEL + col] = v1;
        }
    }
}

// ---------------------------------------------------------------------------
// Flash attention (unchanged): fp32 SIMT, in-place over g_Q.
// ---------------------------------------------------------------------------
#define BQ  64
#define BKC 64
#define PAD 65

__global__ __launch_bounds__(128) void attn_kernel(const int* __restrict__ mask)
{
    extern __shared__ float sm[];
    float* Qs = sm;
    float* Ks = Qs + BQ  * PAD;
    float* Vs = Ks + BKC * PAD;
    float* Ps = Vs + BKC * PAD;

    const int tid  = threadIdx.x;
    const int warp = tid >> 5;
    const int lane = tid & 31;

    const int nh = blockIdx.y;
    const int n  = nh >> 4;
    const int qt = blockIdx.x;
    const size_t hb = (size_t)nh * SEQ * DH;

    const float* Qb = g_Q + hb + (size_t)qt * BQ * DH;
    const float* Kb = g_K + hb;
    const float* Vb = g_V + hb;
    float*       Ab = g_Q + hb + (size_t)qt * BQ * DH;
    const int*   mk = mask + n * SEQ;

    for (int v = tid; v < BQ * DH / 4; v += 128) {
        int r = v >> 4, c = (v & 15) << 2;
        float4 q = *(const float4*)(Qb + r * DH + c);
        float* dst = Qs + r * PAD + c;
        dst[0] = q.x; dst[1] = q.y; dst[2] = q.z; dst[3] = q.w;
    }

    const int tr   = lane >> 3;
    const int tc   = lane & 7;
    const int row0 = warp * 16 + tr * 4;
    const int col0 = tc * 8;

    float m_i[4], l_i[4], O[4][8];
#pragma unroll
    for (int i = 0; i < 4; i++) {
        m_i[i] = -INFINITY; l_i[i] = 0.f;
#pragma unroll
        for (int j = 0; j < 8; j++) O[i][j] = 0.f;
    }

    const float* qp[4];
#pragma unroll
    for (int i = 0; i < 4; i++) qp[i] = Qs + (row0 + i) * PAD;
    const float* kc[8];
#pragma unroll
    for (int j = 0; j < 8; j++) kc[j] = Ks + (col0 + j) * PAD;

    for (int kb = 0; kb < SEQ / BKC; kb++) {
        __syncthreads();
        for (int v = tid; v < BKC * DH / 4; v += 128) {
            int r = v >> 4, c = (v & 15) << 2;
            float4 kq = *(const float4*)(Kb + (size_t)(kb * BKC + r) * DH + c);
            float4 vq = *(const float4*)(Vb + (size_t)(kb * BKC + r) * DH + c);
            float* kd = Ks + r * PAD + c;
            kd[0] = kq.x; kd[1] = kq.y; kd[2] = kq.z; kd[3] = kq.w;
            float* vd = Vs + r * PAD + c;
            vd[0] = vq.x; vd[1] = vq.y; vd[2] = vq.z; vd[3] = vq.w;
        }
        __syncthreads();

        float s[4][8];
#pragma unroll
        for (int i = 0; i < 4; i++)
#pragma unroll
            for (int j = 0; j < 8; j++) s[i][j] = 0.f;

#pragma unroll 16
        for (int d = 0; d < DH; d++) {
            float q0 = qp[0][d], q1 = qp[1][d], q2 = qp[2][d], q3 = qp[3][d];
            float kv[8];
#pragma unroll
            for (int j = 0; j < 8; j++) kv[j] = kc[j][d];
#pragma unroll
            for (int j = 0; j < 8; j++) {
                s[0][j] += q0 * kv[j];
                s[1][j] += q1 * kv[j];
                s[2][j] += q2 * kv[j];
                s[3][j] += q3 * kv[j];
            }
        }

        int mv[8];
#pragma unroll
        for (int j = 0; j < 8; j++) mv[j] = mk[kb * BKC + col0 + j];
#pragma unroll
        for (int i = 0; i < 4; i++)
#pragma unroll
            for (int j = 0; j < 8; j++)
                s[i][j] = (mv[j] != 0) ? s[i][j] * 0.125f : NEGINF;

#pragma unroll
        for (int i = 0; i < 4; i++) {
            float mx = s[i][0];
#pragma unroll
            for (int j = 1; j < 8; j++) mx = fmaxf(mx, s[i][j]);
            mx = fmaxf(mx, __shfl_xor_sync(0xffffffffu, mx, 1));
            mx = fmaxf(mx, __shfl_xor_sync(0xffffffffu, mx, 2));
            mx = fmaxf(mx, __shfl_xor_sync(0xffffffffu, mx, 4));
            float mnew = fmaxf(m_i[i], mx);
            float sum = 0.f;
            float* pr = Ps + (row0 + i) * PAD + col0;
#pragma unroll
            for (int j = 0; j < 8; j++) {
                float p = __expf(s[i][j] - mnew);
                pr[j] = p;
                sum += p;
            }
            sum += __shfl_xor_sync(0xffffffffu, sum, 1);
            sum += __shfl_xor_sync(0xffffffffu, sum, 2);
            sum += __shfl_xor_sync(0xffffffffu, sum, 4);
            float corr = __expf(m_i[i] - mnew);
            l_i[i] = l_i[i] * corr + sum;
            m_i[i] = mnew;
#pragma unroll
            for (int j = 0; j < 8; j++) O[i][j] *= corr;
        }
        __syncwarp();

        const float* pp0 = Ps + (row0 + 0) * PAD;
        const float* pp1 = Ps + (row0 + 1) * PAD;
        const float* pp2 = Ps + (row0 + 2) * PAD;
        const float* pp3 = Ps + (row0 + 3) * PAD;
#pragma unroll 4
        for (int k = 0; k < BKC; k++) {
            float p0 = pp0[k], p1 = pp1[k], p2 = pp2[k], p3 = pp3[k];
            const float* vp = Vs + k * PAD + col0;
            float vv[8];
#pragma unroll
            for (int j = 0; j < 8; j++) vv[j] = vp[j];
#pragma unroll
            for (int j = 0; j < 8; j++) {
                O[0][j] += p0 * vv[j];
                O[1][j] += p1 * vv[j];
                O[2][j] += p2 * vv[j];
                O[3][j] += p3 * vv[j];
            }
        }
        __syncwarp();
    }

#pragma unroll
    for (int i = 0; i < 4; i++) {
        float inv = 1.f / l_i[i];
        float* op = Ab + (size_t)(row0 + i) * DH + col0;
#pragma unroll
        for (int j = 0; j < 8; j++) op[j] = O[i][j] * inv;
    }
}

// ---------------------------------------------------------------------------
extern "C" void kernel_launch(void* const* d_in, const int* in_sizes, int n_in,
                              void* d_out, int out_size)
{
    const float* x   = (const float*)d_in[0];
    const int*  mask = (const int*)  d_in[1];
    const float* wq  = (const float*)d_in[2];
    const float* bq  = (const float*)d_in[3];
    const float* wk  = (const float*)d_in[4];
    const float* bk  = (const float*)d_in[5];
    const float* wv  = (const float*)d_in[6];
    const float* bv  = (const float*)d_in[7];
    const float* wo  = (const float*)d_in[8];
    const float* bo  = (const float*)d_in[9];
    float* out = (float*)d_out;

    const int gemm_smem = 2 * STG_BYTES;            // 81920 B
    cudaFuncSetAttribute(gemm_mma, cudaFuncAttributeMaxDynamicSharedMemorySize, gemm_smem);

    dim3 tgrid(DMODEL / 32, DMODEL / 32), tblk(32, 8);
    dim3 ggrid(DMODEL / 128, MROWS / 128);          // (8, 64)
    const int nsplit = (MROWS * DMODEL / 4 + 255) / 256;

    // split x once
    split_bf16<<<nsplit, 256>>>(x, 0);

    // Q, K, V projections
    transpose_split<<<tgrid, tblk>>>(wq);
    gemm_mma<<<ggrid, 256, gemm_smem>>>(bq, out, 0);
    transpose_split<<<tgrid, tblk>>>(wk);
    gemm_mma<<<ggrid, 256, gemm_smem>>>(bk, out, 1);
    transpose_split<<<tgrid, tblk>>>(wv);
    gemm_mma<<<ggrid, 256, gemm_smem>>>(bv, out, 2);

    // attention (in place over g_Q)
    size_t asmem = (size_t)(2 * BQ * PAD + 2 * BKC * PAD) * sizeof(float);
    cudaFuncSetAttribute(attn_kernel, cudaFuncAttributeMaxDynamicSharedMemorySize, (int)asmem);
    attn_kernel<<<dim3(SEQ / BQ, NB * NHEADS), 128, asmem>>>(mask);

    // output projection
    split_bf16<<<nsplit, 256>>>(x, 1);              // reads g_Q (attn output)
    transpose_split<<<tgrid, tblk>>>(wo);
    gemm_mma<<<ggrid, 256, gemm_smem>>>(bo, out, 3);
}

// round 7
// speedup vs baseline: 2.4951x; 1.9776x over previous
#include <cuda_runtime.h>
#include <cuda_bf16.h>
#include <math.h>
#include <stdint.h>

#define NB     4
#define SEQ    2048
#define DMODEL 1024
#define NHEADS 16
#define DH     64
#define MROWS  8192
#define NEGINF -1e30f

// ---------------------------------------------------------------------------
// Static scratch
// ---------------------------------------------------------------------------
__device__ float g_Q[MROWS*DMODEL];
__device__ float g_K[MROWS*DMODEL];
__device__ float g_V[MROWS*DMODEL];
__device__ __nv_bfloat16 g_xh[MROWS*DMODEL];    // activation hi
__device__ __nv_bfloat16 g_xl[MROWS*DMODEL];    // activation lo
__device__ __nv_bfloat16 g_wth[DMODEL*DMODEL];  // weight^T hi  [N][K]
__device__ __nv_bfloat16 g_wtl[DMODEL*DMODEL];  // weight^T lo  [N][K]

// ---------------------------------------------------------------------------
// PTX helpers (sm_100 base target: mma.sync / ldmatrix / cp.async only)
// ---------------------------------------------------------------------------
__device__ __forceinline__ uint32_t smem_u32(const void* p) {
    uint32_t a;
    asm("{ .reg .u64 t; cvta.to.shared.u64 t, %1; cvt.u32.u64 %0, t; }" : "=r"(a) : "l"(p));
    return a;
}
#define CP_ASYNC16(saddr, gptr) \
    asm volatile("cp.async.cg.shared.global [%0], [%1], 16;" :: "r"(saddr), "l"(gptr))
#define CP_COMMIT() asm volatile("cp.async.commit_group;" ::: "memory")
#define CP_WAIT1()  asm volatile("cp.async.wait_group 1;" ::: "memory")
#define CP_WAIT0()  asm volatile("cp.async.wait_group 0;" ::: "memory")

#define LDSM_X4(r0, r1, r2, r3, addr) \
    asm volatile("ldmatrix.sync.aligned.m8n8.x4.shared.b16 {%0,%1,%2,%3}, [%4];" \
        : "=r"(r0), "=r"(r1), "=r"(r2), "=r"(r3) : "r"(addr))
#define LDSM_X4T(r0, r1, r2, r3, addr) \
    asm volatile("ldmatrix.sync.aligned.m8n8.x4.trans.shared.b16 {%0,%1,%2,%3}, [%4];" \
        : "=r"(r0), "=r"(r1), "=r"(r2), "=r"(r3) : "r"(addr))

__device__ __forceinline__ void mma_bf16(float* c, const uint32_t* a,
                                         uint32_t b0, uint32_t b1) {
    asm volatile(
        "mma.sync.aligned.m16n8k16.row.col.f32.bf16.bf16.f32 "
        "{%0,%1,%2,%3}, {%4,%5,%6,%7}, {%8,%9}, {%0,%1,%2,%3};"
        : "+f"(c[0]), "+f"(c[1]), "+f"(c[2]), "+f"(c[3])
        : "r"(a[0]), "r"(a[1]), "r"(a[2]), "r"(a[3]), "r"(b0), "r"(b1));
}

// split one float4 into bf16 hi/lo pairs and store to smem (8 bytes each)
__device__ __forceinline__ void split_store4(char* smp, int hoff, int loff, float4 v) {
    __nv_bfloat16 h0 = __float2bfloat16(v.x);
    __nv_bfloat16 h1 = __float2bfloat16(v.y);
    __nv_bfloat16 h2 = __float2bfloat16(v.z);
    __nv_bfloat16 h3 = __float2bfloat16(v.w);
    __nv_bfloat16 l0 = __float2bfloat16(v.x - __bfloat162float(h0));
    __nv_bfloat16 l1 = __float2bfloat16(v.y - __bfloat162float(h1));
    __nv_bfloat16 l2 = __float2bfloat16(v.z - __bfloat162float(h2));
    __nv_bfloat16 l3 = __float2bfloat16(v.w - __bfloat162float(h3));
    *(__nv_bfloat162*)(smp + hoff)     = __halves2bfloat162(h0, h1);
    *(__nv_bfloat162*)(smp + hoff + 4) = __halves2bfloat162(h2, h3);
    *(__nv_bfloat162*)(smp + loff)     = __halves2bfloat162(l0, l1);
    *(__nv_bfloat162*)(smp + loff + 4) = __halves2bfloat162(l2, l3);
}

// ---------------------------------------------------------------------------
// fp32 -> bf16 hi/lo split.  src_sel: 0 = ext (input x), 1 = g_Q (attn out)
// ---------------------------------------------------------------------------
__global__ __launch_bounds__(256) void split_bf16(const float* __restrict__ ext,
                                                  int src_sel) {
    const float* src = src_sel ? (const float*)g_Q : ext;
    size_t i4 = ((size_t)blockIdx.x * 256 + threadIdx.x) * 4;
    if (i4 >= (size_t)MROWS * DMODEL) return;
    float4 v = *(const float4*)(src + i4);
    float a[4] = {v.x, v.y, v.z, v.w};
#pragma unroll
    for (int j = 0; j < 4; j++) {
        __nv_bfloat16 hi = __float2bfloat16(a[j]);
        __nv_bfloat16 lo = __float2bfloat16(a[j] - __bfloat162float(hi));
        g_xh[i4 + j] = hi;
        g_xl[i4 + j] = lo;
    }
}

// ---------------------------------------------------------------------------
// Weight transpose + split: w [K][N] fp32 -> g_wth/g_wtl [N][K] bf16
// ---------------------------------------------------------------------------
__global__ __launch_bounds__(256) void transpose_split(const float* __restrict__ w) {
    __shared__ float t[32][33];
    const int tx = threadIdx.x, ty = threadIdx.y;    // 32 x 8
    const int n0 = blockIdx.x * 32, k0 = blockIdx.y * 32;
#pragma unroll
    for (int i = 0; i < 4; i++)
        t[ty + i * 8][tx] = w[(size_t)(k0 + ty + i * 8) * DMODEL + n0 + tx];
    __syncthreads();
#pragma unroll
    for (int i = 0; i < 4; i++) {
        float v = t[tx][ty + i * 8];
        __nv_bfloat16 hi = __float2bfloat16(v);
        __nv_bfloat16 lo = __float2bfloat16(v - __bfloat162float(hi));
        size_t o = (size_t)(n0 + ty + i * 8) * DMODEL + (k0 + tx);
        g_wth[o] = hi;
        g_wtl[o] = lo;
    }
}

// ---------------------------------------------------------------------------
// mma.sync bf16-split GEMM (unchanged from R6, proven)
// ---------------------------------------------------------------------------
#define MAT_BYTES   10240
#define STG_BYTES   40960
#define ROW_B       80
#define NCHUNK      32

__global__ __launch_bounds__(256) void gemm_mma(const float* __restrict__ bias,
                                                float* __restrict__ Cext,
                                                int dst_sel) {
    extern __shared__ char smem[];
    const uint32_t sb = smem_u32(smem);
    const int tid  = threadIdx.x;
    const int wid  = tid >> 5;
    const int lane = tid & 31;
    const int wm = wid & 3;
    const int wn = wid >> 2;
    const int bn = blockIdx.x * 128;
    const int bm = blockIdx.y * 128;

    float c[2][8][4];
#pragma unroll
    for (int mt = 0; mt < 2; mt++)
#pragma unroll
        for (int nt = 0; nt < 8; nt++)
#pragma unroll
            for (int r = 0; r < 4; r++) c[mt][nt][r] = 0.f;

    auto issue = [&](int chunk, int stage) {
        const int k0 = chunk * 32;
        const uint32_t stg = sb + stage * STG_BYTES;
#pragma unroll
        for (int i = 0; i < 8; i++) {
            const int idx = i * 256 + tid;
            const int mat = idx >> 9;
            const int row = (idx >> 2) & 127;
            const int seg = idx & 3;
            const uint32_t sa = stg + mat * MAT_BYTES + row * ROW_B + seg * 16;
            const __nv_bfloat16* gp;
            if (mat == 0)      gp = g_xh  + (size_t)(bm + row) * DMODEL + k0 + seg * 8;
            else if (mat == 1) gp = g_xl  + (size_t)(bm + row) * DMODEL + k0 + seg * 8;
            else if (mat == 2) gp = g_wth + (size_t)(bn + row) * DMODEL + k0 + seg * 8;
            else               gp = g_wtl + (size_t)(bn + row) * DMODEL + k0 + seg * 8;
            CP_ASYNC16(sa, gp);
        }
        CP_COMMIT();
    };

    issue(0, 0);

    const int lr  = lane & 7;
    const int lh8 = (lane >> 3) & 1;
    const int lh16 = lane >> 4;

    for (int chunk = 0; chunk < NCHUNK; chunk++) {
        if (chunk + 1 < NCHUNK) issue(chunk + 1, (chunk + 1) & 1);
        if (chunk + 1 < NCHUNK) { CP_WAIT1(); } else { CP_WAIT0(); }
        __syncthreads();

        const uint32_t stg = sb + (chunk & 1) * STG_BYTES;
        const uint32_t Ah = stg;
        const uint32_t Al = stg + MAT_BYTES;
        const uint32_t Bh = stg + 2 * MAT_BYTES;
        const uint32_t Bl = stg + 3 * MAT_BYTES;

#pragma unroll
        for (int term = 0; term < 3; term++) {
            const uint32_t aB = (term == 2) ? Al : Ah;
            const uint32_t bB = (term == 1) ? Bl : Bh;
#pragma unroll
            for (int ks = 0; ks < 2; ks++) {
                const int kb = ks * 32;
                uint32_t a[2][4];
#pragma unroll
                for (int mt = 0; mt < 2; mt++) {
                    const uint32_t addr = aB
                        + (uint32_t)(wm * 32 + mt * 16 + lr + 8 * lh8) * ROW_B
                        + kb + 16 * lh16;
                    LDSM_X4(a[mt][0], a[mt][1], a[mt][2], a[mt][3], addr);
                }
#pragma unroll
                for (int np = 0; np < 4; np++) {
                    uint32_t b0, b1, b2, b3;
                    const uint32_t addr = bB
                        + (uint32_t)(wn * 64 + np * 16 + lr + 8 * lh16) * ROW_B
                        + kb + 16 * lh8;
                    LDSM_X4(b0, b1, b2, b3, addr);
#pragma unroll
                    for (int mt = 0; mt < 2; mt++) {
                        mma_bf16(c[mt][np * 2 + 0], a[mt], b0, b1);
                        mma_bf16(c[mt][np * 2 + 1], a[mt], b2, b3);
                    }
                }
            }
        }
        __syncthreads();
    }

    float* C = (dst_sel == 0) ? g_Q
             : (dst_sel == 1) ? g_K
             : (dst_sel == 2) ? g_V
             : Cext;

    const int rg = lane >> 2;
    const int cg = (lane & 3) * 2;
#pragma unroll
    for (int mt = 0; mt < 2; mt++) {
#pragma unroll
        for (int nt = 0; nt < 8; nt++) {
            const int row = bm + wm * 32 + mt * 16 + rg;
            const int col = bn + wn * 64 + nt * 8 + cg;
            const float b0 = bias[col], b1 = bias[col + 1];
            float2 v0 = make_float2(c[mt][nt][0] + b0, c[mt][nt][1] + b1);
            float2 v1 = make_float2(c[mt][nt][2] + b0, c[mt][nt][3] + b1);
            *(float2*)&C[(size_t)row * DMODEL + col] = v0;
            *(float2*)&C[(size_t)(row + 8) * DMODEL + col] = v1;
        }
    }
}

// ---------------------------------------------------------------------------
// Tensor-core flash attention. 256 threads (8 warps), BQ=128, key blocks 64.
// All operands bf16 hi/lo split in smem (row stride 144B, ldmatrix
// conflict-free). S: A=Q non-trans, B=K non-trans (R6-proven mapping).
// PV: A=P non-trans, B=V via ldmatrix.trans. fp32 softmax, 3-term products.
// In-place output over this block's g_Q rows. 1/8 scale folded into Q split.
// ---------------------------------------------------------------------------
#define AROW    144
#define OFF_QH  0
#define OFF_QL  (128*AROW)
#define OFF_KH  (2*128*AROW)
#define OFF_KL  (OFF_KH + 64*AROW)
#define OFF_VH  (OFF_KL + 64*AROW)
#define OFF_VL  (OFF_VH + 64*AROW)
#define OFF_PH  (OFF_VL + 64*AROW)
#define OFF_PL  (OFF_PH + 128*AROW)
#define OFF_MSK (OFF_PL + 128*AROW)
#define ATT_SMEM (OFF_MSK + 256)

__global__ __launch_bounds__(256, 2) void attn_mma(const int* __restrict__ mask)
{
    extern __shared__ char sm[];
    const uint32_t sb = smem_u32(sm);
    const int tid  = threadIdx.x;
    const int wid  = tid >> 5;
    const int lane = tid & 31;
    const int lr   = lane & 7;
    const int lh8  = (lane >> 3) & 1;
    const int lh16 = lane >> 4;
    const int g    = lane >> 2;          // row group within m16
    const int t2   = (lane & 3) * 2;     // col pair base
    const int wm16 = wid * 16;           // warp's q-row base (0..112)

    const int nh = blockIdx.y;           // head slab 0..63
    const int nb = nh >> 4;
    const int qt = blockIdx.x;           // 0..15
    const size_t hb = (size_t)nh * SEQ * DH;
    const float* Qb = g_Q + hb + (size_t)qt * 128 * DH;
    const float* Kb = g_K + hb;
    const float* Vb = g_V + hb;
    float*       Ab = g_Q + hb + (size_t)qt * 128 * DH;
    const int*   mk = mask + nb * SEQ;

    // ---- load Q tile (128x64), scale folded, split to bf16 hi/lo ----
#pragma unroll
    for (int i = 0; i < 8; i++) {
        const int idx = i * 256 + tid;        // 2048 float4
        const int r = idx >> 4, c4 = (idx & 15) * 4;
        float4 q = *(const float4*)(Qb + r * DH + c4);
        q.x *= 0.125f; q.y *= 0.125f; q.z *= 0.125f; q.w *= 0.125f;
        const int off = r * AROW + c4 * 2;
        split_store4(sm, OFF_QH + off, OFF_QL + off, q);
    }

    float m0 = -INFINITY, m1 = -INFINITY, l0 = 0.f, l1 = 0.f;
    float co[8][4];
#pragma unroll
    for (int nt = 0; nt < 8; nt++)
#pragma unroll
        for (int r = 0; r < 4; r++) co[nt][r] = 0.f;

    for (int kb = 0; kb < SEQ / 64; kb++) {
        __syncthreads();   // prior iteration's K/V reads complete
        if (tid < 64) *(int*)(sm + OFF_MSK + tid * 4) = mk[kb * 64 + tid];
#pragma unroll
        for (int i = 0; i < 8; i++) {
            const int idx = i * 256 + tid;    // 2048 float4: first 1024 K, then V
            const int r = (idx >> 4) & 63, c4 = (idx & 15) * 4;
            const int off = r * AROW + c4 * 2;
            if (idx < 1024) {
                float4 v = *(const float4*)(Kb + (size_t)(kb * 64 + r) * DH + c4);
                split_store4(sm, OFF_KH + off, OFF_KL + off, v);
            } else {
                float4 v = *(const float4*)(Vb + (size_t)(kb * 64 + r) * DH + c4);
                split_store4(sm, OFF_VH + off, OFF_VL + off, v);
            }
        }
        __syncthreads();

        // ---- S = Q K^T (m16 x n64, 3 split terms) ----
        float cs[8][4];
#pragma unroll
        for (int nt = 0; nt < 8; nt++)
#pragma unroll
            for (int r = 0; r < 4; r++) cs[nt][r] = 0.f;

#pragma unroll
        for (int term = 0; term < 3; term++) {
            const uint32_t aT = sb + ((term == 2) ? OFF_QL : OFF_QH);
            const uint32_t bT = sb + ((term == 1) ? OFF_KL : OFF_KH);
#pragma unroll
            for (int ks = 0; ks < 4; ks++) {
                const int kk = ks * 16;
                uint32_t a[4];
                LDSM_X4(a[0], a[1], a[2], a[3],
                        aT + (uint32_t)(wm16 + lr + 8 * lh8) * AROW + kk * 2 + 16 * lh16);
#pragma unroll
                for (int np = 0; np < 4; np++) {
                    uint32_t b0, b1, b2, b3;
                    LDSM_X4(b0, b1, b2, b3,
                            bT + (uint32_t)(np * 16 + lr + 8 * lh16) * AROW + kk * 2 + 16 * lh8);
                    mma_bf16(cs[np * 2 + 0], a, b0, b1);
                    mma_bf16(cs[np * 2 + 1], a, b2, b3);
                }
            }
        }

        // ---- mask ----
#pragma unroll
        for (int nt = 0; nt < 8; nt++) {
            int2 mv = *(const int2*)(sm + OFF_MSK + (nt * 8 + t2) * 4);
            if (!mv.x) { cs[nt][0] = NEGINF; cs[nt][2] = NEGINF; }
            if (!mv.y) { cs[nt][1] = NEGINF; cs[nt][3] = NEGINF; }
        }

        // ---- online softmax (rows g and g+8) ----
        float mx0 = NEGINF, mx1 = NEGINF;
#pragma unroll
        for (int nt = 0; nt < 8; nt++) {
            mx0 = fmaxf(mx0, fmaxf(cs[nt][0], cs[nt][1]));
            mx1 = fmaxf(mx1, fmaxf(cs[nt][2], cs[nt][3]));
        }
        mx0 = fmaxf(mx0, __shfl_xor_sync(0xffffffffu, mx0, 1));
        mx0 = fmaxf(mx0, __shfl_xor_sync(0xffffffffu, mx0, 2));
        mx1 = fmaxf(mx1, __shfl_xor_sync(0xffffffffu, mx1, 1));
        mx1 = fmaxf(mx1, __shfl_xor_sync(0xffffffffu, mx1, 2));
        const float mn0 = fmaxf(m0, mx0), mn1 = fmaxf(m1, mx1);
        const float corr0 = __expf(m0 - mn0), corr1 = __expf(m1 - mn1);
        float s0 = 0.f, s1 = 0.f;
        const int prow0 = (wm16 + g) * AROW, prow1 = (wm16 + g + 8) * AROW;
#pragma unroll
        for (int nt = 0; nt < 8; nt++) {
            const int cb = (nt * 8 + t2) * 2;
            float p00 = __expf(cs[nt][0] - mn0);
            float p01 = __expf(cs[nt][1] - mn0);
            float p10 = __expf(cs[nt][2] - mn1);
            float p11 = __expf(cs[nt][3] - mn1);
            s0 += p00 + p01; s1 += p10 + p11;
            __nv_bfloat16 h0 = __float2bfloat16(p00), h1 = __float2bfloat16(p01);
            __nv_bfloat16 h2 = __float2bfloat16(p10), h3 = __float2bfloat16(p11);
            *(__nv_bfloat162*)(sm + OFF_PH + prow0 + cb) = __halves2bfloat162(h0, h1);
            *(__nv_bfloat162*)(sm + OFF_PH + prow1 + cb) = __halves2bfloat162(h2, h3);
            *(__nv_bfloat162*)(sm + OFF_PL + prow0 + cb) = __halves2bfloat162(
                __float2bfloat16(p00 - __bfloat162float(h0)),
                __float2bfloat16(p01 - __bfloat162float(h1)));
            *(__nv_bfloat162*)(sm + OFF_PL + prow1 + cb) = __halves2bfloat162(
                __float2bfloat16(p10 - __bfloat162float(h2)),
                __float2bfloat16(p11 - __bfloat162float(h3)));
        }
        s0 += __shfl_xor_sync(0xffffffffu, s0, 1);
        s0 += __shfl_xor_sync(0xffffffffu, s0, 2);
        s1 += __shfl_xor_sync(0xffffffffu, s1, 1);
        s1 += __shfl_xor_sync(0xffffffffu, s1, 2);
        l0 = l0 * corr0 + s0; m0 = mn0;
        l1 = l1 * corr1 + s1; m1 = mn1;
#pragma unroll
        for (int nt = 0; nt < 8; nt++) {
            co[nt][0] *= corr0; co[nt][1] *= corr0;
            co[nt][2] *= corr1; co[nt][3] *= corr1;
        }
        __syncwarp();   // P rows (warp-private) visible to ldmatrix

        // ---- O += P V (k = 64 keys, 3 split terms) ----
#pragma unroll
        for (int term = 0; term < 3; term++) {
            const uint32_t aT = sb + ((term == 2) ? OFF_PL : OFF_PH);
            const uint32_t bT = sb + ((term == 1) ? OFF_VL : OFF_VH);
#pragma unroll
            for (int ks = 0; ks < 4; ks++) {
                const int kk = ks * 16;
                uint32_t a[4];
                LDSM_X4(a[0], a[1], a[2], a[3],
                        aT + (uint32_t)(wm16 + lr + 8 * lh8) * AROW + kk * 2 + 16 * lh16);
#pragma unroll
                for (int np = 0; np < 4; np++) {
                    uint32_t b0, b1, b2, b3;
                    LDSM_X4T(b0, b1, b2, b3,
                             bT + (uint32_t)(kk + lr + 8 * lh8) * AROW + np * 32 + 16 * lh16);
                    mma_bf16(co[np * 2 + 0], a, b0, b1);
                    mma_bf16(co[np * 2 + 1], a, b2, b3);
                }
            }
        }
        __syncwarp();
    }

    // ---- epilogue: normalize, store fp32 in place over Q tile ----
    const float i0 = 1.f / l0, i1 = 1.f / l1;
    const int r0 = wm16 + g, r1 = wm16 + g + 8;
#pragma unroll
    for (int nt = 0; nt < 8; nt++) {
        const int col = nt * 8 + t2;
        *(float2*)(Ab + (size_t)r0 * DH + col) = make_float2(co[nt][0] * i0, co[nt][1] * i0);
        *(float2*)(Ab + (size_t)r1 * DH + col) = make_float2(co[nt][2] * i1, co[nt][3] * i1);
    }
}

// ---------------------------------------------------------------------------
extern "C" void kernel_launch(void* const* d_in, const int* in_sizes, int n_in,
                              void* d_out, int out_size)
{
    const float* x   = (const float*)d_in[0];
    const int*  mask = (const int*)  d_in[1];
    const float* wq  = (const float*)d_in[2];
    const float* bq  = (const float*)d_in[3];
    const float* wk  = (const float*)d_in[4];
    const float* bk  = (const float*)d_in[5];
    const float* wv  = (const float*)d_in[6];
    const float* bv  = (const float*)d_in[7];
    const float* wo  = (const float*)d_in[8];
    const float* bo  = (const float*)d_in[9];
    float* out = (float*)d_out;

    const int gemm_smem = 2 * STG_BYTES;            // 81920 B
    cudaFuncSetAttribute(gemm_mma, cudaFuncAttributeMaxDynamicSharedMemorySize, gemm_smem);
    cudaFuncSetAttribute(attn_mma, cudaFuncAttributeMaxDynamicSharedMemorySize, ATT_SMEM);

    dim3 tgrid(DMODEL / 32, DMODEL / 32), tblk(32, 8);
    dim3 ggrid(DMODEL / 128, MROWS / 128);          // (8, 64)
    const int nsplit = (MROWS * DMODEL / 4 + 255) / 256;

    split_bf16<<<nsplit, 256>>>(x, 0);

    transpose_split<<<tgrid, tblk>>>(wq);
    gemm_mma<<<ggrid, 256, gemm_smem>>>(bq, out, 0);
    transpose_split<<<tgrid, tblk>>>(wk);
    gemm_mma<<<ggrid, 256, gemm_smem>>>(bk, out, 1);
    transpose_split<<<tgrid, tblk>>>(wv);
    gemm_mma<<<ggrid, 256, gemm_smem>>>(bv, out, 2);

    attn_mma<<<dim3(SEQ / 128, NB * NHEADS), 256, ATT_SMEM>>>(mask);

    split_bf16<<<nsplit, 256>>>(x, 1);              // reads g_Q (attn output)
    transpose_split<<<tgrid, tblk>>>(wo);
    gemm_mma<<<ggrid, 256, gemm_smem>>>(bo, out, 3);
}

// round 9
// speedup vs baseline: 3.0590x; 1.2260x over previous
#include <cuda_runtime.h>
#include <cuda_bf16.h>
#include <math.h>
#include <stdint.h>

#define NB     4
#define SEQ    2048
#define DMODEL 1024
#define NHEADS 16
#define DH     64
#define MROWS  8192
#define NEGINF -1e30f

// ---------------------------------------------------------------------------
// Static scratch (all projection outputs live as pre-split bf16 hi/lo)
// ---------------------------------------------------------------------------
__device__ __nv_bfloat16 g_xh[MROWS*DMODEL];    // activation hi (also attn out)
__device__ __nv_bfloat16 g_xl[MROWS*DMODEL];    // activation lo
__device__ __nv_bfloat16 g_wth[DMODEL*DMODEL];  // weight^T hi  [N][K]
__device__ __nv_bfloat16 g_wtl[DMODEL*DMODEL];  // weight^T lo  [N][K]
__device__ __nv_bfloat16 g_qh[MROWS*DMODEL];    // Q hi (1/8 scale folded)
__device__ __nv_bfloat16 g_ql[MROWS*DMODEL];
__device__ __nv_bfloat16 g_kh[MROWS*DMODEL];
__device__ __nv_bfloat16 g_kl[MROWS*DMODEL];
__device__ __nv_bfloat16 g_vh[MROWS*DMODEL];
__device__ __nv_bfloat16 g_vl[MROWS*DMODEL];

// ---------------------------------------------------------------------------
// PTX helpers (sm_100 base target)
// ---------------------------------------------------------------------------
__device__ __forceinline__ uint32_t smem_u32(const void* p) {
    uint32_t a;
    asm("{ .reg .u64 t; cvta.to.shared.u64 t, %1; cvt.u32.u64 %0, t; }" : "=r"(a) : "l"(p));
    return a;
}
#define CP_ASYNC16(saddr, gptr) \
    asm volatile("cp.async.cg.shared.global [%0], [%1], 16;" :: "r"(saddr), "l"(gptr))
#define CP_COMMIT() asm volatile("cp.async.commit_group;" ::: "memory")
#define CP_WAIT1()  asm volatile("cp.async.wait_group 1;" ::: "memory")
#define CP_WAIT0()  asm volatile("cp.async.wait_group 0;" ::: "memory")

#define LDSM_X4(r0, r1, r2, r3, addr) \
    asm volatile("ldmatrix.sync.aligned.m8n8.x4.shared.b16 {%0,%1,%2,%3}, [%4];" \
        : "=r"(r0), "=r"(r1), "=r"(r2), "=r"(r3) : "r"(addr))
#define LDSM_X4T(r0, r1, r2, r3, addr) \
    asm volatile("ldmatrix.sync.aligned.m8n8.x4.trans.shared.b16 {%0,%1,%2,%3}, [%4];" \
        : "=r"(r0), "=r"(r1), "=r"(r2), "=r"(r3) : "r"(addr))

__device__ __forceinline__ void mma_bf16(float* c, const uint32_t* a,
                                         uint32_t b0, uint32_t b1) {
    asm volatile(
        "mma.sync.aligned.m16n8k16.row.col.f32.bf16.bf16.f32 "
        "{%0,%1,%2,%3}, {%4,%5,%6,%7}, {%8,%9}, {%0,%1,%2,%3};"
        : "+f"(c[0]), "+f"(c[1]), "+f"(c[2]), "+f"(c[3])
        : "r"(a[0]), "r"(a[1]), "r"(a[2]), "r"(a[3]), "r"(b0), "r"(b1));
}

__device__ __forceinline__ __nv_bfloat162 hi2(float a, float b) {
    return __halves2bfloat162(__float2bfloat16(a), __float2bfloat16(b));
}
__device__ __forceinline__ __nv_bfloat162 lo2(float a, float b) {
    __nv_bfloat16 ha = __float2bfloat16(a), hb = __float2bfloat16(b);
    return __halves2bfloat162(__float2bfloat16(a - __bfloat162float(ha)),
                              __float2bfloat16(b - __bfloat162float(hb)));
}

// ---------------------------------------------------------------------------
// fp32 -> bf16 hi/lo split of x
// ---------------------------------------------------------------------------
__global__ __launch_bounds__(256) void split_bf16(const float* __restrict__ src) {
    size_t i4 = ((size_t)blockIdx.x * 256 + threadIdx.x) * 4;
    if (i4 >= (size_t)MROWS * DMODEL) return;
    float4 v = *(const float4*)(src + i4);
    float a[4] = {v.x, v.y, v.z, v.w};
#pragma unroll
    for (int j = 0; j < 4; j++) {
        __nv_bfloat16 hi = __float2bfloat16(a[j]);
        __nv_bfloat16 lo = __float2bfloat16(a[j] - __bfloat162float(hi));
        g_xh[i4 + j] = hi;
        g_xl[i4 + j] = lo;
    }
}

// ---------------------------------------------------------------------------
// Weight transpose + split: w [K][N] fp32 -> g_wth/g_wtl [N][K] bf16
// ---------------------------------------------------------------------------
__global__ __launch_bounds__(256) void transpose_split(const float* __restrict__ w) {
    __shared__ float t[32][33];
    const int tx = threadIdx.x, ty = threadIdx.y;    // 32 x 8
    const int n0 = blockIdx.x * 32, k0 = blockIdx.y * 32;
#pragma unroll
    for (int i = 0; i < 4; i++)
        t[ty + i * 8][tx] = w[(size_t)(k0 + ty + i * 8) * DMODEL + n0 + tx];
    __syncthreads();
#pragma unroll
    for (int i = 0; i < 4; i++) {
        float v = t[tx][ty + i * 8];
        __nv_bfloat16 hi = __float2bfloat16(v);
        __nv_bfloat16 lo = __float2bfloat16(v - __bfloat162float(hi));
        size_t o = (size_t)(n0 + ty + i * 8) * DMODEL + (k0 + tx);
        g_wth[o] = hi;
        g_wtl[o] = lo;
    }
}

// ---------------------------------------------------------------------------
// mma.sync bf16-split GEMM. dst_sel 0/1/2: write split bf16 hi/lo to
// Q (x0.125 scale folded) / K / V.  dst_sel 3: fp32 to Cext.
// ---------------------------------------------------------------------------
#define MAT_BYTES   10240
#define STG_BYTES   40960
#define ROW_B       80
#define NCHUNK      32

__global__ __launch_bounds__(256) void gemm_mma(const float* __restrict__ bias,
                                                float* __restrict__ Cext,
                                                int dst_sel) {
    extern __shared__ char smem[];
    const uint32_t sb = smem_u32(smem);
    const int tid  = threadIdx.x;
    const int wid  = tid >> 5;
    const int lane = tid & 31;
    const int wm = wid & 3;
    const int wn = wid >> 2;
    const int bn = blockIdx.x * 128;
    const int bm = blockIdx.y * 128;

    float c[2][8][4];
#pragma unroll
    for (int mt = 0; mt < 2; mt++)
#pragma unroll
        for (int nt = 0; nt < 8; nt++)
#pragma unroll
            for (int r = 0; r < 4; r++) c[mt][nt][r] = 0.f;

    auto issue = [&](int chunk, int stage) {
        const int k0 = chunk * 32;
        const uint32_t stg = sb + stage * STG_BYTES;
#pragma unroll
        for (int i = 0; i < 8; i++) {
            const int idx = i * 256 + tid;
            const int mat = idx >> 9;
            const int row = (idx >> 2) & 127;
            const int seg = idx & 3;
            const uint32_t sa = stg + mat * MAT_BYTES + row * ROW_B + seg * 16;
            const __nv_bfloat16* gp;
            if (mat == 0)      gp = g_xh  + (size_t)(bm + row) * DMODEL + k0 + seg * 8;
            else if (mat == 1) gp = g_xl  + (size_t)(bm + row) * DMODEL + k0 + seg * 8;
            else if (mat == 2) gp = g_wth + (size_t)(bn + row) * DMODEL + k0 + seg * 8;
            else               gp = g_wtl + (size_t)(bn + row) * DMODEL + k0 + seg * 8;
            CP_ASYNC16(sa, gp);
        }
        CP_COMMIT();
    };

    issue(0, 0);

    const int lr  = lane & 7;
    const int lh8 = (lane >> 3) & 1;
    const int lh16 = lane >> 4;

    for (int chunk = 0; chunk < NCHUNK; chunk++) {
        if (chunk + 1 < NCHUNK) issue(chunk + 1, (chunk + 1) & 1);
        if (chunk + 1 < NCHUNK) { CP_WAIT1(); } else { CP_WAIT0(); }
        __syncthreads();

        const uint32_t stg = sb + (chunk & 1) * STG_BYTES;
        const uint32_t Ah = stg;
        const uint32_t Al = stg + MAT_BYTES;
        const uint32_t Bh = stg + 2 * MAT_BYTES;
        const uint32_t Bl = stg + 3 * MAT_BYTES;

#pragma unroll
        for (int ks = 0; ks < 2; ks++) {
            const int kb = ks * 32;
            uint32_t ah[2][4], al[2][4];
#pragma unroll
            for (int mt = 0; mt < 2; mt++) {
                const uint32_t ra = (uint32_t)(wm * 32 + mt * 16 + lr + 8 * lh8) * ROW_B
                                  + kb + 16 * lh16;
                LDSM_X4(ah[mt][0], ah[mt][1], ah[mt][2], ah[mt][3], Ah + ra);
                LDSM_X4(al[mt][0], al[mt][1], al[mt][2], al[mt][3], Al + ra);
            }
#pragma unroll
            for (int np = 0; np < 4; np++) {
                const uint32_t rb = (uint32_t)(wn * 64 + np * 16 + lr + 8 * lh16) * ROW_B
                                  + kb + 16 * lh8;
                uint32_t b0, b1, b2, b3;
                LDSM_X4(b0, b1, b2, b3, Bh + rb);      // Bh: used by Ah and Al
#pragma unroll
                for (int mt = 0; mt < 2; mt++) {
                    mma_bf16(c[mt][np * 2 + 0], ah[mt], b0, b1);
                    mma_bf16(c[mt][np * 2 + 1], ah[mt], b2, b3);
                    mma_bf16(c[mt][np * 2 + 0], al[mt], b0, b1);
                    mma_bf16(c[mt][np * 2 + 1], al[mt], b2, b3);
                }
                LDSM_X4(b0, b1, b2, b3, Bl + rb);      // Bl: used by Ah only
#pragma unroll
                for (int mt = 0; mt < 2; mt++) {
                    mma_bf16(c[mt][np * 2 + 0], ah[mt], b0, b1);
                    mma_bf16(c[mt][np * 2 + 1], ah[mt], b2, b3);
                }
            }
        }
        __syncthreads();
    }

    const int rg = lane >> 2;
    const int cg = (lane & 3) * 2;
    if (dst_sel == 3) {
#pragma unroll
        for (int mt = 0; mt < 2; mt++)
#pragma unroll
            for (int nt = 0; nt < 8; nt++) {
                const int row = bm + wm * 32 + mt * 16 + rg;
                const int col = bn + wn * 64 + nt * 8 + cg;
                const float b0 = bias[col], b1 = bias[col + 1];
                *(float2*)&Cext[(size_t)row * DMODEL + col] =
                    make_float2(c[mt][nt][0] + b0, c[mt][nt][1] + b1);
                *(float2*)&Cext[(size_t)(row + 8) * DMODEL + col] =
                    make_float2(c[mt][nt][2] + b0, c[mt][nt][3] + b1);
            }
    } else {
        __nv_bfloat16* H = (dst_sel == 0) ? g_qh : (dst_sel == 1) ? g_kh : g_vh;
        __nv_bfloat16* L = (dst_sel == 0) ? g_ql : (dst_sel == 1) ? g_kl : g_vl;
        const float scl = (dst_sel == 0) ? 0.125f : 1.f;
#pragma unroll
        for (int mt = 0; mt < 2; mt++)
#pragma unroll
            for (int nt = 0; nt < 8; nt++) {
                const int row = bm + wm * 32 + mt * 16 + rg;
                const int col = bn + wn * 64 + nt * 8 + cg;
                const float b0 = bias[col], b1 = bias[col + 1];
                float v0 = (c[mt][nt][0] + b0) * scl, v1 = (c[mt][nt][1] + b1) * scl;
                float v2 = (c[mt][nt][2] + b0) * scl, v3 = (c[mt][nt][3] + b1) * scl;
                size_t o0 = (size_t)row * DMODEL + col;
                size_t o1 = (size_t)(row + 8) * DMODEL + col;
                *(__nv_bfloat162*)&H[o0] = hi2(v0, v1);
                *(__nv_bfloat162*)&L[o0] = lo2(v0, v1);
                *(__nv_bfloat162*)&H[o1] = hi2(v2, v3);
                *(__nv_bfloat162*)&L[o1] = lo2(v2, v3);
            }
    }
}

// ---------------------------------------------------------------------------
// Tensor-core flash attention, pre-split operands. 256 threads, BQ=128,
// key blocks 64, cp.async loads, AROW=144 padded rows, output split to
// g_xh/g_xl (the final GEMM's A input).
// ---------------------------------------------------------------------------
#define AROW    144
#define OFF_QH  0
#define OFF_QL  (128*AROW)
#define OFF_KH  (2*128*AROW)
#define OFF_PH  (OFF_KH + 4*64*AROW)
#define OFF_PL  (OFF_PH + 128*AROW)
#define OFF_MSK (OFF_PL + 128*AROW)
#define ATT_SMEM (OFF_MSK + 256)

__global__ __launch_bounds__(256, 2) void attn_mma(const int* __restrict__ mask)
{
    extern __shared__ char sm[];
    const uint32_t sb = smem_u32(sm);
    const int tid  = threadIdx.x;
    const int wid  = tid >> 5;
    const int lane = tid & 31;
    const int lr   = lane & 7;
    const int lh8  = (lane >> 3) & 1;
    const int lh16 = lane >> 4;
    const int g    = lane >> 2;
    const int t2   = (lane & 3) * 2;
    const int wm16 = wid * 16;

    const int nh = blockIdx.y;
    const int nb = nh >> 4;
    const int qt = blockIdx.x;
    const size_t hb = (size_t)nh * SEQ * DH;
    const size_t qoff = hb + (size_t)qt * 128 * DH;
    const int* mk = mask + nb * SEQ;

    // ---- Q tile: cp.async bf16 hi/lo (2048 x 16B) ----
#pragma unroll
    for (int i = 0; i < 8; i++) {
        const int idx = i * 256 + tid;
        const int mat = idx >> 10;            // 0: hi, 1: lo
        const int r = (idx >> 3) & 127;
        const int s = idx & 7;
        const __nv_bfloat16* gp = (mat ? g_ql : g_qh) + qoff + r * DH + s * 8;
        CP_ASYNC16(sb + (mat ? OFF_QL : OFF_QH) + r * AROW + s * 16, gp);
    }
    CP_COMMIT();

    float m0 = -INFINITY, m1 = -INFINITY, l0 = 0.f, l1 = 0.f;
    float co[8][4];
#pragma unroll
    for (int nt = 0; nt < 8; nt++)
#pragma unroll
        for (int r = 0; r < 4; r++) co[nt][r] = 0.f;

    for (int kb = 0; kb < SEQ / 64; kb++) {
        __syncthreads();   // prior iteration's K/V/mask reads complete
        if (tid < 64) *(int*)(sm + OFF_MSK + tid * 4) = mk[kb * 64 + tid];
        // K/V tiles: 4 mats (KH,KL,VH,VL) x 64 rows x 8 segs
#pragma unroll
        for (int i = 0; i < 8; i++) {
            const int idx = i * 256 + tid;
            const int mat = idx >> 9;
            const int r = (idx >> 3) & 63;
            const int s = idx & 7;
            const __nv_bfloat16* gb =
                (mat == 0) ? g_kh : (mat == 1) ? g_kl : (mat == 2) ? g_vh : g_vl;
            CP_ASYNC16(sb + OFF_KH + mat * 64 * AROW + r * AROW + s * 16,
                       gb + hb + (size_t)(kb * 64 + r) * DH + s * 8);
        }
        CP_COMMIT();
        CP_WAIT0();        // first iteration also covers the Q group
        __syncthreads();

        // ---- S = Q K^T ----
        float cs[8][4];
#pragma unroll
        for (int nt = 0; nt < 8; nt++)
#pragma unroll
            for (int r = 0; r < 4; r++) cs[nt][r] = 0.f;

#pragma unroll
        for (int ks = 0; ks < 4; ks++) {
            const int kk2 = ks * 32;
            const uint32_t ra = (uint32_t)(wm16 + lr + 8 * lh8) * AROW + kk2 + 16 * lh16;
            uint32_t ah[4], al[4];
            LDSM_X4(ah[0], ah[1], ah[2], ah[3], sb + OFF_QH + ra);
            LDSM_X4(al[0], al[1], al[2], al[3], sb + OFF_QL + ra);
#pragma unroll
            for (int np = 0; np < 4; np++) {
                const uint32_t rb = (uint32_t)(np * 16 + lr + 8 * lh16) * AROW + kk2 + 16 * lh8;
                uint32_t b0, b1, b2, b3;
                LDSM_X4(b0, b1, b2, b3, sb + OFF_KH + rb);           // Kh
                mma_bf16(cs[np * 2 + 0], ah, b0, b1);
                mma_bf16(cs[np * 2 + 1], ah, b2, b3);
                mma_bf16(cs[np * 2 + 0], al, b0, b1);
                mma_bf16(cs[np * 2 + 1], al, b2, b3);
                LDSM_X4(b0, b1, b2, b3, sb + OFF_KH + 64 * AROW + rb); // Kl
                mma_bf16(cs[np * 2 + 0], ah, b0, b1);
                mma_bf16(cs[np * 2 + 1], ah, b2, b3);
            }
        }

        // ---- mask ----
#pragma unroll
        for (int nt = 0; nt < 8; nt++) {
            int2 mv = *(const int2*)(sm + OFF_MSK + (nt * 8 + t2) * 4);
            if (!mv.x) { cs[nt][0] = NEGINF; cs[nt][2] = NEGINF; }
            if (!mv.y) { cs[nt][1] = NEGINF; cs[nt][3] = NEGINF; }
        }

        // ---- online softmax ----
        float mx0 = NEGINF, mx1 = NEGINF;
#pragma unroll
        for (int nt = 0; nt < 8; nt++) {
            mx0 = fmaxf(mx0, fmaxf(cs[nt][0], cs[nt][1]));
            mx1 = fmaxf(mx1, fmaxf(cs[nt][2], cs[nt][3]));
        }
        mx0 = fmaxf(mx0, __shfl_xor_sync(0xffffffffu, mx0, 1));
        mx0 = fmaxf(mx0, __shfl_xor_sync(0xffffffffu, mx0, 2));
        mx1 = fmaxf(mx1, __shfl_xor_sync(0xffffffffu, mx1, 1));
        mx1 = fmaxf(mx1, __shfl_xor_sync(0xffffffffu, mx1, 2));
        const float mn0 = fmaxf(m0, mx0), mn1 = fmaxf(m1, mx1);
        const float corr0 = __expf(m0 - mn0), corr1 = __expf(m1 - mn1);
        float s0 = 0.f, s1 = 0.f;
        const int prow0 = (wm16 + g) * AROW, prow1 = (wm16 + g + 8) * AROW;
#pragma unroll
        for (int nt = 0; nt < 8; nt++) {
            const int cb = (nt * 8 + t2) * 2;
            float p00 = __expf(cs[nt][0] - mn0);
            float p01 = __expf(cs[nt][1] - mn0);
            float p10 = __expf(cs[nt][2] - mn1);
            float p11 = __expf(cs[nt][3] - mn1);
            s0 += p00 + p01; s1 += p10 + p11;
            *(__nv_bfloat162*)(sm + OFF_PH + prow0 + cb) = hi2(p00, p01);
            *(__nv_bfloat162*)(sm + OFF_PH + prow1 + cb) = hi2(p10, p11);
            *(__nv_bfloat162*)(sm + OFF_PL + prow0 + cb) = lo2(p00, p01);
            *(__nv_bfloat162*)(sm + OFF_PL + prow1 + cb) = lo2(p10, p11);
        }
        s0 += __shfl_xor_sync(0xffffffffu, s0, 1);
        s0 += __shfl_xor_sync(0xffffffffu, s0, 2);
        s1 += __shfl_xor_sync(0xffffffffu, s1, 1);
        s1 += __shfl_xor_sync(0xffffffffu, s1, 2);
        l0 = l0 * corr0 + s0; m0 = mn0;
        l1 = l1 * corr1 + s1; m1 = mn1;
#pragma unroll
        for (int nt = 0; nt < 8; nt++) {
            co[nt][0] *= corr0; co[nt][1] *= corr0;
            co[nt][2] *= corr1; co[nt][3] *= corr1;
        }
        __syncwarp();   // P rows (warp-private) visible to ldmatrix

        // ---- O += P V ----
#pragma unroll
        for (int ks = 0; ks < 4; ks++) {
            const int kk2 = ks * 32;
            const uint32_t ra = (uint32_t)(wm16 + lr + 8 * lh8) * AROW + kk2 + 16 * lh16;
            uint32_t ph[4], pl[4];
            LDSM_X4(ph[0], ph[1], ph[2], ph[3], sb + OFF_PH + ra);
            LDSM_X4(pl[0], pl[1], pl[2], pl[3], sb + OFF_PL + ra);
#pragma unroll
            for (int np = 0; np < 4; np++) {
                const uint32_t rv = (uint32_t)(ks * 16 + lr + 8 * lh8) * AROW
                                  + np * 32 + 16 * lh16;
                uint32_t b0, b1, b2, b3;
                LDSM_X4T(b0, b1, b2, b3, sb + OFF_KH + 2 * 64 * AROW + rv);   // Vh
                mma_bf16(co[np * 2 + 0], ph, b0, b1);
                mma_bf16(co[np * 2 + 1], ph, b2, b3);
                mma_bf16(co[np * 2 + 0], pl, b0, b1);
                mma_bf16(co[np * 2 + 1], pl, b2, b3);
                LDSM_X4T(b0, b1, b2, b3, sb + OFF_KH + 3 * 64 * AROW + rv);   // Vl
                mma_bf16(co[np * 2 + 0], ph, b0, b1);
                mma_bf16(co[np * 2 + 1], ph, b2, b3);
            }
        }
        __syncwarp();
    }

    // ---- epilogue: normalize, split, write hi/lo to g_xh/g_xl ----
    const float i0 = 1.f / l0, i1 = 1.f / l1;
    const int r0 = wm16 + g, r1 = wm16 + g + 8;
#pragma unroll
    for (int nt = 0; nt < 8; nt++) {
        const int col = nt * 8 + t2;
        float v0 = co[nt][0] * i0, v1 = co[nt][1] * i0;
        float v2 = co[nt][2] * i1, v3 = co[nt][3] * i1;
        size_t o0 = qoff + (size_t)r0 * DH + col;
        size_t o1 = qoff + (size_t)r1 * DH + col;
        *(__nv_bfloat162*)&g_xh[o0] = hi2(v0, v1);
        *(__nv_bfloat162*)&g_xl[o0] = lo2(v0, v1);
        *(__nv_bfloat162*)&g_xh[o1] = hi2(v2, v3);
        *(__nv_bfloat162*)&g_xl[o1] = lo2(v2, v3);
    }
}

// ---------------------------------------------------------------------------
extern "C" void kernel_launch(void* const* d_in, const int* in_sizes, int n_in,
                              void* d_out, int out_size)
{
    const float* x   = (const float*)d_in[0];
    const int*  mask = (const int*)  d_in[1];
    const float* wq  = (const float*)d_in[2];
    const float* bq  = (const float*)d_in[3];
    const float* wk  = (const float*)d_in[4];
    const float* bk  = (const float*)d_in[5];
    const float* wv  = (const float*)d_in[6];
    const float* bv  = (const float*)d_in[7];
    const float* wo  = (const float*)d_in[8];
    const float* bo  = (const float*)d_in[9];
    float* out = (float*)d_out;

    const int gemm_smem = 2 * STG_BYTES;            // 81920 B
    cudaFuncSetAttribute(gemm_mma, cudaFuncAttributeMaxDynamicSharedMemorySize, gemm_smem);
    cudaFuncSetAttribute(attn_mma, cudaFuncAttributeMaxDynamicSharedMemorySize, ATT_SMEM);

    dim3 tgrid(DMODEL / 32, DMODEL / 32), tblk(32, 8);
    dim3 ggrid(DMODEL / 128, MROWS / 128);          // (8, 64)
    const int nsplit = (MROWS * DMODEL / 4 + 255) / 256;

    split_bf16<<<nsplit, 256>>>(x);

    transpose_split<<<tgrid, tblk>>>(wq);
    gemm_mma<<<ggrid, 256, gemm_smem>>>(bq, out, 0);
    transpose_split<<<tgrid, tblk>>>(wk);
    gemm_mma<<<ggrid, 256, gemm_smem>>>(bk, out, 1);
    transpose_split<<<tgrid, tblk>>>(wv);
    gemm_mma<<<ggrid, 256, gemm_smem>>>(bv, out, 2);

    attn_mma<<<dim3(SEQ / 128, NB * NHEADS), 256, ATT_SMEM>>>(mask);

    transpose_split<<<tgrid, tblk>>>(wo);
    gemm_mma<<<ggrid, 256, gemm_smem>>>(bo, out, 3);
}

// round 10
// speedup vs baseline: 3.0746x; 1.0051x over previous
#include <cuda_runtime.h>
#include <cuda_bf16.h>
#include <math.h>
#include <stdint.h>

#define NB     4
#define SEQ    2048
#define DMODEL 1024
#define NHEADS 16
#define DH     64
#define MROWS  8192
#define NEGINF -1e30f

// ---------------------------------------------------------------------------
// Static scratch (all projection outputs live as pre-split bf16 hi/lo)
// ---------------------------------------------------------------------------
__device__ __nv_bfloat16 g_xh[MROWS*DMODEL];     // activation hi (also attn out)
__device__ __nv_bfloat16 g_xl[MROWS*DMODEL];     // activation lo
__device__ __nv_bfloat16 g_wth4[4*DMODEL*DMODEL]; // weight^T hi [4][N][K]
__device__ __nv_bfloat16 g_wtl4[4*DMODEL*DMODEL]; // weight^T lo [4][N][K]
__device__ __nv_bfloat16 g_qh[MROWS*DMODEL];     // Q hi (1/8 scale folded)
__device__ __nv_bfloat16 g_ql[MROWS*DMODEL];
__device__ __nv_bfloat16 g_kh[MROWS*DMODEL];
__device__ __nv_bfloat16 g_kl[MROWS*DMODEL];
__device__ __nv_bfloat16 g_vh[MROWS*DMODEL];
__device__ __nv_bfloat16 g_vl[MROWS*DMODEL];

// ---------------------------------------------------------------------------
// PTX helpers (sm_100 base target)
// ---------------------------------------------------------------------------
__device__ __forceinline__ uint32_t smem_u32(const void* p) {
    uint32_t a;
    asm("{ .reg .u64 t; cvta.to.shared.u64 t, %1; cvt.u32.u64 %0, t; }" : "=r"(a) : "l"(p));
    return a;
}
#define CP_ASYNC16(saddr, gptr) \
    asm volatile("cp.async.cg.shared.global [%0], [%1], 16;" :: "r"(saddr), "l"(gptr))
#define CP_COMMIT() asm volatile("cp.async.commit_group;" ::: "memory")
#define CP_WAIT1()  asm volatile("cp.async.wait_group 1;" ::: "memory")
#define CP_WAIT0()  asm volatile("cp.async.wait_group 0;" ::: "memory")

#define LDSM_X4(r0, r1, r2, r3, addr) \
    asm volatile("ldmatrix.sync.aligned.m8n8.x4.shared.b16 {%0,%1,%2,%3}, [%4];" \
        : "=r"(r0), "=r"(r1), "=r"(r2), "=r"(r3) : "r"(addr))
#define LDSM_X4T(r0, r1, r2, r3, addr) \
    asm volatile("ldmatrix.sync.aligned.m8n8.x4.trans.shared.b16 {%0,%1,%2,%3}, [%4];" \
        : "=r"(r0), "=r"(r1), "=r"(r2), "=r"(r3) : "r"(addr))

__device__ __forceinline__ void mma_bf16(float* c, const uint32_t* a,
                                         uint32_t b0, uint32_t b1) {
    asm volatile(
        "mma.sync.aligned.m16n8k16.row.col.f32.bf16.bf16.f32 "
        "{%0,%1,%2,%3}, {%4,%5,%6,%7}, {%8,%9}, {%0,%1,%2,%3};"
        : "+f"(c[0]), "+f"(c[1]), "+f"(c[2]), "+f"(c[3])
        : "r"(a[0]), "r"(a[1]), "r"(a[2]), "r"(a[3]), "r"(b0), "r"(b1));
}

__device__ __forceinline__ __nv_bfloat162 hi2(float a, float b) {
    return __halves2bfloat162(__float2bfloat16(a), __float2bfloat16(b));
}
__device__ __forceinline__ __nv_bfloat162 lo2(float a, float b) {
    __nv_bfloat16 ha = __float2bfloat16(a), hb = __float2bfloat16(b);
    return __halves2bfloat162(__float2bfloat16(a - __bfloat162float(ha)),
                              __float2bfloat16(b - __bfloat162float(hb)));
}

// ---------------------------------------------------------------------------
// fp32 -> bf16 hi/lo split of x
// ---------------------------------------------------------------------------
__global__ __launch_bounds__(256) void split_bf16(const float* __restrict__ src) {
    size_t i4 = ((size_t)blockIdx.x * 256 + threadIdx.x) * 4;
    if (i4 >= (size_t)MROWS * DMODEL) return;
    float4 v = *(const float4*)(src + i4);
    float a[4] = {v.x, v.y, v.z, v.w};
#pragma unroll
    for (int j = 0; j < 4; j++) {
        __nv_bfloat16 hi = __float2bfloat16(a[j]);
        __nv_bfloat16 lo = __float2bfloat16(a[j] - __bfloat162float(hi));
        g_xh[i4 + j] = hi;
        g_xl[i4 + j] = lo;
    }
}

// ---------------------------------------------------------------------------
// All-four weight transpose + split: w[z] [K][N] fp32 -> slot z of [N][K] bf16
// grid = (32, 32, 4)
// ---------------------------------------------------------------------------
__global__ __launch_bounds__(256) void transpose_split4(
    const float* __restrict__ wq, const float* __restrict__ wk,
    const float* __restrict__ wv, const float* __restrict__ wo) {
    __shared__ float t[32][33];
    const int tx = threadIdx.x, ty = threadIdx.y;    // 32 x 8
    const int n0 = blockIdx.x * 32, k0 = blockIdx.y * 32;
    const int z = blockIdx.z;
    const float* w = (z == 0) ? wq : (z == 1) ? wk : (z == 2) ? wv : wo;
    __nv_bfloat16* H = g_wth4 + (size_t)z * DMODEL * DMODEL;
    __nv_bfloat16* L = g_wtl4 + (size_t)z * DMODEL * DMODEL;
#pragma unroll
    for (int i = 0; i < 4; i++)
        t[ty + i * 8][tx] = w[(size_t)(k0 + ty + i * 8) * DMODEL + n0 + tx];
    __syncthreads();
#pragma unroll
    for (int i = 0; i < 4; i++) {
        float v = t[tx][ty + i * 8];
        __nv_bfloat16 hi = __float2bfloat16(v);
        __nv_bfloat16 lo = __float2bfloat16(v - __bfloat162float(hi));
        size_t o = (size_t)(n0 + ty + i * 8) * DMODEL + (k0 + tx);
        H[o] = hi;
        L[o] = lo;
    }
}

// ---------------------------------------------------------------------------
// mma.sync bf16-split GEMM. wsel picks weight slot. dst_sel 0/1/2: split
// bf16 hi/lo to Q(x0.125)/K/V; dst_sel 3: fp32 to Cext.
// ---------------------------------------------------------------------------
#define MAT_BYTES   10240
#define STG_BYTES   40960
#define ROW_B       80
#define NCHUNK      32

__global__ __launch_bounds__(256) void gemm_mma(const float* __restrict__ bias,
                                                float* __restrict__ Cext,
                                                int wsel, int dst_sel) {
    extern __shared__ char smem[];
    const uint32_t sb = smem_u32(smem);
    const int tid  = threadIdx.x;
    const int wid  = tid >> 5;
    const int lane = tid & 31;
    const int wm = wid & 3;
    const int wn = wid >> 2;
    const int bn = blockIdx.x * 128;
    const int bm = blockIdx.y * 128;
    const __nv_bfloat16* WH = g_wth4 + (size_t)wsel * DMODEL * DMODEL;
    const __nv_bfloat16* WL = g_wtl4 + (size_t)wsel * DMODEL * DMODEL;

    float c[2][8][4];
#pragma unroll
    for (int mt = 0; mt < 2; mt++)
#pragma unroll
        for (int nt = 0; nt < 8; nt++)
#pragma unroll
            for (int r = 0; r < 4; r++) c[mt][nt][r] = 0.f;

    auto issue = [&](int chunk, int stage) {
        const int k0 = chunk * 32;
        const uint32_t stg = sb + stage * STG_BYTES;
#pragma unroll
        for (int i = 0; i < 8; i++) {
            const int idx = i * 256 + tid;
            const int mat = idx >> 9;
            const int row = (idx >> 2) & 127;
            const int seg = idx & 3;
            const uint32_t sa = stg + mat * MAT_BYTES + row * ROW_B + seg * 16;
            const __nv_bfloat16* gp;
            if (mat == 0)      gp = g_xh + (size_t)(bm + row) * DMODEL + k0 + seg * 8;
            else if (mat == 1) gp = g_xl + (size_t)(bm + row) * DMODEL + k0 + seg * 8;
            else if (mat == 2) gp = WH   + (size_t)(bn + row) * DMODEL + k0 + seg * 8;
            else               gp = WL   + (size_t)(bn + row) * DMODEL + k0 + seg * 8;
            CP_ASYNC16(sa, gp);
        }
        CP_COMMIT();
    };

    issue(0, 0);

    const int lr  = lane & 7;
    const int lh8 = (lane >> 3) & 1;
    const int lh16 = lane >> 4;

    for (int chunk = 0; chunk < NCHUNK; chunk++) {
        if (chunk + 1 < NCHUNK) issue(chunk + 1, (chunk + 1) & 1);
        if (chunk + 1 < NCHUNK) { CP_WAIT1(); } else { CP_WAIT0(); }
        __syncthreads();

        const uint32_t stg = sb + (chunk & 1) * STG_BYTES;
        const uint32_t Ah = stg;
        const uint32_t Al = stg + MAT_BYTES;
        const uint32_t Bh = stg + 2 * MAT_BYTES;
        const uint32_t Bl = stg + 3 * MAT_BYTES;

#pragma unroll
        for (int ks = 0; ks < 2; ks++) {
            const int kb = ks * 32;
            uint32_t ah[2][4], al[2][4];
#pragma unroll
            for (int mt = 0; mt < 2; mt++) {
                const uint32_t ra = (uint32_t)(wm * 32 + mt * 16 + lr + 8 * lh8) * ROW_B
                                  + kb + 16 * lh16;
                LDSM_X4(ah[mt][0], ah[mt][1], ah[mt][2], ah[mt][3], Ah + ra);
                LDSM_X4(al[mt][0], al[mt][1], al[mt][2], al[mt][3], Al + ra);
            }
#pragma unroll
            for (int np = 0; np < 4; np++) {
                const uint32_t rb = (uint32_t)(wn * 64 + np * 16 + lr + 8 * lh16) * ROW_B
                                  + kb + 16 * lh8;
                uint32_t b0, b1, b2, b3;
                LDSM_X4(b0, b1, b2, b3, Bh + rb);      // Bh: used by Ah and Al
#pragma unroll
                for (int mt = 0; mt < 2; mt++) {
                    mma_bf16(c[mt][np * 2 + 0], ah[mt], b0, b1);
                    mma_bf16(c[mt][np * 2 + 1], ah[mt], b2, b3);
                    mma_bf16(c[mt][np * 2 + 0], al[mt], b0, b1);
                    mma_bf16(c[mt][np * 2 + 1], al[mt], b2, b3);
                }
                LDSM_X4(b0, b1, b2, b3, Bl + rb);      // Bl: used by Ah only
#pragma unroll
                for (int mt = 0; mt < 2; mt++) {
                    mma_bf16(c[mt][np * 2 + 0], ah[mt], b0, b1);
                    mma_bf16(c[mt][np * 2 + 1], ah[mt], b2, b3);
                }
            }
        }
        __syncthreads();
    }

    const int rg = lane >> 2;
    const int cg = (lane & 3) * 2;
    if (dst_sel == 3) {
#pragma unroll
        for (int mt = 0; mt < 2; mt++)
#pragma unroll
            for (int nt = 0; nt < 8; nt++) {
                const int row = bm + wm * 32 + mt * 16 + rg;
                const int col = bn + wn * 64 + nt * 8 + cg;
                const float b0 = bias[col], b1 = bias[col + 1];
                *(float2*)&Cext[(size_t)row * DMODEL + col] =
                    make_float2(c[mt][nt][0] + b0, c[mt][nt][1] + b1);
                *(float2*)&Cext[(size_t)(row + 8) * DMODEL + col] =
                    make_float2(c[mt][nt][2] + b0, c[mt][nt][3] + b1);
            }
    } else {
        __nv_bfloat16* H = (dst_sel == 0) ? g_qh : (dst_sel == 1) ? g_kh : g_vh;
        __nv_bfloat16* L = (dst_sel == 0) ? g_ql : (dst_sel == 1) ? g_kl : g_vl;
        const float scl = (dst_sel == 0) ? 0.125f : 1.f;
#pragma unroll
        for (int mt = 0; mt < 2; mt++)
#pragma unroll
            for (int nt = 0; nt < 8; nt++) {
                const int row = bm + wm * 32 + mt * 16 + rg;
                const int col = bn + wn * 64 + nt * 8 + cg;
                const float b0 = bias[col], b1 = bias[col + 1];
                float v0 = (c[mt][nt][0] + b0) * scl, v1 = (c[mt][nt][1] + b1) * scl;
                float v2 = (c[mt][nt][2] + b0) * scl, v3 = (c[mt][nt][3] + b1) * scl;
                size_t o0 = (size_t)row * DMODEL + col;
                size_t o1 = (size_t)(row + 8) * DMODEL + col;
                *(__nv_bfloat162*)&H[o0] = hi2(v0, v1);
                *(__nv_bfloat162*)&L[o0] = lo2(v0, v1);
                *(__nv_bfloat162*)&H[o1] = hi2(v2, v3);
                *(__nv_bfloat162*)&L[o1] = lo2(v2, v3);
            }
    }
}

// ---------------------------------------------------------------------------
// Tensor-core flash attention, software-pipelined cp.async:
//   group A = K hi/lo (issued during previous PV), group B = V hi/lo
//   (issued after first barrier, overlaps S). Mask double-buffered,
//   written one iteration ahead. 2 barriers/iter (same as before).
// ---------------------------------------------------------------------------
#define AROW    144
#define OFF_QH  0
#define OFF_QL  (128*AROW)
#define OFF_KH  (2*128*AROW)
#define OFF_PH  (OFF_KH + 4*64*AROW)
#define OFF_PL  (OFF_PH + 128*AROW)
#define OFF_MSK (OFF_PL + 128*AROW)
#define ATT_SMEM (OFF_MSK + 512)          // 2 x 256B mask buffers

__global__ __launch_bounds__(256, 2) void attn_mma(const int* __restrict__ mask)
{
    extern __shared__ char sm[];
    const uint32_t sb = smem_u32(sm);
    const int tid  = threadIdx.x;
    const int wid  = tid >> 5;
    const int lane = tid & 31;
    const int lr   = lane & 7;
    const int lh8  = (lane >> 3) & 1;
    const int lh16 = lane >> 4;
    const int g    = lane >> 2;
    const int t2   = (lane & 3) * 2;
    const int wm16 = wid * 16;

    const int nh = blockIdx.y;
    const int nb = nh >> 4;
    const int qt = blockIdx.x;
    const size_t hb = (size_t)nh * SEQ * DH;
    const size_t qoff = hb + (size_t)qt * 128 * DH;
    const int* mk = mask + nb * SEQ;

    // issue-K helper: 2 mats x 64 rows x 8 segs = 1024 x 16B
    auto issueK = [&](int kb) {
#pragma unroll
        for (int i = 0; i < 4; i++) {
            const int idx = i * 256 + tid;
            const int mat = idx >> 9;
            const int r = (idx >> 3) & 63;
            const int s = idx & 7;
            const __nv_bfloat16* gb = mat ? g_kl : g_kh;
            CP_ASYNC16(sb + OFF_KH + mat * 64 * AROW + r * AROW + s * 16,
                       gb + hb + (size_t)(kb * 64 + r) * DH + s * 8);
        }
    };
    auto issueV = [&](int kb) {
#pragma unroll
        for (int i = 0; i < 4; i++) {
            const int idx = i * 256 + tid;
            const int mat = idx >> 9;
            const int r = (idx >> 3) & 63;
            const int s = idx & 7;
            const __nv_bfloat16* gb = mat ? g_vl : g_vh;
            CP_ASYNC16(sb + OFF_KH + (2 + mat) * 64 * AROW + r * AROW + s * 16,
                       gb + hb + (size_t)(kb * 64 + r) * DH + s * 8);
        }
    };

    // ---- pre-loop: Q tile + K_0 + mask_0 ----
#pragma unroll
    for (int i = 0; i < 8; i++) {
        const int idx = i * 256 + tid;
        const int mat = idx >> 10;            // 0: hi, 1: lo
        const int r = (idx >> 3) & 127;
        const int s = idx & 7;
        const __nv_bfloat16* gp = (mat ? g_ql : g_qh) + qoff + r * DH + s * 8;
        CP_ASYNC16(sb + (mat ? OFF_QL : OFF_QH) + r * AROW + s * 16, gp);
    }
    CP_COMMIT();
    if (tid < 64) *(int*)(sm + OFF_MSK + tid * 4) = mk[tid];   // mask_0 -> buf 0
    issueK(0);
    CP_COMMIT();

    float m0 = -INFINITY, m1 = -INFINITY, l0 = 0.f, l1 = 0.f;
    float co[8][4];
#pragma unroll
    for (int nt = 0; nt < 8; nt++)
#pragma unroll
        for (int r = 0; r < 4; r++) co[nt][r] = 0.f;

    for (int kb = 0; kb < SEQ / 64; kb++) {
        // [1] K_kb ready (everything in flight drains); barrier also proves
        //     all warps finished PV_{kb-1} -> V buffer reusable
        CP_WAIT0();
        __syncthreads();

        // [2] V_kb load overlaps S compute
        issueV(kb);
        CP_COMMIT();

        // [3] S = Q K^T
        float cs[8][4];
#pragma unroll
        for (int nt = 0; nt < 8; nt++)
#pragma unroll
            for (int r = 0; r < 4; r++) cs[nt][r] = 0.f;

#pragma unroll
        for (int ks = 0; ks < 4; ks++) {
            const int kk2 = ks * 32;
            const uint32_t ra = (uint32_t)(wm16 + lr + 8 * lh8) * AROW + kk2 + 16 * lh16;
            uint32_t ah[4], al[4];
            LDSM_X4(ah[0], ah[1], ah[2], ah[3], sb + OFF_QH + ra);
            LDSM_X4(al[0], al[1], al[2], al[3], sb + OFF_QL + ra);
#pragma unroll
            for (int np = 0; np < 4; np++) {
                const uint32_t rb = (uint32_t)(np * 16 + lr + 8 * lh16) * AROW + kk2 + 16 * lh8;
                uint32_t b0, b1, b2, b3;
                LDSM_X4(b0, b1, b2, b3, sb + OFF_KH + rb);             // Kh
                mma_bf16(cs[np * 2 + 0], ah, b0, b1);
                mma_bf16(cs[np * 2 + 1], ah, b2, b3);
                mma_bf16(cs[np * 2 + 0], al, b0, b1);
                mma_bf16(cs[np * 2 + 1], al, b2, b3);
                LDSM_X4(b0, b1, b2, b3, sb + OFF_KH + 64 * AROW + rb); // Kl
                mma_bf16(cs[np * 2 + 0], ah, b0, b1);
                mma_bf16(cs[np * 2 + 1], ah, b2, b3);
            }
        }

        // mask (buffer kb&1, written one iteration ahead)
        const uint32_t mbase = OFF_MSK + (kb & 1) * 256;
#pragma unroll
        for (int nt = 0; nt < 8; nt++) {
            int2 mv = *(const int2*)(sm + mbase + (nt * 8 + t2) * 4);
            if (!mv.x) { cs[nt][0] = NEGINF; cs[nt][2] = NEGINF; }
            if (!mv.y) { cs[nt][1] = NEGINF; cs[nt][3] = NEGINF; }
        }

        // online softmax
        float mx0 = NEGINF, mx1 = NEGINF;
#pragma unroll
        for (int nt = 0; nt < 8; nt++) {
            mx0 = fmaxf(mx0, fmaxf(cs[nt][0], cs[nt][1]));
            mx1 = fmaxf(mx1, fmaxf(cs[nt][2], cs[nt][3]));
        }
        mx0 = fmaxf(mx0, __shfl_xor_sync(0xffffffffu, mx0, 1));
        mx0 = fmaxf(mx0, __shfl_xor_sync(0xffffffffu, mx0, 2));
        mx1 = fmaxf(mx1, __shfl_xor_sync(0xffffffffu, mx1, 1));
        mx1 = fmaxf(mx1, __shfl_xor_sync(0xffffffffu, mx1, 2));
        const float mn0 = fmaxf(m0, mx0), mn1 = fmaxf(m1, mx1);
        const float corr0 = __expf(m0 - mn0), corr1 = __expf(m1 - mn1);
        float s0 = 0.f, s1 = 0.f;
        const int prow0 = (wm16 + g) * AROW, prow1 = (wm16 + g + 8) * AROW;
#pragma unroll
        for (int nt = 0; nt < 8; nt++) {
            const int cb = (nt * 8 + t2) * 2;
            float p00 = __expf(cs[nt][0] - mn0);
            float p01 = __expf(cs[nt][1] - mn0);
            float p10 = __expf(cs[nt][2] - mn1);
            float p11 = __expf(cs[nt][3] - mn1);
            s0 += p00 + p01; s1 += p10 + p11;
            *(__nv_bfloat162*)(sm + OFF_PH + prow0 + cb) = hi2(p00, p01);
            *(__nv_bfloat162*)(sm + OFF_PH + prow1 + cb) = hi2(p10, p11);
            *(__nv_bfloat162*)(sm + OFF_PL + prow0 + cb) = lo2(p00, p01);
            *(__nv_bfloat162*)(sm + OFF_PL + prow1 + cb) = lo2(p10, p11);
        }
        s0 += __shfl_xor_sync(0xffffffffu, s0, 1);
        s0 += __shfl_xor_sync(0xffffffffu, s0, 2);
        s1 += __shfl_xor_sync(0xffffffffu, s1, 1);
        s1 += __shfl_xor_sync(0xffffffffu, s1, 2);
        l0 = l0 * corr0 + s0; m0 = mn0;
        l1 = l1 * corr1 + s1; m1 = mn1;
#pragma unroll
        for (int nt = 0; nt < 8; nt++) {
            co[nt][0] *= corr0; co[nt][1] *= corr0;
            co[nt][2] *= corr1; co[nt][3] *= corr1;
        }

        // [4] V_kb ready; barrier also proves all warps done with K buffer
        CP_WAIT0();
        __syncthreads();

        // [5] next iteration's K + mask load overlap PV compute
        if (kb + 1 < SEQ / 64) {
            issueK(kb + 1);
            if (tid < 64)
                *(int*)(sm + OFF_MSK + ((kb + 1) & 1) * 256 + tid * 4) = mk[(kb + 1) * 64 + tid];
            CP_COMMIT();
        }

        // [6] O += P V
#pragma unroll
        for (int ks = 0; ks < 4; ks++) {
            const int kk2 = ks * 32;
            const uint32_t ra = (uint32_t)(wm16 + lr + 8 * lh8) * AROW + kk2 + 16 * lh16;
            uint32_t ph[4], pl[4];
            LDSM_X4(ph[0], ph[1], ph[2], ph[3], sb + OFF_PH + ra);
            LDSM_X4(pl[0], pl[1], pl[2], pl[3], sb + OFF_PL + ra);
#pragma unroll
            for (int np = 0; np < 4; np++) {
                const uint32_t rv = (uint32_t)(ks * 16 + lr + 8 * lh8) * AROW
                                  + np * 32 + 16 * lh16;
                uint32_t b0, b1, b2, b3;
                LDSM_X4T(b0, b1, b2, b3, sb + OFF_KH + 2 * 64 * AROW + rv);   // Vh
                mma_bf16(co[np * 2 + 0], ph, b0, b1);
                mma_bf16(co[np * 2 + 1], ph, b2, b3);
                mma_bf16(co[np * 2 + 0], pl, b0, b1);
                mma_bf16(co[np * 2 + 1], pl, b2, b3);
                LDSM_X4T(b0, b1, b2, b3, sb + OFF_KH + 3 * 64 * AROW + rv);   // Vl
                mma_bf16(co[np * 2 + 0], ph, b0, b1);
                mma_bf16(co[np * 2 + 1], ph, b2, b3);
            }
        }
        __syncwarp();
    }

    // ---- epilogue: normalize, split, write hi/lo to g_xh/g_xl ----
    const float i0 = 1.f / l0, i1 = 1.f / l1;
    const int r0 = wm16 + g, r1 = wm16 + g + 8;
#pragma unroll
    for (int nt = 0; nt < 8; nt++) {
        const int col = nt * 8 + t2;
        float v0 = co[nt][0] * i0, v1 = co[nt][1] * i0;
        float v2 = co[nt][2] * i1, v3 = co[nt][3] * i1;
        size_t o0 = qoff + (size_t)r0 * DH + col;
        size_t o1 = qoff + (size_t)r1 * DH + col;
        *(__nv_bfloat162*)&g_xh[o0] = hi2(v0, v1);
        *(__nv_bfloat162*)&g_xl[o0] = lo2(v0, v1);
        *(__nv_bfloat162*)&g_xh[o1] = hi2(v2, v3);
        *(__nv_bfloat162*)&g_xl[o1] = lo2(v2, v3);
    }
}

// ---------------------------------------------------------------------------
extern "C" void kernel_launch(void* const* d_in, const int* in_sizes, int n_in,
                              void* d_out, int out_size)
{
    const float* x   = (const float*)d_in[0];
    const int*  mask = (const int*)  d_in[1];
    const float* wq  = (const float*)d_in[2];
    const float* bq  = (const float*)d_in[3];
    const float* wk  = (const float*)d_in[4];
    const float* bk  = (const float*)d_in[5];
    const float* wv  = (const float*)d_in[6];
    const float* bv  = (const float*)d_in[7];
    const float* wo  = (const float*)d_in[8];
    const float* bo  = (const float*)d_in[9];
    float* out = (float*)d_out;

    const int gemm_smem = 2 * STG_BYTES;            // 81920 B
    cudaFuncSetAttribute(gemm_mma, cudaFuncAttributeMaxDynamicSharedMemorySize, gemm_smem);
    cudaFuncSetAttribute(attn_mma, cudaFuncAttributeMaxDynamicSharedMemorySize, ATT_SMEM);

    dim3 ggrid(DMODEL / 128, MROWS / 128);          // (8, 64)
    const int nsplit = (MROWS * DMODEL / 4 + 255) / 256;

    // 1: x split   2: all four weight transposes
    split_bf16<<<nsplit, 256>>>(x);
    transpose_split4<<<dim3(32, 32, 4), dim3(32, 8)>>>(wq, wk, wv, wo);

    // 3-5: Q, K, V projections
    gemm_mma<<<ggrid, 256, gemm_smem>>>(bq, out, 0, 0);
    gemm_mma<<<ggrid, 256, gemm_smem>>>(bk, out, 1, 1);
    gemm_mma<<<ggrid, 256, gemm_smem>>>(bv, out, 2, 2);

    // 6: attention (ncu -s 5 -c 1 captures this launch)
    attn_mma<<<dim3(SEQ / 128, NB * NHEADS), 256, ATT_SMEM>>>(mask);

    // 7: output projection
    gemm_mma<<<ggrid, 256, gemm_smem>>>(bo, out, 3, 3);
}

// round 11
// speedup vs baseline: 3.2996x; 1.0732x over previous
#include <cuda_runtime.h>
#include <cuda_bf16.h>
#include <math.h>
#include <stdint.h>

#define NB     4
#define SEQ    2048
#define DMODEL 1024
#define NHEADS 16
#define DH     64
#define MROWS  8192
#define NEGINF -1e30f

// ---------------------------------------------------------------------------
// Static scratch (all projection outputs live as pre-split bf16 hi/lo)
// ---------------------------------------------------------------------------
__device__ __nv_bfloat16 g_xh[MROWS*DMODEL];     // activation hi (also attn out)
__device__ __nv_bfloat16 g_xl[MROWS*DMODEL];     // activation lo
__device__ __nv_bfloat16 g_wth4[4*DMODEL*DMODEL]; // weight^T hi [4][N][K]
__device__ __nv_bfloat16 g_wtl4[4*DMODEL*DMODEL]; // weight^T lo [4][N][K]
__device__ __nv_bfloat16 g_qh[MROWS*DMODEL];     // Q hi (1/8 scale folded)
__device__ __nv_bfloat16 g_ql[MROWS*DMODEL];
__device__ __nv_bfloat16 g_kh[MROWS*DMODEL];
__device__ __nv_bfloat16 g_kl[MROWS*DMODEL];
__device__ __nv_bfloat16 g_vh[MROWS*DMODEL];
__device__ __nv_bfloat16 g_vl[MROWS*DMODEL];

// ---------------------------------------------------------------------------
// PTX helpers (sm_100 base target)
// ---------------------------------------------------------------------------
__device__ __forceinline__ uint32_t smem_u32(const void* p) {
    uint32_t a;
    asm("{ .reg .u64 t; cvta.to.shared.u64 t, %1; cvt.u32.u64 %0, t; }" : "=r"(a) : "l"(p));
    return a;
}
#define CP_ASYNC16(saddr, gptr) \
    asm volatile("cp.async.cg.shared.global [%0], [%1], 16;" :: "r"(saddr), "l"(gptr))
#define CP_COMMIT() asm volatile("cp.async.commit_group;" ::: "memory")
#define CP_WAIT1()  asm volatile("cp.async.wait_group 1;" ::: "memory")
#define CP_WAIT0()  asm volatile("cp.async.wait_group 0;" ::: "memory")

#define LDSM_X4(r0, r1, r2, r3, addr) \
    asm volatile("ldmatrix.sync.aligned.m8n8.x4.shared.b16 {%0,%1,%2,%3}, [%4];" \
        : "=r"(r0), "=r"(r1), "=r"(r2), "=r"(r3) : "r"(addr))
#define LDSM_X4T(r0, r1, r2, r3, addr) \
    asm volatile("ldmatrix.sync.aligned.m8n8.x4.trans.shared.b16 {%0,%1,%2,%3}, [%4];" \
        : "=r"(r0), "=r"(r1), "=r"(r2), "=r"(r3) : "r"(addr))

__device__ __forceinline__ void mma_bf16(float* c, const uint32_t* a,
                                         uint32_t b0, uint32_t b1) {
    asm volatile(
        "mma.sync.aligned.m16n8k16.row.col.f32.bf16.bf16.f32 "
        "{%0,%1,%2,%3}, {%4,%5,%6,%7}, {%8,%9}, {%0,%1,%2,%3};"
        : "+f"(c[0]), "+f"(c[1]), "+f"(c[2]), "+f"(c[3])
        : "r"(a[0]), "r"(a[1]), "r"(a[2]), "r"(a[3]), "r"(b0), "r"(b1));
}

__device__ __forceinline__ __nv_bfloat162 hi2(float a, float b) {
    return __halves2bfloat162(__float2bfloat16(a), __float2bfloat16(b));
}
__device__ __forceinline__ __nv_bfloat162 lo2(float a, float b) {
    __nv_bfloat16 ha = __float2bfloat16(a), hb = __float2bfloat16(b);
    return __halves2bfloat162(__float2bfloat16(a - __bfloat162float(ha)),
                              __float2bfloat16(b - __bfloat162float(hb)));
}

// ---------------------------------------------------------------------------
// fp32 -> bf16 hi/lo split of x
// ---------------------------------------------------------------------------
__global__ __launch_bounds__(256) void split_bf16(const float* __restrict__ src) {
    size_t i4 = ((size_t)blockIdx.x * 256 + threadIdx.x) * 4;
    if (i4 >= (size_t)MROWS * DMODEL) return;
    float4 v = *(const float4*)(src + i4);
    float a[4] = {v.x, v.y, v.z, v.w};
#pragma unroll
    for (int j = 0; j < 4; j++) {
        __nv_bfloat16 hi = __float2bfloat16(a[j]);
        __nv_bfloat16 lo = __float2bfloat16(a[j] - __bfloat162float(hi));
        g_xh[i4 + j] = hi;
        g_xl[i4 + j] = lo;
    }
}

// ---------------------------------------------------------------------------
// All-four weight transpose + split: w[z] [K][N] fp32 -> slot z of [N][K] bf16
// ---------------------------------------------------------------------------
__global__ __launch_bounds__(256) void transpose_split4(
    const float* __restrict__ wq, const float* __restrict__ wk,
    const float* __restrict__ wv, const float* __restrict__ wo) {
    __shared__ float t[32][33];
    const int tx = threadIdx.x, ty = threadIdx.y;    // 32 x 8
    const int n0 = blockIdx.x * 32, k0 = blockIdx.y * 32;
    const int z = blockIdx.z;
    const float* w = (z == 0) ? wq : (z == 1) ? wk : (z == 2) ? wv : wo;
    __nv_bfloat16* H = g_wth4 + (size_t)z * DMODEL * DMODEL;
    __nv_bfloat16* L = g_wtl4 + (size_t)z * DMODEL * DMODEL;
#pragma unroll
    for (int i = 0; i < 4; i++)
        t[ty + i * 8][tx] = w[(size_t)(k0 + ty + i * 8) * DMODEL + n0 + tx];
    __syncthreads();
#pragma unroll
    for (int i = 0; i < 4; i++) {
        float v = t[tx][ty + i * 8];
        __nv_bfloat16 hi = __float2bfloat16(v);
        __nv_bfloat16 lo = __float2bfloat16(v - __bfloat162float(hi));
        size_t o = (size_t)(n0 + ty + i * 8) * DMODEL + (k0 + tx);
        H[o] = hi;
        L[o] = lo;
    }
}

// ---------------------------------------------------------------------------
// mma.sync bf16-split GEMM. __launch_bounds__(256,2) caps regs at 128 so
// TWO CTAs co-reside per SM (R10 profile: 132 regs -> 1 CTA/SM, occ 12.4%,
// tensor 46% -- register-bound residency was the binding constraint).
// ---------------------------------------------------------------------------
#define MAT_BYTES   10240
#define STG_BYTES   40960
#define ROW_B       80
#define NCHUNK      32

__global__ __launch_bounds__(256, 2) void gemm_mma(const float* __restrict__ bias,
                                                   float* __restrict__ Cext,
                                                   int wsel, int dst_sel) {
    extern __shared__ char smem[];
    const uint32_t sb = smem_u32(smem);
    const int tid  = threadIdx.x;
    const int wid  = tid >> 5;
    const int lane = tid & 31;
    const int wm = wid & 3;
    const int wn = wid >> 2;
    const int bn = blockIdx.x * 128;
    const int bm = blockIdx.y * 128;
    const __nv_bfloat16* WH = g_wth4 + (size_t)wsel * DMODEL * DMODEL;
    const __nv_bfloat16* WL = g_wtl4 + (size_t)wsel * DMODEL * DMODEL;

    float c[2][8][4];
#pragma unroll
    for (int mt = 0; mt < 2; mt++)
#pragma unroll
        for (int nt = 0; nt < 8; nt++)
#pragma unroll
            for (int r = 0; r < 4; r++) c[mt][nt][r] = 0.f;

    auto issue = [&](int chunk, int stage) {
        const int k0 = chunk * 32;
        const uint32_t stg = sb + stage * STG_BYTES;
#pragma unroll
        for (int i = 0; i < 8; i++) {
            const int idx = i * 256 + tid;
            const int mat = idx >> 9;
            const int row = (idx >> 2) & 127;
            const int seg = idx & 3;
            const uint32_t sa = stg + mat * MAT_BYTES + row * ROW_B + seg * 16;
            const __nv_bfloat16* gp;
            if (mat == 0)      gp = g_xh + (size_t)(bm + row) * DMODEL + k0 + seg * 8;
            else if (mat == 1) gp = g_xl + (size_t)(bm + row) * DMODEL + k0 + seg * 8;
            else if (mat == 2) gp = WH   + (size_t)(bn + row) * DMODEL + k0 + seg * 8;
            else               gp = WL   + (size_t)(bn + row) * DMODEL + k0 + seg * 8;
            CP_ASYNC16(sa, gp);
        }
        CP_COMMIT();
    };

    issue(0, 0);

    const int lr  = lane & 7;
    const int lh8 = (lane >> 3) & 1;
    const int lh16 = lane >> 4;

    for (int chunk = 0; chunk < NCHUNK; chunk++) {
        if (chunk + 1 < NCHUNK) issue(chunk + 1, (chunk + 1) & 1);
        if (chunk + 1 < NCHUNK) { CP_WAIT1(); } else { CP_WAIT0(); }
        __syncthreads();

        const uint32_t stg = sb + (chunk & 1) * STG_BYTES;
        const uint32_t Ah = stg;
        const uint32_t Al = stg + MAT_BYTES;
        const uint32_t Bh = stg + 2 * MAT_BYTES;
        const uint32_t Bl = stg + 3 * MAT_BYTES;

#pragma unroll
        for (int ks = 0; ks < 2; ks++) {
            const int kb = ks * 32;
            uint32_t ah[2][4], al[2][4];
#pragma unroll
            for (int mt = 0; mt < 2; mt++) {
                const uint32_t ra = (uint32_t)(wm * 32 + mt * 16 + lr + 8 * lh8) * ROW_B
                                  + kb + 16 * lh16;
                LDSM_X4(ah[mt][0], ah[mt][1], ah[mt][2], ah[mt][3], Ah + ra);
                LDSM_X4(al[mt][0], al[mt][1], al[mt][2], al[mt][3], Al + ra);
            }
#pragma unroll
            for (int np = 0; np < 4; np++) {
                const uint32_t rb = (uint32_t)(wn * 64 + np * 16 + lr + 8 * lh16) * ROW_B
                                  + kb + 16 * lh8;
                uint32_t b0, b1, b2, b3;
                LDSM_X4(b0, b1, b2, b3, Bh + rb);      // Bh: used by Ah and Al
#pragma unroll
                for (int mt = 0; mt < 2; mt++) {
                    mma_bf16(c[mt][np * 2 + 0], ah[mt], b0, b1);
                    mma_bf16(c[mt][np * 2 + 1], ah[mt], b2, b3);
                    mma_bf16(c[mt][np * 2 + 0], al[mt], b0, b1);
                    mma_bf16(c[mt][np * 2 + 1], al[mt], b2, b3);
                }
                LDSM_X4(b0, b1, b2, b3, Bl + rb);      // Bl: used by Ah only
#pragma unroll
                for (int mt = 0; mt < 2; mt++) {
                    mma_bf16(c[mt][np * 2 + 0], ah[mt], b0, b1);
                    mma_bf16(c[mt][np * 2 + 1], ah[mt], b2, b3);
                }
            }
        }
        __syncthreads();
    }

    const int rg = lane >> 2;
    const int cg = (lane & 3) * 2;
    if (dst_sel == 3) {
#pragma unroll
        for (int mt = 0; mt < 2; mt++)
#pragma unroll
            for (int nt = 0; nt < 8; nt++) {
                const int row = bm + wm * 32 + mt * 16 + rg;
                const int col = bn + wn * 64 + nt * 8 + cg;
                const float b0 = bias[col], b1 = bias[col + 1];
                *(float2*)&Cext[(size_t)row * DMODEL + col] =
                    make_float2(c[mt][nt][0] + b0, c[mt][nt][1] + b1);
                *(float2*)&Cext[(size_t)(row + 8) * DMODEL + col] =
                    make_float2(c[mt][nt][2] + b0, c[mt][nt][3] + b1);
            }
    } else {
        __nv_bfloat16* H = (dst_sel == 0) ? g_qh : (dst_sel == 1) ? g_kh : g_vh;
        __nv_bfloat16* L = (dst_sel == 0) ? g_ql : (dst_sel == 1) ? g_kl : g_vl;
        const float scl = (dst_sel == 0) ? 0.125f : 1.f;
#pragma unroll
        for (int mt = 0; mt < 2; mt++)
#pragma unroll
            for (int nt = 0; nt < 8; nt++) {
                const int row = bm + wm * 32 + mt * 16 + rg;
                const int col = bn + wn * 64 + nt * 8 + cg;
                const float b0 = bias[col], b1 = bias[col + 1];
                float v0 = (c[mt][nt][0] + b0) * scl, v1 = (c[mt][nt][1] + b1) * scl;
                float v2 = (c[mt][nt][2] + b0) * scl, v3 = (c[mt][nt][3] + b1) * scl;
                size_t o0 = (size_t)row * DMODEL + col;
                size_t o1 = (size_t)(row + 8) * DMODEL + col;
                *(__nv_bfloat162*)&H[o0] = hi2(v0, v1);
                *(__nv_bfloat162*)&L[o0] = lo2(v0, v1);
                *(__nv_bfloat162*)&H[o1] = hi2(v2, v3);
                *(__nv_bfloat162*)&L[o1] = lo2(v2, v3);
            }
    }
}

// ---------------------------------------------------------------------------
// Tensor-core flash attention (unchanged from R10)
// ---------------------------------------------------------------------------
#define AROW    144
#define OFF_QH  0
#define OFF_QL  (128*AROW)
#define OFF_KH  (2*128*AROW)
#define OFF_PH  (OFF_KH + 4*64*AROW)
#define OFF_PL  (OFF_PH + 128*AROW)
#define OFF_MSK (OFF_PL + 128*AROW)
#define ATT_SMEM (OFF_MSK + 512)          // 2 x 256B mask buffers

__global__ __launch_bounds__(256, 2) void attn_mma(const int* __restrict__ mask)
{
    extern __shared__ char sm[];
    const uint32_t sb = smem_u32(sm);
    const int tid  = threadIdx.x;
    const int wid  = tid >> 5;
    const int lane = tid & 31;
    const int lr   = lane & 7;
    const int lh8  = (lane >> 3) & 1;
    const int lh16 = lane >> 4;
    const int g    = lane >> 2;
    const int t2   = (lane & 3) * 2;
    const int wm16 = wid * 16;

    const int nh = blockIdx.y;
    const int nb = nh >> 4;
    const int qt = blockIdx.x;
    const size_t hb = (size_t)nh * SEQ * DH;
    const size_t qoff = hb + (size_t)qt * 128 * DH;
    const int* mk = mask + nb * SEQ;

    auto issueK = [&](int kb) {
#pragma unroll
        for (int i = 0; i < 4; i++) {
            const int idx = i * 256 + tid;
            const int mat = idx >> 9;
            const int r = (idx >> 3) & 63;
            const int s = idx & 7;
            const __nv_bfloat16* gb = mat ? g_kl : g_kh;
            CP_ASYNC16(sb + OFF_KH + mat * 64 * AROW + r * AROW + s * 16,
                       gb + hb + (size_t)(kb * 64 + r) * DH + s * 8);
        }
    };
    auto issueV = [&](int kb) {
#pragma unroll
        for (int i = 0; i < 4; i++) {
            const int idx = i * 256 + tid;
            const int mat = idx >> 9;
            const int r = (idx >> 3) & 63;
            const int s = idx & 7;
            const __nv_bfloat16* gb = mat ? g_vl : g_vh;
            CP_ASYNC16(sb + OFF_KH + (2 + mat) * 64 * AROW + r * AROW + s * 16,
                       gb + hb + (size_t)(kb * 64 + r) * DH + s * 8);
        }
    };

    // ---- pre-loop: Q tile + K_0 + mask_0 ----
#pragma unroll
    for (int i = 0; i < 8; i++) {
        const int idx = i * 256 + tid;
        const int mat = idx >> 10;            // 0: hi, 1: lo
        const int r = (idx >> 3) & 127;
        const int s = idx & 7;
        const __nv_bfloat16* gp = (mat ? g_ql : g_qh) + qoff + r * DH + s * 8;
        CP_ASYNC16(sb + (mat ? OFF_QL : OFF_QH) + r * AROW + s * 16, gp);
    }
    CP_COMMIT();
    if (tid < 64) *(int*)(sm + OFF_MSK + tid * 4) = mk[tid];   // mask_0 -> buf 0
    issueK(0);
    CP_COMMIT();

    float m0 = -INFINITY, m1 = -INFINITY, l0 = 0.f, l1 = 0.f;
    float co[8][4];
#pragma unroll
    for (int nt = 0; nt < 8; nt++)
#pragma unroll
        for (int r = 0; r < 4; r++) co[nt][r] = 0.f;

    for (int kb = 0; kb < SEQ / 64; kb++) {
        CP_WAIT0();
        __syncthreads();

        issueV(kb);
        CP_COMMIT();

        // S = Q K^T
        float cs[8][4];
#pragma unroll
        for (int nt = 0; nt < 8; nt++)
#pragma unroll
            for (int r = 0; r < 4; r++) cs[nt][r] = 0.f;

#pragma unroll
        for (int ks = 0; ks < 4; ks++) {
            const int kk2 = ks * 32;
            const uint32_t ra = (uint32_t)(wm16 + lr + 8 * lh8) * AROW + kk2 + 16 * lh16;
            uint32_t ah[4], al[4];
            LDSM_X4(ah[0], ah[1], ah[2], ah[3], sb + OFF_QH + ra);
            LDSM_X4(al[0], al[1], al[2], al[3], sb + OFF_QL + ra);
#pragma unroll
            for (int np = 0; np < 4; np++) {
                const uint32_t rb = (uint32_t)(np * 16 + lr + 8 * lh16) * AROW + kk2 + 16 * lh8;
                uint32_t b0, b1, b2, b3;
                LDSM_X4(b0, b1, b2, b3, sb + OFF_KH + rb);             // Kh
                mma_bf16(cs[np * 2 + 0], ah, b0, b1);
                mma_bf16(cs[np * 2 + 1], ah, b2, b3);
                mma_bf16(cs[np * 2 + 0], al, b0, b1);
                mma_bf16(cs[np * 2 + 1], al, b2, b3);
                LDSM_X4(b0, b1, b2, b3, sb + OFF_KH + 64 * AROW + rb); // Kl
                mma_bf16(cs[np * 2 + 0], ah, b0, b1);
                mma_bf16(cs[np * 2 + 1], ah, b2, b3);
            }
        }

        // mask
        const uint32_t mbase = OFF_MSK + (kb & 1) * 256;
#pragma unroll
        for (int nt = 0; nt < 8; nt++) {
            int2 mv = *(const int2*)(sm + mbase + (nt * 8 + t2) * 4);
            if (!mv.x) { cs[nt][0] = NEGINF; cs[nt][2] = NEGINF; }
            if (!mv.y) { cs[nt][1] = NEGINF; cs[nt][3] = NEGINF; }
        }

        // online softmax
        float mx0 = NEGINF, mx1 = NEGINF;
#pragma unroll
        for (int nt = 0; nt < 8; nt++) {
            mx0 = fmaxf(mx0, fmaxf(cs[nt][0], cs[nt][1]));
            mx1 = fmaxf(mx1, fmaxf(cs[nt][2], cs[nt][3]));
        }
        mx0 = fmaxf(mx0, __shfl_xor_sync(0xffffffffu, mx0, 1));
        mx0 = fmaxf(mx0, __shfl_xor_sync(0xffffffffu, mx0, 2));
        mx1 = fmaxf(mx1, __shfl_xor_sync(0xffffffffu, mx1, 1));
        mx1 = fmaxf(mx1, __shfl_xor_sync(0xffffffffu, mx1, 2));
        const float mn0 = fmaxf(m0, mx0), mn1 = fmaxf(m1, mx1);
        const float corr0 = __expf(m0 - mn0), corr1 = __expf(m1 - mn1);
        float s0 = 0.f, s1 = 0.f;
        const int prow0 = (wm16 + g) * AROW, prow1 = (wm16 + g + 8) * AROW;
#pragma unroll
        for (int nt = 0; nt < 8; nt++) {
            const int cb = (nt * 8 + t2) * 2;
            float p00 = __expf(cs[nt][0] - mn0);
            float p01 = __expf(cs[nt][1] - mn0);
            float p10 = __expf(cs[nt][2] - mn1);
            float p11 = __expf(cs[nt][3] - mn1);
            s0 += p00 + p01; s1 += p10 + p11;
            *(__nv_bfloat162*)(sm + OFF_PH + prow0 + cb) = hi2(p00, p01);
            *(__nv_bfloat162*)(sm + OFF_PH + prow1 + cb) = hi2(p10, p11);
            *(__nv_bfloat162*)(sm + OFF_PL + prow0 + cb) = lo2(p00, p01);
            *(__nv_bfloat162*)(sm + OFF_PL + prow1 + cb) = lo2(p10, p11);
        }
        s0 += __shfl_xor_sync(0xffffffffu, s0, 1);
        s0 += __shfl_xor_sync(0xffffffffu, s0, 2);
        s1 += __shfl_xor_sync(0xffffffffu, s1, 1);
        s1 += __shfl_xor_sync(0xffffffffu, s1, 2);
        l0 = l0 * corr0 + s0; m0 = mn0;
        l1 = l1 * corr1 + s1; m1 = mn1;
#pragma unroll
        for (int nt = 0; nt < 8; nt++) {
            co[nt][0] *= corr0; co[nt][1] *= corr0;
            co[nt][2] *= corr1; co[nt][3] *= corr1;
        }

        CP_WAIT0();
        __syncthreads();

        if (kb + 1 < SEQ / 64) {
            issueK(kb + 1);
            if (tid < 64)
                *(int*)(sm + OFF_MSK + ((kb + 1) & 1) * 256 + tid * 4) = mk[(kb + 1) * 64 + tid];
            CP_COMMIT();
        }

        // O += P V
#pragma unroll
        for (int ks = 0; ks < 4; ks++) {
            const int kk2 = ks * 32;
            const uint32_t ra = (uint32_t)(wm16 + lr + 8 * lh8) * AROW + kk2 + 16 * lh16;
            uint32_t ph[4], pl[4];
            LDSM_X4(ph[0], ph[1], ph[2], ph[3], sb + OFF_PH + ra);
            LDSM_X4(pl[0], pl[1], pl[2], pl[3], sb + OFF_PL + ra);
#pragma unroll
            for (int np = 0; np < 4; np++) {
                const uint32_t rv = (uint32_t)(ks * 16 + lr + 8 * lh8) * AROW
                                  + np * 32 + 16 * lh16;
                uint32_t b0, b1, b2, b3;
                LDSM_X4T(b0, b1, b2, b3, sb + OFF_KH + 2 * 64 * AROW + rv);   // Vh
                mma_bf16(co[np * 2 + 0], ph, b0, b1);
                mma_bf16(co[np * 2 + 1], ph, b2, b3);
                mma_bf16(co[np * 2 + 0], pl, b0, b1);
                mma_bf16(co[np * 2 + 1], pl, b2, b3);
                LDSM_X4T(b0, b1, b2, b3, sb + OFF_KH + 3 * 64 * AROW + rv);   // Vl
                mma_bf16(co[np * 2 + 0], ph, b0, b1);
                mma_bf16(co[np * 2 + 1], ph, b2, b3);
            }
        }
        __syncwarp();
    }

    // ---- epilogue ----
    const float i0 = 1.f / l0, i1 = 1.f / l1;
    const int r0 = wm16 + g, r1 = wm16 + g + 8;
#pragma unroll
    for (int nt = 0; nt < 8; nt++) {
        const int col = nt * 8 + t2;
        float v0 = co[nt][0] * i0, v1 = co[nt][1] * i0;
        float v2 = co[nt][2] * i1, v3 = co[nt][3] * i1;
        size_t o0 = qoff + (size_t)r0 * DH + col;
        size_t o1 = qoff + (size_t)r1 * DH + col;
        *(__nv_bfloat162*)&g_xh[o0] = hi2(v0, v1);
        *(__nv_bfloat162*)&g_xl[o0] = lo2(v0, v1);
        *(__nv_bfloat162*)&g_xh[o1] = hi2(v2, v3);
        *(__nv_bfloat162*)&g_xl[o1] = lo2(v2, v3);
    }
}

// ---------------------------------------------------------------------------
extern "C" void kernel_launch(void* const* d_in, const int* in_sizes, int n_in,
                              void* d_out, int out_size)
{
    const float* x   = (const float*)d_in[0];
    const int*  mask = (const int*)  d_in[1];
    const float* wq  = (const float*)d_in[2];
    const float* bq  = (const float*)d_in[3];
    const float* wk  = (const float*)d_in[4];
    const float* bk  = (const float*)d_in[5];
    const float* wv  = (const float*)d_in[6];
    const float* bv  = (const float*)d_in[7];
    const float* wo  = (const float*)d_in[8];
    const float* bo  = (const float*)d_in[9];
    float* out = (float*)d_out;

    const int gemm_smem = 2 * STG_BYTES;            // 81920 B
    cudaFuncSetAttribute(gemm_mma, cudaFuncAttributeMaxDynamicSharedMemorySize, gemm_smem);
    cudaFuncSetAttribute(attn_mma, cudaFuncAttributeMaxDynamicSharedMemorySize, ATT_SMEM);

    dim3 ggrid(DMODEL / 128, MROWS / 128);          // (8, 64)
    const int nsplit = (MROWS * DMODEL / 4 + 255) / 256;

    split_bf16<<<nsplit, 256>>>(x);
    transpose_split4<<<dim3(32, 32, 4), dim3(32, 8)>>>(wq, wk, wv, wo);

    gemm_mma<<<ggrid, 256, gemm_smem>>>(bq, out, 0, 0);
    gemm_mma<<<ggrid, 256, gemm_smem>>>(bk, out, 1, 1);
    gemm_mma<<<ggrid, 256, gemm_smem>>>(bv, out, 2, 2);

    attn_mma<<<dim3(SEQ / 128, NB * NHEADS), 256, ATT_SMEM>>>(mask);

    gemm_mma<<<ggrid, 256, gemm_smem>>>(bo, out, 3, 3);
}

// round 12
// speedup vs baseline: 3.4380x; 1.0419x over previous
#include <cuda_runtime.h>
#include <cuda_bf16.h>
#include <math.h>
#include <stdint.h>

#define NB     4
#define SEQ    2048
#define DMODEL 1024
#define NHEADS 16
#define DH     64
#define MROWS  8192
#define NEGINF -1e30f

// ---------------------------------------------------------------------------
// Static scratch (all projection outputs live as pre-split bf16 hi/lo)
// ---------------------------------------------------------------------------
__device__ __nv_bfloat16 g_xh[MROWS*DMODEL];     // activation hi (also attn out)
__device__ __nv_bfloat16 g_xl[MROWS*DMODEL];     // activation lo
__device__ __nv_bfloat16 g_wth4[4*DMODEL*DMODEL]; // weight^T hi [4][N][K]
__device__ __nv_bfloat16 g_wtl4[4*DMODEL*DMODEL]; // weight^T lo [4][N][K]
__device__ __nv_bfloat16 g_qh[MROWS*DMODEL];     // Q hi (1/8 scale folded)
__device__ __nv_bfloat16 g_ql[MROWS*DMODEL];
__device__ __nv_bfloat16 g_kh[MROWS*DMODEL];
__device__ __nv_bfloat16 g_kl[MROWS*DMODEL];
__device__ __nv_bfloat16 g_vh[MROWS*DMODEL];
__device__ __nv_bfloat16 g_vl[MROWS*DMODEL];

// ---------------------------------------------------------------------------
// PTX helpers (sm_100 base target)
// ---------------------------------------------------------------------------
__device__ __forceinline__ uint32_t smem_u32(const void* p) {
    uint32_t a;
    asm("{ .reg .u64 t; cvta.to.shared.u64 t, %1; cvt.u32.u64 %0, t; }" : "=r"(a) : "l"(p));
    return a;
}
#define CP_ASYNC16(saddr, gptr) \
    asm volatile("cp.async.cg.shared.global [%0], [%1], 16;" :: "r"(saddr), "l"(gptr))
#define CP_COMMIT() asm volatile("cp.async.commit_group;" ::: "memory")
#define CP_WAIT1()  asm volatile("cp.async.wait_group 1;" ::: "memory")
#define CP_WAIT0()  asm volatile("cp.async.wait_group 0;" ::: "memory")

#define LDSM_X4(r0, r1, r2, r3, addr) \
    asm volatile("ldmatrix.sync.aligned.m8n8.x4.shared.b16 {%0,%1,%2,%3}, [%4];" \
        : "=r"(r0), "=r"(r1), "=r"(r2), "=r"(r3) : "r"(addr))
#define LDSM_X4T(r0, r1, r2, r3, addr) \
    asm volatile("ldmatrix.sync.aligned.m8n8.x4.trans.shared.b16 {%0,%1,%2,%3}, [%4];" \
        : "=r"(r0), "=r"(r1), "=r"(r2), "=r"(r3) : "r"(addr))

__device__ __forceinline__ void mma_bf16(float* c, const uint32_t* a,
                                         uint32_t b0, uint32_t b1) {
    asm volatile(
        "mma.sync.aligned.m16n8k16.row.col.f32.bf16.bf16.f32 "
        "{%0,%1,%2,%3}, {%4,%5,%6,%7}, {%8,%9}, {%0,%1,%2,%3};"
        : "+f"(c[0]), "+f"(c[1]), "+f"(c[2]), "+f"(c[3])
        : "r"(a[0]), "r"(a[1]), "r"(a[2]), "r"(a[3]), "r"(b0), "r"(b1));
}

__device__ __forceinline__ __nv_bfloat162 hi2(float a, float b) {
    return __halves2bfloat162(__float2bfloat16(a), __float2bfloat16(b));
}
__device__ __forceinline__ __nv_bfloat162 lo2(float a, float b) {
    __nv_bfloat16 ha = __float2bfloat16(a), hb = __float2bfloat16(b);
    return __halves2bfloat162(__float2bfloat16(a - __bfloat162float(ha)),
                              __float2bfloat16(b - __bfloat162float(hb)));
}

// ---------------------------------------------------------------------------
// fp32 -> bf16 hi/lo split of x
// ---------------------------------------------------------------------------
__global__ __launch_bounds__(256) void split_bf16(const float* __restrict__ src) {
    size_t i4 = ((size_t)blockIdx.x * 256 + threadIdx.x) * 4;
    if (i4 >= (size_t)MROWS * DMODEL) return;
    float4 v = *(const float4*)(src + i4);
    float a[4] = {v.x, v.y, v.z, v.w};
#pragma unroll
    for (int j = 0; j < 4; j++) {
        __nv_bfloat16 hi = __float2bfloat16(a[j]);
        __nv_bfloat16 lo = __float2bfloat16(a[j] - __bfloat162float(hi));
        g_xh[i4 + j] = hi;
        g_xl[i4 + j] = lo;
    }
}

// ---------------------------------------------------------------------------
// All-four weight transpose + split: w[z] [K][N] fp32 -> slot z of [N][K] bf16
// ---------------------------------------------------------------------------
__global__ __launch_bounds__(256) void transpose_split4(
    const float* __restrict__ wq, const float* __restrict__ wk,
    const float* __restrict__ wv, const float* __restrict__ wo) {
    __shared__ float t[32][33];
    const int tx = threadIdx.x, ty = threadIdx.y;    // 32 x 8
    const int n0 = blockIdx.x * 32, k0 = blockIdx.y * 32;
    const int z = blockIdx.z;
    const float* w = (z == 0) ? wq : (z == 1) ? wk : (z == 2) ? wv : wo;
    __nv_bfloat16* H = g_wth4 + (size_t)z * DMODEL * DMODEL;
    __nv_bfloat16* L = g_wtl4 + (size_t)z * DMODEL * DMODEL;
#pragma unroll
    for (int i = 0; i < 4; i++)
        t[ty + i * 8][tx] = w[(size_t)(k0 + ty + i * 8) * DMODEL + n0 + tx];
    __syncthreads();
#pragma unroll
    for (int i = 0; i < 4; i++) {
        float v = t[tx][ty + i * 8];
        __nv_bfloat16 hi = __float2bfloat16(v);
        __nv_bfloat16 lo = __float2bfloat16(v - __bfloat162float(hi));
        size_t o = (size_t)(n0 + ty + i * 8) * DMODEL + (k0 + tx);
        H[o] = hi;
        L[o] = lo;
    }
}

// ---------------------------------------------------------------------------
// mma.sync bf16-split GEMM, ILP-scheduled: all 4 Bh fragments live in
// distinct registers so the 16 ah*bh MMAs (then 16 al*bh) hit 16 independent
// accumulators -- no same-acc RAW at distance 2 (R11: that chain held tensor
// at 52%). mode 0: merged QKV (grid.x = 24, wsel = bx>>3, split bf16 out).
// mode 1: output projection (grid.x = 8, fp32 to Cext).
// ---------------------------------------------------------------------------
#define MAT_BYTES   10240
#define STG_BYTES   40960
#define ROW_B       80
#define NCHUNK      32

__global__ __launch_bounds__(256, 2) void gemm_mma(
    const float* __restrict__ biasQ, const float* __restrict__ biasK,
    const float* __restrict__ biasV, const float* __restrict__ biasO,
    float* __restrict__ Cext, int mode) {
    extern __shared__ char smem[];
    const uint32_t sb = smem_u32(smem);
    const int tid  = threadIdx.x;
    const int wid  = tid >> 5;
    const int lane = tid & 31;
    const int wm = wid & 3;
    const int wn = wid >> 2;
    const int wsel    = (mode == 0) ? (blockIdx.x >> 3) : 3;
    const int dst_sel = (mode == 0) ? wsel : 3;
    const float* bias = (mode == 1) ? biasO
                      : (wsel == 0) ? biasQ : (wsel == 1) ? biasK : biasV;
    const int bn = (mode == 0 ? (blockIdx.x & 7) : blockIdx.x) * 128;
    const int bm = blockIdx.y * 128;
    const __nv_bfloat16* WH = g_wth4 + (size_t)wsel * DMODEL * DMODEL;
    const __nv_bfloat16* WL = g_wtl4 + (size_t)wsel * DMODEL * DMODEL;

    float c[2][8][4];
#pragma unroll
    for (int mt = 0; mt < 2; mt++)
#pragma unroll
        for (int nt = 0; nt < 8; nt++)
#pragma unroll
            for (int r = 0; r < 4; r++) c[mt][nt][r] = 0.f;

    auto issue = [&](int chunk, int stage) {
        const int k0 = chunk * 32;
        const uint32_t stg = sb + stage * STG_BYTES;
#pragma unroll
        for (int i = 0; i < 8; i++) {
            const int idx = i * 256 + tid;
            const int mat = idx >> 9;
            const int row = (idx >> 2) & 127;
            const int seg = idx & 3;
            const uint32_t sa = stg + mat * MAT_BYTES + row * ROW_B + seg * 16;
            const __nv_bfloat16* gp;
            if (mat == 0)      gp = g_xh + (size_t)(bm + row) * DMODEL + k0 + seg * 8;
            else if (mat == 1) gp = g_xl + (size_t)(bm + row) * DMODEL + k0 + seg * 8;
            else if (mat == 2) gp = WH   + (size_t)(bn + row) * DMODEL + k0 + seg * 8;
            else               gp = WL   + (size_t)(bn + row) * DMODEL + k0 + seg * 8;
            CP_ASYNC16(sa, gp);
        }
        CP_COMMIT();
    };

    issue(0, 0);

    const int lr  = lane & 7;
    const int lh8 = (lane >> 3) & 1;
    const int lh16 = lane >> 4;

    for (int chunk = 0; chunk < NCHUNK; chunk++) {
        if (chunk + 1 < NCHUNK) issue(chunk + 1, (chunk + 1) & 1);
        if (chunk + 1 < NCHUNK) { CP_WAIT1(); } else { CP_WAIT0(); }
        __syncthreads();

        const uint32_t stg = sb + (chunk & 1) * STG_BYTES;
        const uint32_t Ah = stg;
        const uint32_t Al = stg + MAT_BYTES;
        const uint32_t Bh = stg + 2 * MAT_BYTES;
        const uint32_t Bl = stg + 3 * MAT_BYTES;

#pragma unroll
        for (int ks = 0; ks < 2; ks++) {
            const int kb = ks * 32;
            uint32_t ah[2][4], al[2][4];
#pragma unroll
            for (int mt = 0; mt < 2; mt++) {
                const uint32_t ra = (uint32_t)(wm * 32 + mt * 16 + lr + 8 * lh8) * ROW_B
                                  + kb + 16 * lh16;
                LDSM_X4(ah[mt][0], ah[mt][1], ah[mt][2], ah[mt][3], Ah + ra);
                LDSM_X4(al[mt][0], al[mt][1], al[mt][2], al[mt][3], Al + ra);
            }
            // all 4 Bh fragments in distinct registers
            uint32_t bh[4][4];
#pragma unroll
            for (int np = 0; np < 4; np++) {
                const uint32_t rb = (uint32_t)(wn * 64 + np * 16 + lr + 8 * lh16) * ROW_B
                                  + kb + 16 * lh8;
                LDSM_X4(bh[np][0], bh[np][1], bh[np][2], bh[np][3], Bh + rb);
            }
            // term 1: ah x bh -- 16 independent accumulators
#pragma unroll
            for (int np = 0; np < 4; np++)
#pragma unroll
                for (int mt = 0; mt < 2; mt++) {
                    mma_bf16(c[mt][np * 2 + 0], ah[mt], bh[np][0], bh[np][1]);
                    mma_bf16(c[mt][np * 2 + 1], ah[mt], bh[np][2], bh[np][3]);
                }
            // term 2: al x bh -- same 16 targets, distance 16 from term 1
#pragma unroll
            for (int np = 0; np < 4; np++)
#pragma unroll
                for (int mt = 0; mt < 2; mt++) {
                    mma_bf16(c[mt][np * 2 + 0], al[mt], bh[np][0], bh[np][1]);
                    mma_bf16(c[mt][np * 2 + 1], al[mt], bh[np][2], bh[np][3]);
                }
            // term 3: ah x bl, np pairs (8 independent targets per pair)
#pragma unroll
            for (int nh = 0; nh < 2; nh++) {
                uint32_t bl[2][4];
#pragma unroll
                for (int j = 0; j < 2; j++) {
                    const int np = nh * 2 + j;
                    const uint32_t rb = (uint32_t)(wn * 64 + np * 16 + lr + 8 * lh16) * ROW_B
                                      + kb + 16 * lh8;
                    LDSM_X4(bl[j][0], bl[j][1], bl[j][2], bl[j][3], Bl + rb);
                }
#pragma unroll
                for (int j = 0; j < 2; j++) {
                    const int np = nh * 2 + j;
#pragma unroll
                    for (int mt = 0; mt < 2; mt++) {
                        mma_bf16(c[mt][np * 2 + 0], ah[mt], bl[j][0], bl[j][1]);
                        mma_bf16(c[mt][np * 2 + 1], ah[mt], bl[j][2], bl[j][3]);
                    }
                }
            }
        }
        __syncthreads();
    }

    const int rg = lane >> 2;
    const int cg = (lane & 3) * 2;
    if (dst_sel == 3) {
#pragma unroll
        for (int mt = 0; mt < 2; mt++)
#pragma unroll
            for (int nt = 0; nt < 8; nt++) {
                const int row = bm + wm * 32 + mt * 16 + rg;
                const int col = bn + wn * 64 + nt * 8 + cg;
                const float b0 = bias[col], b1 = bias[col + 1];
                *(float2*)&Cext[(size_t)row * DMODEL + col] =
                    make_float2(c[mt][nt][0] + b0, c[mt][nt][1] + b1);
                *(float2*)&Cext[(size_t)(row + 8) * DMODEL + col] =
                    make_float2(c[mt][nt][2] + b0, c[mt][nt][3] + b1);
            }
    } else {
        __nv_bfloat16* H = (dst_sel == 0) ? g_qh : (dst_sel == 1) ? g_kh : g_vh;
        __nv_bfloat16* L = (dst_sel == 0) ? g_ql : (dst_sel == 1) ? g_kl : g_vl;
        const float scl = (dst_sel == 0) ? 0.125f : 1.f;
#pragma unroll
        for (int mt = 0; mt < 2; mt++)
#pragma unroll
            for (int nt = 0; nt < 8; nt++) {
                const int row = bm + wm * 32 + mt * 16 + rg;
                const int col = bn + wn * 64 + nt * 8 + cg;
                const float b0 = bias[col], b1 = bias[col + 1];
                float v0 = (c[mt][nt][0] + b0) * scl, v1 = (c[mt][nt][1] + b1) * scl;
                float v2 = (c[mt][nt][2] + b0) * scl, v3 = (c[mt][nt][3] + b1) * scl;
                size_t o0 = (size_t)row * DMODEL + col;
                size_t o1 = (size_t)(row + 8) * DMODEL + col;
                *(__nv_bfloat162*)&H[o0] = hi2(v0, v1);
                *(__nv_bfloat162*)&L[o0] = lo2(v0, v1);
                *(__nv_bfloat162*)&H[o1] = hi2(v2, v3);
                *(__nv_bfloat162*)&L[o1] = lo2(v2, v3);
            }
    }
}

// ---------------------------------------------------------------------------
// Tensor-core flash attention (unchanged from R11)
// ---------------------------------------------------------------------------
#define AROW    144
#define OFF_QH  0
#define OFF_QL  (128*AROW)
#define OFF_KH  (2*128*AROW)
#define OFF_PH  (OFF_KH + 4*64*AROW)
#define OFF_PL  (OFF_PH + 128*AROW)
#define OFF_MSK (OFF_PL + 128*AROW)
#define ATT_SMEM (OFF_MSK + 512)          // 2 x 256B mask buffers

__global__ __launch_bounds__(256, 2) void attn_mma(const int* __restrict__ mask)
{
    extern __shared__ char sm[];
    const uint32_t sb = smem_u32(sm);
    const int tid  = threadIdx.x;
    const int wid  = tid >> 5;
    const int lane = tid & 31;
    const int lr   = lane & 7;
    const int lh8  = (lane >> 3) & 1;
    const int lh16 = lane >> 4;
    const int g    = lane >> 2;
    const int t2   = (lane & 3) * 2;
    const int wm16 = wid * 16;

    const int nh = blockIdx.y;
    const int nb = nh >> 4;
    const int qt = blockIdx.x;
    const size_t hb = (size_t)nh * SEQ * DH;
    const size_t qoff = hb + (size_t)qt * 128 * DH;
    const int* mk = mask + nb * SEQ;

    auto issueK = [&](int kb) {
#pragma unroll
        for (int i = 0; i < 4; i++) {
            const int idx = i * 256 + tid;
            const int mat = idx >> 9;
            const int r = (idx >> 3) & 63;
            const int s = idx & 7;
            const __nv_bfloat16* gb = mat ? g_kl : g_kh;
            CP_ASYNC16(sb + OFF_KH + mat * 64 * AROW + r * AROW + s * 16,
                       gb + hb + (size_t)(kb * 64 + r) * DH + s * 8);
        }
    };
    auto issueV = [&](int kb) {
#pragma unroll
        for (int i = 0; i < 4; i++) {
            const int idx = i * 256 + tid;
            const int mat = idx >> 9;
            const int r = (idx >> 3) & 63;
            const int s = idx & 7;
            const __nv_bfloat16* gb = mat ? g_vl : g_vh;
            CP_ASYNC16(sb + OFF_KH + (2 + mat) * 64 * AROW + r * AROW + s * 16,
                       gb + hb + (size_t)(kb * 64 + r) * DH + s * 8);
        }
    };

    // ---- pre-loop: Q tile + K_0 + mask_0 ----
#pragma unroll
    for (int i = 0; i < 8; i++) {
        const int idx = i * 256 + tid;
        const int mat = idx >> 10;            // 0: hi, 1: lo
        const int r = (idx >> 3) & 127;
        const int s = idx & 7;
        const __nv_bfloat16* gp = (mat ? g_ql : g_qh) + qoff + r * DH + s * 8;
        CP_ASYNC16(sb + (mat ? OFF_QL : OFF_QH) + r * AROW + s * 16, gp);
    }
    CP_COMMIT();
    if (tid < 64) *(int*)(sm + OFF_MSK + tid * 4) = mk[tid];   // mask_0 -> buf 0
    issueK(0);
    CP_COMMIT();

    float m0 = -INFINITY, m1 = -INFINITY, l0 = 0.f, l1 = 0.f;
    float co[8][4];
#pragma unroll
    for (int nt = 0; nt < 8; nt++)
#pragma unroll
        for (int r = 0; r < 4; r++) co[nt][r] = 0.f;

    for (int kb = 0; kb < SEQ / 64; kb++) {
        CP_WAIT0();
        __syncthreads();

        issueV(kb);
        CP_COMMIT();

        // S = Q K^T
        float cs[8][4];
#pragma unroll
        for (int nt = 0; nt < 8; nt++)
#pragma unroll
            for (int r = 0; r < 4; r++) cs[nt][r] = 0.f;

#pragma unroll
        for (int ks = 0; ks < 4; ks++) {
            const int kk2 = ks * 32;
            const uint32_t ra = (uint32_t)(wm16 + lr + 8 * lh8) * AROW + kk2 + 16 * lh16;
            uint32_t ah[4], al[4];
            LDSM_X4(ah[0], ah[1], ah[2], ah[3], sb + OFF_QH + ra);
            LDSM_X4(al[0], al[1], al[2], al[3], sb + OFF_QL + ra);
#pragma unroll
            for (int np = 0; np < 4; np++) {
                const uint32_t rb = (uint32_t)(np * 16 + lr + 8 * lh16) * AROW + kk2 + 16 * lh8;
                uint32_t b0, b1, b2, b3;
                LDSM_X4(b0, b1, b2, b3, sb + OFF_KH + rb);             // Kh
                mma_bf16(cs[np * 2 + 0], ah, b0, b1);
                mma_bf16(cs[np * 2 + 1], ah, b2, b3);
                mma_bf16(cs[np * 2 + 0], al, b0, b1);
                mma_bf16(cs[np * 2 + 1], al, b2, b3);
                LDSM_X4(b0, b1, b2, b3, sb + OFF_KH + 64 * AROW + rb); // Kl
                mma_bf16(cs[np * 2 + 0], ah, b0, b1);
                mma_bf16(cs[np * 2 + 1], ah, b2, b3);
            }
        }

        // mask
        const uint32_t mbase = OFF_MSK + (kb & 1) * 256;
#pragma unroll
        for (int nt = 0; nt < 8; nt++) {
            int2 mv = *(const int2*)(sm + mbase + (nt * 8 + t2) * 4);
            if (!mv.x) { cs[nt][0] = NEGINF; cs[nt][2] = NEGINF; }
            if (!mv.y) { cs[nt][1] = NEGINF; cs[nt][3] = NEGINF; }
        }

        // online softmax
        float mx0 = NEGINF, mx1 = NEGINF;
#pragma unroll
        for (int nt = 0; nt < 8; nt++) {
            mx0 = fmaxf(mx0, fmaxf(cs[nt][0], cs[nt][1]));
            mx1 = fmaxf(mx1, fmaxf(cs[nt][2], cs[nt][3]));
        }
        mx0 = fmaxf(mx0, __shfl_xor_sync(0xffffffffu, mx0, 1));
        mx0 = fmaxf(mx0, __shfl_xor_sync(0xffffffffu, mx0, 2));
        mx1 = fmaxf(mx1, __shfl_xor_sync(0xffffffffu, mx1, 1));
        mx1 = fmaxf(mx1, __shfl_xor_sync(0xffffffffu, mx1, 2));
        const float mn0 = fmaxf(m0, mx0), mn1 = fmaxf(m1, mx1);
        const float corr0 = __expf(m0 - mn0), corr1 = __expf(m1 - mn1);
        float s0 = 0.f, s1 = 0.f;
        const int prow0 = (wm16 + g) * AROW, prow1 = (wm16 + g + 8) * AROW;
#pragma unroll
        for (int nt = 0; nt < 8; nt++) {
            const int cb = (nt * 8 + t2) * 2;
            float p00 = __expf(cs[nt][0] - mn0);
            float p01 = __expf(cs[nt][1] - mn0);
            float p10 = __expf(cs[nt][2] - mn1);
            float p11 = __expf(cs[nt][3] - mn1);
            s0 += p00 + p01; s1 += p10 + p11;
            *(__nv_bfloat162*)(sm + OFF_PH + prow0 + cb) = hi2(p00, p01);
            *(__nv_bfloat162*)(sm + OFF_PH + prow1 + cb) = hi2(p10, p11);
            *(__nv_bfloat162*)(sm + OFF_PL + prow0 + cb) = lo2(p00, p01);
            *(__nv_bfloat162*)(sm + OFF_PL + prow1 + cb) = lo2(p10, p11);
        }
        s0 += __shfl_xor_sync(0xffffffffu, s0, 1);
        s0 += __shfl_xor_sync(0xffffffffu, s0, 2);
        s1 += __shfl_xor_sync(0xffffffffu, s1, 1);
        s1 += __shfl_xor_sync(0xffffffffu, s1, 2);
        l0 = l0 * corr0 + s0; m0 = mn0;
        l1 = l1 * corr1 + s1; m1 = mn1;
#pragma unroll
        for (int nt = 0; nt < 8; nt++) {
            co[nt][0] *= corr0; co[nt][1] *= corr0;
            co[nt][2] *= corr1; co[nt][3] *= corr1;
        }

        CP_WAIT0();
        __syncthreads();

        if (kb + 1 < SEQ / 64) {
            issueK(kb + 1);
            if (tid < 64)
                *(int*)(sm + OFF_MSK + ((kb + 1) & 1) * 256 + tid * 4) = mk[(kb + 1) * 64 + tid];
            CP_COMMIT();
        }

        // O += P V
#pragma unroll
        for (int ks = 0; ks < 4; ks++) {
            const int kk2 = ks * 32;
            const uint32_t ra = (uint32_t)(wm16 + lr + 8 * lh8) * AROW + kk2 + 16 * lh16;
            uint32_t ph[4], pl[4];
            LDSM_X4(ph[0], ph[1], ph[2], ph[3], sb + OFF_PH + ra);
            LDSM_X4(pl[0], pl[1], pl[2], pl[3], sb + OFF_PL + ra);
#pragma unroll
            for (int np = 0; np < 4; np++) {
                const uint32_t rv = (uint32_t)(ks * 16 + lr + 8 * lh8) * AROW
                                  + np * 32 + 16 * lh16;
                uint32_t b0, b1, b2, b3;
                LDSM_X4T(b0, b1, b2, b3, sb + OFF_KH + 2 * 64 * AROW + rv);   // Vh
                mma_bf16(co[np * 2 + 0], ph, b0, b1);
                mma_bf16(co[np * 2 + 1], ph, b2, b3);
                mma_bf16(co[np * 2 + 0], pl, b0, b1);
                mma_bf16(co[np * 2 + 1], pl, b2, b3);
                LDSM_X4T(b0, b1, b2, b3, sb + OFF_KH + 3 * 64 * AROW + rv);   // Vl
                mma_bf16(co[np * 2 + 0], ph, b0, b1);
                mma_bf16(co[np * 2 + 1], ph, b2, b3);
            }
        }
        __syncwarp();
    }

    // ---- epilogue ----
    const float i0 = 1.f / l0, i1 = 1.f / l1;
    const int r0 = wm16 + g, r1 = wm16 + g + 8;
#pragma unroll
    for (int nt = 0; nt < 8; nt++) {
        const int col = nt * 8 + t2;
        float v0 = co[nt][0] * i0, v1 = co[nt][1] * i0;
        float v2 = co[nt][2] * i1, v3 = co[nt][3] * i1;
        size_t o0 = qoff + (size_t)r0 * DH + col;
        size_t o1 = qoff + (size_t)r1 * DH + col;
        *(__nv_bfloat162*)&g_xh[o0] = hi2(v0, v1);
        *(__nv_bfloat162*)&g_xl[o0] = lo2(v0, v1);
        *(__nv_bfloat162*)&g_xh[o1] = hi2(v2, v3);
        *(__nv_bfloat162*)&g_xl[o1] = lo2(v2, v3);
    }
}

// ---------------------------------------------------------------------------
extern "C" void kernel_launch(void* const* d_in, const int* in_sizes, int n_in,
                              void* d_out, int out_size)
{
    const float* x   = (const float*)d_in[0];
    const int*  mask = (const int*)  d_in[1];
    const float* wq  = (const float*)d_in[2];
    const float* bq  = (const float*)d_in[3];
    const float* wk  = (const float*)d_in[4];
    const float* bk  = (const float*)d_in[5];
    const float* wv  = (const float*)d_in[6];
    const float* bv  = (const float*)d_in[7];
    const float* wo  = (const float*)d_in[8];
    const float* bo  = (const float*)d_in[9];
    float* out = (float*)d_out;

    const int gemm_smem = 2 * STG_BYTES;            // 81920 B
    cudaFuncSetAttribute(gemm_mma, cudaFuncAttributeMaxDynamicSharedMemorySize, gemm_smem);
    cudaFuncSetAttribute(attn_mma, cudaFuncAttributeMaxDynamicSharedMemorySize, ATT_SMEM);

    const int nsplit = (MROWS * DMODEL / 4 + 255) / 256;

    split_bf16<<<nsplit, 256>>>(x);
    transpose_split4<<<dim3(32, 32, 4), dim3(32, 8)>>>(wq, wk, wv, wo);

    // merged QKV projection: grid.x = 3 * 8
    gemm_mma<<<dim3(24, 64), 256, gemm_smem>>>(bq, bk, bv, bo, out, 0);

    attn_mma<<<dim3(SEQ / 128, NB * NHEADS), 256, ATT_SMEM>>>(mask);

    // output projection
    gemm_mma<<<dim3(8, 64), 256, gemm_smem>>>(bq, bk, bv, bo, out, 1);
}

// round 13
// speedup vs baseline: 3.5663x; 1.0373x over previous
#include <cuda_runtime.h>
#include <cuda_bf16.h>
#include <math.h>
#include <stdint.h>

#define NB     4
#define SEQ    2048
#define DMODEL 1024
#define NHEADS 16
#define DH     64
#define MROWS  8192
#define NEGINF -1e30f

// ---------------------------------------------------------------------------
// Static scratch (all projection outputs live as pre-split bf16 hi/lo)
// ---------------------------------------------------------------------------
__device__ __nv_bfloat16 g_xh[MROWS*DMODEL];     // activation hi (also attn out)
__device__ __nv_bfloat16 g_xl[MROWS*DMODEL];     // activation lo
__device__ __nv_bfloat16 g_wth4[4*DMODEL*DMODEL]; // weight^T hi [4][N][K]
__device__ __nv_bfloat16 g_wtl4[4*DMODEL*DMODEL]; // weight^T lo [4][N][K]
__device__ __nv_bfloat16 g_qh[MROWS*DMODEL];     // Q hi (1/8 scale folded)
__device__ __nv_bfloat16 g_ql[MROWS*DMODEL];
__device__ __nv_bfloat16 g_kh[MROWS*DMODEL];
__device__ __nv_bfloat16 g_kl[MROWS*DMODEL];
__device__ __nv_bfloat16 g_vh[MROWS*DMODEL];
__device__ __nv_bfloat16 g_vl[MROWS*DMODEL];

// ---------------------------------------------------------------------------
// PTX helpers (sm_100 base target)
// ---------------------------------------------------------------------------
__device__ __forceinline__ uint32_t smem_u32(const void* p) {
    uint32_t a;
    asm("{ .reg .u64 t; cvta.to.shared.u64 t, %1; cvt.u32.u64 %0, t; }" : "=r"(a) : "l"(p));
    return a;
}
#define CP_ASYNC16(saddr, gptr) \
    asm volatile("cp.async.cg.shared.global [%0], [%1], 16;" :: "r"(saddr), "l"(gptr))
#define CP_COMMIT() asm volatile("cp.async.commit_group;" ::: "memory")
#define CP_WAIT1()  asm volatile("cp.async.wait_group 1;" ::: "memory")
#define CP_WAIT0()  asm volatile("cp.async.wait_group 0;" ::: "memory")

#define LDSM_X4(r0, r1, r2, r3, addr) \
    asm volatile("ldmatrix.sync.aligned.m8n8.x4.shared.b16 {%0,%1,%2,%3}, [%4];" \
        : "=r"(r0), "=r"(r1), "=r"(r2), "=r"(r3) : "r"(addr))
#define LDSM_X4T(r0, r1, r2, r3, addr) \
    asm volatile("ldmatrix.sync.aligned.m8n8.x4.trans.shared.b16 {%0,%1,%2,%3}, [%4];" \
        : "=r"(r0), "=r"(r1), "=r"(r2), "=r"(r3) : "r"(addr))

__device__ __forceinline__ void mma_bf16(float* c, const uint32_t* a,
                                         uint32_t b0, uint32_t b1) {
    asm volatile(
        "mma.sync.aligned.m16n8k16.row.col.f32.bf16.bf16.f32 "
        "{%0,%1,%2,%3}, {%4,%5,%6,%7}, {%8,%9}, {%0,%1,%2,%3};"
        : "+f"(c[0]), "+f"(c[1]), "+f"(c[2]), "+f"(c[3])
        : "r"(a[0]), "r"(a[1]), "r"(a[2]), "r"(a[3]), "r"(b0), "r"(b1));
}

__device__ __forceinline__ __nv_bfloat162 hi2(float a, float b) {
    return __halves2bfloat162(__float2bfloat16(a), __float2bfloat16(b));
}
__device__ __forceinline__ __nv_bfloat162 lo2(float a, float b) {
    __nv_bfloat16 ha = __float2bfloat16(a), hb = __float2bfloat16(b);
    return __halves2bfloat162(__float2bfloat16(a - __bfloat162float(ha)),
                              __float2bfloat16(b - __bfloat162float(hb)));
}
__device__ __forceinline__ uint32_t hi2u(float a, float b) {
    __nv_bfloat162 v = hi2(a, b);
    return *(uint32_t*)&v;
}
__device__ __forceinline__ uint32_t lo2u(float a, float b) {
    __nv_bfloat162 v = lo2(a, b);
    return *(uint32_t*)&v;
}

// ---------------------------------------------------------------------------
// fp32 -> bf16 hi/lo split of x
// ---------------------------------------------------------------------------
__global__ __launch_bounds__(256) void split_bf16(const float* __restrict__ src) {
    size_t i4 = ((size_t)blockIdx.x * 256 + threadIdx.x) * 4;
    if (i4 >= (size_t)MROWS * DMODEL) return;
    float4 v = *(const float4*)(src + i4);
    float a[4] = {v.x, v.y, v.z, v.w};
#pragma unroll
    for (int j = 0; j < 4; j++) {
        __nv_bfloat16 hi = __float2bfloat16(a[j]);
        __nv_bfloat16 lo = __float2bfloat16(a[j] - __bfloat162float(hi));
        g_xh[i4 + j] = hi;
        g_xl[i4 + j] = lo;
    }
}

// ---------------------------------------------------------------------------
// All-four weight transpose + split
// ---------------------------------------------------------------------------
__global__ __launch_bounds__(256) void transpose_split4(
    const float* __restrict__ wq, const float* __restrict__ wk,
    const float* __restrict__ wv, const float* __restrict__ wo) {
    __shared__ float t[32][33];
    const int tx = threadIdx.x, ty = threadIdx.y;    // 32 x 8
    const int n0 = blockIdx.x * 32, k0 = blockIdx.y * 32;
    const int z = blockIdx.z;
    const float* w = (z == 0) ? wq : (z == 1) ? wk : (z == 2) ? wv : wo;
    __nv_bfloat16* H = g_wth4 + (size_t)z * DMODEL * DMODEL;
    __nv_bfloat16* L = g_wtl4 + (size_t)z * DMODEL * DMODEL;
#pragma unroll
    for (int i = 0; i < 4; i++)
        t[ty + i * 8][tx] = w[(size_t)(k0 + ty + i * 8) * DMODEL + n0 + tx];
    __syncthreads();
#pragma unroll
    for (int i = 0; i < 4; i++) {
        float v = t[tx][ty + i * 8];
        __nv_bfloat16 hi = __float2bfloat16(v);
        __nv_bfloat16 lo = __float2bfloat16(v - __bfloat162float(hi));
        size_t o = (size_t)(n0 + ty + i * 8) * DMODEL + (k0 + tx);
        H[o] = hi;
        L[o] = lo;
    }
}

// ---------------------------------------------------------------------------
// mma.sync bf16-split GEMM (unchanged from R12)
// ---------------------------------------------------------------------------
#define MAT_BYTES   10240
#define STG_BYTES   40960
#define ROW_B       80
#define NCHUNK      32

__global__ __launch_bounds__(256, 2) void gemm_mma(
    const float* __restrict__ biasQ, const float* __restrict__ biasK,
    const float* __restrict__ biasV, const float* __restrict__ biasO,
    float* __restrict__ Cext, int mode) {
    extern __shared__ char smem[];
    const uint32_t sb = smem_u32(smem);
    const int tid  = threadIdx.x;
    const int wid  = tid >> 5;
    const int lane = tid & 31;
    const int wm = wid & 3;
    const int wn = wid >> 2;
    const int wsel    = (mode == 0) ? (blockIdx.x >> 3) : 3;
    const int dst_sel = (mode == 0) ? wsel : 3;
    const float* bias = (mode == 1) ? biasO
                      : (wsel == 0) ? biasQ : (wsel == 1) ? biasK : biasV;
    const int bn = (mode == 0 ? (blockIdx.x & 7) : blockIdx.x) * 128;
    const int bm = blockIdx.y * 128;
    const __nv_bfloat16* WH = g_wth4 + (size_t)wsel * DMODEL * DMODEL;
    const __nv_bfloat16* WL = g_wtl4 + (size_t)wsel * DMODEL * DMODEL;

    float c[2][8][4];
#pragma unroll
    for (int mt = 0; mt < 2; mt++)
#pragma unroll
        for (int nt = 0; nt < 8; nt++)
#pragma unroll
            for (int r = 0; r < 4; r++) c[mt][nt][r] = 0.f;

    auto issue = [&](int chunk, int stage) {
        const int k0 = chunk * 32;
        const uint32_t stg = sb + stage * STG_BYTES;
#pragma unroll
        for (int i = 0; i < 8; i++) {
            const int idx = i * 256 + tid;
            const int mat = idx >> 9;
            const int row = (idx >> 2) & 127;
            const int seg = idx & 3;
            const uint32_t sa = stg + mat * MAT_BYTES + row * ROW_B + seg * 16;
            const __nv_bfloat16* gp;
            if (mat == 0)      gp = g_xh + (size_t)(bm + row) * DMODEL + k0 + seg * 8;
            else if (mat == 1) gp = g_xl + (size_t)(bm + row) * DMODEL + k0 + seg * 8;
            else if (mat == 2) gp = WH   + (size_t)(bn + row) * DMODEL + k0 + seg * 8;
            else               gp = WL   + (size_t)(bn + row) * DMODEL + k0 + seg * 8;
            CP_ASYNC16(sa, gp);
        }
        CP_COMMIT();
    };

    issue(0, 0);

    const int lr  = lane & 7;
    const int lh8 = (lane >> 3) & 1;
    const int lh16 = lane >> 4;

    for (int chunk = 0; chunk < NCHUNK; chunk++) {
        if (chunk + 1 < NCHUNK) issue(chunk + 1, (chunk + 1) & 1);
        if (chunk + 1 < NCHUNK) { CP_WAIT1(); } else { CP_WAIT0(); }
        __syncthreads();

        const uint32_t stg = sb + (chunk & 1) * STG_BYTES;
        const uint32_t Ah = stg;
        const uint32_t Al = stg + MAT_BYTES;
        const uint32_t Bh = stg + 2 * MAT_BYTES;
        const uint32_t Bl = stg + 3 * MAT_BYTES;

#pragma unroll
        for (int ks = 0; ks < 2; ks++) {
            const int kb = ks * 32;
            uint32_t ah[2][4], al[2][4];
#pragma unroll
            for (int mt = 0; mt < 2; mt++) {
                const uint32_t ra = (uint32_t)(wm * 32 + mt * 16 + lr + 8 * lh8) * ROW_B
                                  + kb + 16 * lh16;
                LDSM_X4(ah[mt][0], ah[mt][1], ah[mt][2], ah[mt][3], Ah + ra);
                LDSM_X4(al[mt][0], al[mt][1], al[mt][2], al[mt][3], Al + ra);
            }
            uint32_t bh[4][4];
#pragma unroll
            for (int np = 0; np < 4; np++) {
                const uint32_t rb = (uint32_t)(wn * 64 + np * 16 + lr + 8 * lh16) * ROW_B
                                  + kb + 16 * lh8;
                LDSM_X4(bh[np][0], bh[np][1], bh[np][2], bh[np][3], Bh + rb);
            }
#pragma unroll
            for (int np = 0; np < 4; np++)
#pragma unroll
                for (int mt = 0; mt < 2; mt++) {
                    mma_bf16(c[mt][np * 2 + 0], ah[mt], bh[np][0], bh[np][1]);
                    mma_bf16(c[mt][np * 2 + 1], ah[mt], bh[np][2], bh[np][3]);
                }
#pragma unroll
            for (int np = 0; np < 4; np++)
#pragma unroll
                for (int mt = 0; mt < 2; mt++) {
                    mma_bf16(c[mt][np * 2 + 0], al[mt], bh[np][0], bh[np][1]);
                    mma_bf16(c[mt][np * 2 + 1], al[mt], bh[np][2], bh[np][3]);
                }
#pragma unroll
            for (int nh = 0; nh < 2; nh++) {
                uint32_t bl[2][4];
#pragma unroll
                for (int j = 0; j < 2; j++) {
                    const int np = nh * 2 + j;
                    const uint32_t rb = (uint32_t)(wn * 64 + np * 16 + lr + 8 * lh16) * ROW_B
                                      + kb + 16 * lh8;
                    LDSM_X4(bl[j][0], bl[j][1], bl[j][2], bl[j][3], Bl + rb);
                }
#pragma unroll
                for (int j = 0; j < 2; j++) {
                    const int np = nh * 2 + j;
#pragma unroll
                    for (int mt = 0; mt < 2; mt++) {
                        mma_bf16(c[mt][np * 2 + 0], ah[mt], bl[j][0], bl[j][1]);
                        mma_bf16(c[mt][np * 2 + 1], ah[mt], bl[j][2], bl[j][3]);
                    }
                }
            }
        }
        __syncthreads();
    }

    const int rg = lane >> 2;
    const int cg = (lane & 3) * 2;
    if (dst_sel == 3) {
#pragma unroll
        for (int mt = 0; mt < 2; mt++)
#pragma unroll
            for (int nt = 0; nt < 8; nt++) {
                const int row = bm + wm * 32 + mt * 16 + rg;
                const int col = bn + wn * 64 + nt * 8 + cg;
                const float b0 = bias[col], b1 = bias[col + 1];
                *(float2*)&Cext[(size_t)row * DMODEL + col] =
                    make_float2(c[mt][nt][0] + b0, c[mt][nt][1] + b1);
                *(float2*)&Cext[(size_t)(row + 8) * DMODEL + col] =
                    make_float2(c[mt][nt][2] + b0, c[mt][nt][3] + b1);
            }
    } else {
        __nv_bfloat16* H = (dst_sel == 0) ? g_qh : (dst_sel == 1) ? g_kh : g_vh;
        __nv_bfloat16* L = (dst_sel == 0) ? g_ql : (dst_sel == 1) ? g_kl : g_vl;
        const float scl = (dst_sel == 0) ? 0.125f : 1.f;
#pragma unroll
        for (int mt = 0; mt < 2; mt++)
#pragma unroll
            for (int nt = 0; nt < 8; nt++) {
                const int row = bm + wm * 32 + mt * 16 + rg;
                const int col = bn + wn * 64 + nt * 8 + cg;
                const float b0 = bias[col], b1 = bias[col + 1];
                float v0 = (c[mt][nt][0] + b0) * scl, v1 = (c[mt][nt][1] + b1) * scl;
                float v2 = (c[mt][nt][2] + b0) * scl, v3 = (c[mt][nt][3] + b1) * scl;
                size_t o0 = (size_t)row * DMODEL + col;
                size_t o1 = (size_t)(row + 8) * DMODEL + col;
                *(__nv_bfloat162*)&H[o0] = hi2(v0, v1);
                *(__nv_bfloat162*)&L[o0] = lo2(v0, v1);
                *(__nv_bfloat162*)&H[o1] = hi2(v2, v3);
                *(__nv_bfloat162*)&L[o1] = lo2(v2, v3);
            }
    }
}

// ---------------------------------------------------------------------------
// Tensor-core flash attention, register-resident P: the S accumulator
// layout IS the A-fragment layout of the PV mma (row.col), so P never
// touches smem -- no P stores, no P ldmatrix, 36.9KB less smem.
// ILP-scheduled MMA batches (all Bh frags resident) as in gemm_mma.
// ---------------------------------------------------------------------------
#define AROW    144
#define OFF_QH  0
#define OFF_QL  (128*AROW)
#define OFF_KH  (2*128*AROW)
#define OFF_MSK (OFF_KH + 4*64*AROW)
#define ATT_SMEM (OFF_MSK + 512)          // 2 x 256B mask buffers

__global__ __launch_bounds__(256, 2) void attn_mma(const int* __restrict__ mask)
{
    extern __shared__ char sm[];
    const uint32_t sb = smem_u32(sm);
    const int tid  = threadIdx.x;
    const int wid  = tid >> 5;
    const int lane = tid & 31;
    const int lr   = lane & 7;
    const int lh8  = (lane >> 3) & 1;
    const int lh16 = lane >> 4;
    const int g    = lane >> 2;
    const int t2   = (lane & 3) * 2;
    const int wm16 = wid * 16;

    const int nh = blockIdx.y;
    const int nb = nh >> 4;
    const int qt = blockIdx.x;
    const size_t hb = (size_t)nh * SEQ * DH;
    const size_t qoff = hb + (size_t)qt * 128 * DH;
    const int* mk = mask + nb * SEQ;

    auto issueK = [&](int kb) {
#pragma unroll
        for (int i = 0; i < 4; i++) {
            const int idx = i * 256 + tid;
            const int mat = idx >> 9;
            const int r = (idx >> 3) & 63;
            const int s = idx & 7;
            const __nv_bfloat16* gb = mat ? g_kl : g_kh;
            CP_ASYNC16(sb + OFF_KH + mat * 64 * AROW + r * AROW + s * 16,
                       gb + hb + (size_t)(kb * 64 + r) * DH + s * 8);
        }
    };
    auto issueV = [&](int kb) {
#pragma unroll
        for (int i = 0; i < 4; i++) {
            const int idx = i * 256 + tid;
            const int mat = idx >> 9;
            const int r = (idx >> 3) & 63;
            const int s = idx & 7;
            const __nv_bfloat16* gb = mat ? g_vl : g_vh;
            CP_ASYNC16(sb + OFF_KH + (2 + mat) * 64 * AROW + r * AROW + s * 16,
                       gb + hb + (size_t)(kb * 64 + r) * DH + s * 8);
        }
    };

    // ---- pre-loop: Q tile + K_0 + mask_0 ----
#pragma unroll
    for (int i = 0; i < 8; i++) {
        const int idx = i * 256 + tid;
        const int mat = idx >> 10;
        const int r = (idx >> 3) & 127;
        const int s = idx & 7;
        const __nv_bfloat16* gp = (mat ? g_ql : g_qh) + qoff + r * DH + s * 8;
        CP_ASYNC16(sb + (mat ? OFF_QL : OFF_QH) + r * AROW + s * 16, gp);
    }
    CP_COMMIT();
    if (tid < 64) *(int*)(sm + OFF_MSK + tid * 4) = mk[tid];
    issueK(0);
    CP_COMMIT();

    float m0 = -INFINITY, m1 = -INFINITY, l0 = 0.f, l1 = 0.f;
    float co[8][4];
#pragma unroll
    for (int nt = 0; nt < 8; nt++)
#pragma unroll
        for (int r = 0; r < 4; r++) co[nt][r] = 0.f;

    for (int kb = 0; kb < SEQ / 64; kb++) {
        CP_WAIT0();
        __syncthreads();

        issueV(kb);
        CP_COMMIT();

        // ---- S = Q K^T (ILP batches over resident Kh fragments) ----
        float cs[8][4];
#pragma unroll
        for (int nt = 0; nt < 8; nt++)
#pragma unroll
            for (int r = 0; r < 4; r++) cs[nt][r] = 0.f;

#pragma unroll
        for (int ks = 0; ks < 4; ks++) {
            const int kk2 = ks * 32;
            const uint32_t ra = (uint32_t)(wm16 + lr + 8 * lh8) * AROW + kk2 + 16 * lh16;
            uint32_t ah[4], al[4];
            LDSM_X4(ah[0], ah[1], ah[2], ah[3], sb + OFF_QH + ra);
            LDSM_X4(al[0], al[1], al[2], al[3], sb + OFF_QL + ra);
            uint32_t bh[4][4];
#pragma unroll
            for (int np = 0; np < 4; np++) {
                const uint32_t rb = (uint32_t)(np * 16 + lr + 8 * lh16) * AROW + kk2 + 16 * lh8;
                LDSM_X4(bh[np][0], bh[np][1], bh[np][2], bh[np][3], sb + OFF_KH + rb);
            }
#pragma unroll
            for (int np = 0; np < 4; np++) {
                mma_bf16(cs[np * 2 + 0], ah, bh[np][0], bh[np][1]);
                mma_bf16(cs[np * 2 + 1], ah, bh[np][2], bh[np][3]);
            }
#pragma unroll
            for (int np = 0; np < 4; np++) {
                mma_bf16(cs[np * 2 + 0], al, bh[np][0], bh[np][1]);
                mma_bf16(cs[np * 2 + 1], al, bh[np][2], bh[np][3]);
            }
#pragma unroll
            for (int nhh = 0; nhh < 2; nhh++) {
                uint32_t bl[2][4];
#pragma unroll
                for (int j = 0; j < 2; j++) {
                    const int np = nhh * 2 + j;
                    const uint32_t rb = (uint32_t)(np * 16 + lr + 8 * lh16) * AROW + kk2 + 16 * lh8;
                    LDSM_X4(bl[j][0], bl[j][1], bl[j][2], bl[j][3],
                            sb + OFF_KH + 64 * AROW + rb);
                }
#pragma unroll
                for (int j = 0; j < 2; j++) {
                    const int np = nhh * 2 + j;
                    mma_bf16(cs[np * 2 + 0], ah, bl[j][0], bl[j][1]);
                    mma_bf16(cs[np * 2 + 1], ah, bl[j][2], bl[j][3]);
                }
            }
        }

        // ---- mask ----
        const uint32_t mbase = OFF_MSK + (kb & 1) * 256;
#pragma unroll
        for (int nt = 0; nt < 8; nt++) {
            int2 mv = *(const int2*)(sm + mbase + (nt * 8 + t2) * 4);
            if (!mv.x) { cs[nt][0] = NEGINF; cs[nt][2] = NEGINF; }
            if (!mv.y) { cs[nt][1] = NEGINF; cs[nt][3] = NEGINF; }
        }

        // ---- online softmax; exp in place (cs becomes P, fp32) ----
        float mx0 = NEGINF, mx1 = NEGINF;
#pragma unroll
        for (int nt = 0; nt < 8; nt++) {
            mx0 = fmaxf(mx0, fmaxf(cs[nt][0], cs[nt][1]));
            mx1 = fmaxf(mx1, fmaxf(cs[nt][2], cs[nt][3]));
        }
        mx0 = fmaxf(mx0, __shfl_xor_sync(0xffffffffu, mx0, 1));
        mx0 = fmaxf(mx0, __shfl_xor_sync(0xffffffffu, mx0, 2));
        mx1 = fmaxf(mx1, __shfl_xor_sync(0xffffffffu, mx1, 1));
        mx1 = fmaxf(mx1, __shfl_xor_sync(0xffffffffu, mx1, 2));
        const float mn0 = fmaxf(m0, mx0), mn1 = fmaxf(m1, mx1);
        const float corr0 = __expf(m0 - mn0), corr1 = __expf(m1 - mn1);
        float s0 = 0.f, s1 = 0.f;
#pragma unroll
        for (int nt = 0; nt < 8; nt++) {
            cs[nt][0] = __expf(cs[nt][0] - mn0);
            cs[nt][1] = __expf(cs[nt][1] - mn0);
            cs[nt][2] = __expf(cs[nt][2] - mn1);
            cs[nt][3] = __expf(cs[nt][3] - mn1);
            s0 += cs[nt][0] + cs[nt][1];
            s1 += cs[nt][2] + cs[nt][3];
        }
        s0 += __shfl_xor_sync(0xffffffffu, s0, 1);
        s0 += __shfl_xor_sync(0xffffffffu, s0, 2);
        s1 += __shfl_xor_sync(0xffffffffu, s1, 1);
        s1 += __shfl_xor_sync(0xffffffffu, s1, 2);
        l0 = l0 * corr0 + s0; m0 = mn0;
        l1 = l1 * corr1 + s1; m1 = mn1;
#pragma unroll
        for (int nt = 0; nt < 8; nt++) {
            co[nt][0] *= corr0; co[nt][1] *= corr0;
            co[nt][2] *= corr1; co[nt][3] *= corr1;
        }

        CP_WAIT0();
        __syncthreads();

        if (kb + 1 < SEQ / 64) {
            issueK(kb + 1);
            if (tid < 64)
                *(int*)(sm + OFF_MSK + ((kb + 1) & 1) * 256 + tid * 4) = mk[(kb + 1) * 64 + tid];
            CP_COMMIT();
        }

        // ---- O += P V, P fragments built from registers (no smem) ----
#pragma unroll
        for (int kf = 0; kf < 4; kf++) {
            // A-fragment of P for keys kf*16..+15 (accumulator layout == A layout)
            uint32_t ph[4], pl[4];
            ph[0] = hi2u(cs[2 * kf][0],     cs[2 * kf][1]);
            ph[1] = hi2u(cs[2 * kf][2],     cs[2 * kf][3]);
            ph[2] = hi2u(cs[2 * kf + 1][0], cs[2 * kf + 1][1]);
            ph[3] = hi2u(cs[2 * kf + 1][2], cs[2 * kf + 1][3]);
            pl[0] = lo2u(cs[2 * kf][0],     cs[2 * kf][1]);
            pl[1] = lo2u(cs[2 * kf][2],     cs[2 * kf][3]);
            pl[2] = lo2u(cs[2 * kf + 1][0], cs[2 * kf + 1][1]);
            pl[3] = lo2u(cs[2 * kf + 1][2], cs[2 * kf + 1][3]);

            uint32_t vh[4][4];
#pragma unroll
            for (int np = 0; np < 4; np++) {
                const uint32_t rv = (uint32_t)(kf * 16 + lr + 8 * lh8) * AROW
                                  + np * 32 + 16 * lh16;
                LDSM_X4T(vh[np][0], vh[np][1], vh[np][2], vh[np][3],
                         sb + OFF_KH + 2 * 64 * AROW + rv);
            }
#pragma unroll
            for (int np = 0; np < 4; np++) {
                mma_bf16(co[np * 2 + 0], ph, vh[np][0], vh[np][1]);
                mma_bf16(co[np * 2 + 1], ph, vh[np][2], vh[np][3]);
            }
#pragma unroll
            for (int np = 0; np < 4; np++) {
                mma_bf16(co[np * 2 + 0], pl, vh[np][0], vh[np][1]);
                mma_bf16(co[np * 2 + 1], pl, vh[np][2], vh[np][3]);
            }
#pragma unroll
            for (int nhh = 0; nhh < 2; nhh++) {
                uint32_t vl[2][4];
#pragma unroll
                for (int j = 0; j < 2; j++) {
                    const int np = nhh * 2 + j;
                    const uint32_t rv = (uint32_t)(kf * 16 + lr + 8 * lh8) * AROW
                                      + np * 32 + 16 * lh16;
                    LDSM_X4T(vl[j][0], vl[j][1], vl[j][2], vl[j][3],
                             sb + OFF_KH + 3 * 64 * AROW + rv);
                }
#pragma unroll
                for (int j = 0; j < 2; j++) {
                    const int np = nhh * 2 + j;
                    mma_bf16(co[np * 2 + 0], ph, vl[j][0], vl[j][1]);
                    mma_bf16(co[np * 2 + 1], ph, vl[j][2], vl[j][3]);
                }
            }
        }
    }

    // ---- epilogue: normalize, split, write hi/lo to g_xh/g_xl ----
    const float i0 = 1.f / l0, i1 = 1.f / l1;
    const int r0 = wm16 + g, r1 = wm16 + g + 8;
#pragma unroll
    for (int nt = 0; nt < 8; nt++) {
        const int col = nt * 8 + t2;
        float v0 = co[nt][0] * i0, v1 = co[nt][1] * i0;
        float v2 = co[nt][2] * i1, v3 = co[nt][3] * i1;
        size_t o0 = qoff + (size_t)r0 * DH + col;
        size_t o1 = qoff + (size_t)r1 * DH + col;
        *(__nv_bfloat162*)&g_xh[o0] = hi2(v0, v1);
        *(__nv_bfloat162*)&g_xl[o0] = lo2(v0, v1);
        *(__nv_bfloat162*)&g_xh[o1] = hi2(v2, v3);
        *(__nv_bfloat162*)&g_xl[o1] = lo2(v2, v3);
    }
}

// ---------------------------------------------------------------------------
extern "C" void kernel_launch(void* const* d_in, const int* in_sizes, int n_in,
                              void* d_out, int out_size)
{
    const float* x   = (const float*)d_in[0];
    const int*  mask = (const int*)  d_in[1];
    const float* wq  = (const float*)d_in[2];
    const float* bq  = (const float*)d_in[3];
    const float* wk  = (const float*)d_in[4];
    const float* bk  = (const float*)d_in[5];
    const float* wv  = (const float*)d_in[6];
    const float* bv  = (const float*)d_in[7];
    const float* wo  = (const float*)d_in[8];
    const float* bo  = (const float*)d_in[9];
    float* out = (float*)d_out;

    const int gemm_smem = 2 * STG_BYTES;            // 81920 B
    cudaFuncSetAttribute(gemm_mma, cudaFuncAttributeMaxDynamicSharedMemorySize, gemm_smem);
    cudaFuncSetAttribute(attn_mma, cudaFuncAttributeMaxDynamicSharedMemorySize, ATT_SMEM);

    const int nsplit = (MROWS * DMODEL / 4 + 255) / 256;

    split_bf16<<<nsplit, 256>>>(x);
    transpose_split4<<<dim3(32, 32, 4), dim3(32, 8)>>>(wq, wk, wv, wo);

    // merged QKV projection
    gemm_mma<<<dim3(24, 64), 256, gemm_smem>>>(bq, bk, bv, bo, out, 0);

    attn_mma<<<dim3(SEQ / 128, NB * NHEADS), 256, ATT_SMEM>>>(mask);

    // output projection
    gemm_mma<<<dim3(8, 64), 256, gemm_smem>>>(bq, bk, bv, bo, out, 1);
}

// round 15
// speedup vs baseline: 3.6150x; 1.0137x over previous
#include <cuda_runtime.h>
#include <cuda_bf16.h>
#include <math.h>
#include <stdint.h>

#define NB     4
#define SEQ    2048
#define DMODEL 1024
#define NHEADS 16
#define DH     64
#define MROWS  8192
#define NEGINF -1e30f
#define LOG2E  1.4426950408889634f

// ---------------------------------------------------------------------------
// Static scratch (all projection outputs live as pre-split bf16 hi/lo)
// ---------------------------------------------------------------------------
__device__ __nv_bfloat16 g_xh[MROWS*DMODEL];     // activation hi (also attn out)
__device__ __nv_bfloat16 g_xl[MROWS*DMODEL];     // activation lo
__device__ __nv_bfloat16 g_wth4[4*DMODEL*DMODEL]; // weight^T hi [4][N][K]
__device__ __nv_bfloat16 g_wtl4[4*DMODEL*DMODEL]; // weight^T lo [4][N][K]
__device__ __nv_bfloat16 g_qh[MROWS*DMODEL];     // Q hi (0.125*log2e folded)
__device__ __nv_bfloat16 g_ql[MROWS*DMODEL];
__device__ __nv_bfloat16 g_kh[MROWS*DMODEL];
__device__ __nv_bfloat16 g_kl[MROWS*DMODEL];
__device__ __nv_bfloat16 g_vh[MROWS*DMODEL];
__device__ __nv_bfloat16 g_vl[MROWS*DMODEL];

// ---------------------------------------------------------------------------
// PTX helpers (sm_100 base target)
// ---------------------------------------------------------------------------
__device__ __forceinline__ uint32_t smem_u32(const void* p) {
    uint32_t a;
    asm("{ .reg .u64 t; cvta.to.shared.u64 t, %1; cvt.u32.u64 %0, t; }" : "=r"(a) : "l"(p));
    return a;
}
#define CP_ASYNC16(saddr, gptr) \
    asm volatile("cp.async.cg.shared.global [%0], [%1], 16;" :: "r"(saddr), "l"(gptr))
#define CP_COMMIT() asm volatile("cp.async.commit_group;" ::: "memory")
#define CP_WAIT1()  asm volatile("cp.async.wait_group 1;" ::: "memory")
#define CP_WAIT0()  asm volatile("cp.async.wait_group 0;" ::: "memory")

#define LDSM_X4(r0, r1, r2, r3, addr) \
    asm volatile("ldmatrix.sync.aligned.m8n8.x4.shared.b16 {%0,%1,%2,%3}, [%4];" \
        : "=r"(r0), "=r"(r1), "=r"(r2), "=r"(r3) : "r"(addr))
#define LDSM_X4T(r0, r1, r2, r3, addr) \
    asm volatile("ldmatrix.sync.aligned.m8n8.x4.trans.shared.b16 {%0,%1,%2,%3}, [%4];" \
        : "=r"(r0), "=r"(r1), "=r"(r2), "=r"(r3) : "r"(addr))

__device__ __forceinline__ void mma_bf16(float* c, const uint32_t* a,
                                         uint32_t b0, uint32_t b1) {
    asm volatile(
        "mma.sync.aligned.m16n8k16.row.col.f32.bf16.bf16.f32 "
        "{%0,%1,%2,%3}, {%4,%5,%6,%7}, {%8,%9}, {%0,%1,%2,%3};"
        : "+f"(c[0]), "+f"(c[1]), "+f"(c[2]), "+f"(c[3])
        : "r"(a[0]), "r"(a[1]), "r"(a[2]), "r"(a[3]), "r"(b0), "r"(b1));
}

__device__ __forceinline__ __nv_bfloat162 hi2(float a, float b) {
    return __halves2bfloat162(__float2bfloat16(a), __float2bfloat16(b));
}
__device__ __forceinline__ __nv_bfloat162 lo2(float a, float b) {
    __nv_bfloat16 ha = __float2bfloat16(a), hb = __float2bfloat16(b);
    return __halves2bfloat162(__float2bfloat16(a - __bfloat162float(ha)),
                              __float2bfloat16(b - __bfloat162float(hb)));
}

// Truncation split helpers (hot path): hi = bits&0xFFFF0000 (exact, Sterbenz
// makes lo = f - hi exact in fp32). One PRMT packs two hi's.
__device__ __forceinline__ uint32_t hitrunc2(float a, float b) {
    uint32_t r;
    asm("prmt.b32 %0, %1, %2, 0x7632;"
        : "=r"(r) : "r"(__float_as_uint(a)), "r"(__float_as_uint(b)));
    return r;
}
__device__ __forceinline__ float ftrunc(float a) {
    return __uint_as_float(__float_as_uint(a) & 0xFFFF0000u);
}
__device__ __forceinline__ uint32_t pack2(float a, float b) {  // {lo=a, hi=b}
    uint32_t r;
    asm("cvt.rn.bf16x2.f32 %0, %1, %2;" : "=r"(r) : "f"(b), "f"(a));
    return r;
}

// ---------------------------------------------------------------------------
// fp32 -> bf16 hi/lo split of x
// ---------------------------------------------------------------------------
__global__ __launch_bounds__(256) void split_bf16(const float* __restrict__ src) {
    size_t i4 = ((size_t)blockIdx.x * 256 + threadIdx.x) * 4;
    if (i4 >= (size_t)MROWS * DMODEL) return;
    float4 v = *(const float4*)(src + i4);
    float a[4] = {v.x, v.y, v.z, v.w};
#pragma unroll
    for (int j = 0; j < 4; j++) {
        __nv_bfloat16 hi = __float2bfloat16(a[j]);
        __nv_bfloat16 lo = __float2bfloat16(a[j] - __bfloat162float(hi));
        g_xh[i4 + j] = hi;
        g_xl[i4 + j] = lo;
    }
}

// ---------------------------------------------------------------------------
// All-four weight transpose + split
// ---------------------------------------------------------------------------
__global__ __launch_bounds__(256) void transpose_split4(
    const float* __restrict__ wq, const float* __restrict__ wk,
    const float* __restrict__ wv, const float* __restrict__ wo) {
    __shared__ float t[32][33];
    const int tx = threadIdx.x, ty = threadIdx.y;    // 32 x 8
    const int n0 = blockIdx.x * 32, k0 = blockIdx.y * 32;
    const int z = blockIdx.z;
    const float* w = (z == 0) ? wq : (z == 1) ? wk : (z == 2) ? wv : wo;
    __nv_bfloat16* H = g_wth4 + (size_t)z * DMODEL * DMODEL;
    __nv_bfloat16* L = g_wtl4 + (size_t)z * DMODEL * DMODEL;
#pragma unroll
    for (int i = 0; i < 4; i++)
        t[ty + i * 8][tx] = w[(size_t)(k0 + ty + i * 8) * DMODEL + n0 + tx];
    __syncthreads();
#pragma unroll
    for (int i = 0; i < 4; i++) {
        float v = t[tx][ty + i * 8];
        __nv_bfloat16 hi = __float2bfloat16(v);
        __nv_bfloat16 lo = __float2bfloat16(v - __bfloat162float(hi));
        size_t o = (size_t)(n0 + ty + i * 8) * DMODEL + (k0 + tx);
        H[o] = hi;
        L[o] = lo;
    }
}

// ---------------------------------------------------------------------------
// mma.sync bf16-split GEMM (R12 ILP schedule; Q scale now 0.125*log2e so
// attention softmax runs in exp2 domain)
// ---------------------------------------------------------------------------
#define MAT_BYTES   10240
#define STG_BYTES   40960
#define ROW_B       80
#define NCHUNK      32

__global__ __launch_bounds__(256, 2) void gemm_mma(
    const float* __restrict__ biasQ, const float* __restrict__ biasK,
    const float* __restrict__ biasV, const float* __restrict__ biasO,
    float* __restrict__ Cext, int mode) {
    extern __shared__ char smem[];
    const uint32_t sb = smem_u32(smem);
    const int tid  = threadIdx.x;
    const int wid  = tid >> 5;
    const int lane = tid & 31;
    const int wm = wid & 3;
    const int wn = wid >> 2;
    const int wsel    = (mode == 0) ? (blockIdx.x >> 3) : 3;
    const int dst_sel = (mode == 0) ? wsel : 3;
    const float* bias = (mode == 1) ? biasO
                      : (wsel == 0) ? biasQ : (wsel == 1) ? biasK : biasV;
    const int bn = (mode == 0 ? (blockIdx.x & 7) : blockIdx.x) * 128;
    const int bm = blockIdx.y * 128;
    const __nv_bfloat16* WH = g_wth4 + (size_t)wsel * DMODEL * DMODEL;
    const __nv_bfloat16* WL = g_wtl4 + (size_t)wsel * DMODEL * DMODEL;

    float c[2][8][4];
#pragma unroll
    for (int mt = 0; mt < 2; mt++)
#pragma unroll
        for (int nt = 0; nt < 8; nt++)
#pragma unroll
            for (int r = 0; r < 4; r++) c[mt][nt][r] = 0.f;

    auto issue = [&](int chunk, int stage) {
        const int k0 = chunk * 32;
        const uint32_t stg = sb + stage * STG_BYTES;
#pragma unroll
        for (int i = 0; i < 8; i++) {
            const int idx = i * 256 + tid;
            const int mat = idx >> 9;
            const int row = (idx >> 2) & 127;
            const int seg = idx & 3;
            const uint32_t sa = stg + mat * MAT_BYTES + row * ROW_B + seg * 16;
            const __nv_bfloat16* gp;
            if (mat == 0)      gp = g_xh + (size_t)(bm + row) * DMODEL + k0 + seg * 8;
            else if (mat == 1) gp = g_xl + (size_t)(bm + row) * DMODEL + k0 + seg * 8;
            else if (mat == 2) gp = WH   + (size_t)(bn + row) * DMODEL + k0 + seg * 8;
            else               gp = WL   + (size_t)(bn + row) * DMODEL + k0 + seg * 8;
            CP_ASYNC16(sa, gp);
        }
        CP_COMMIT();
    };

    issue(0, 0);

    const int lr  = lane & 7;
    const int lh8 = (lane >> 3) & 1;
    const int lh16 = lane >> 4;

    for (int chunk = 0; chunk < NCHUNK; chunk++) {
        if (chunk + 1 < NCHUNK) issue(chunk + 1, (chunk + 1) & 1);
        if (chunk + 1 < NCHUNK) { CP_WAIT1(); } else { CP_WAIT0(); }
        __syncthreads();

        const uint32_t stg = sb + (chunk & 1) * STG_BYTES;
        const uint32_t Ah = stg;
        const uint32_t Al = stg + MAT_BYTES;
        const uint32_t Bh = stg + 2 * MAT_BYTES;
        const uint32_t Bl = stg + 3 * MAT_BYTES;

#pragma unroll
        for (int ks = 0; ks < 2; ks++) {
            const int kb = ks * 32;
            uint32_t ah[2][4], al[2][4];
#pragma unroll
            for (int mt = 0; mt < 2; mt++) {
                const uint32_t ra = (uint32_t)(wm * 32 + mt * 16 + lr + 8 * lh8) * ROW_B
                                  + kb + 16 * lh16;
                LDSM_X4(ah[mt][0], ah[mt][1], ah[mt][2], ah[mt][3], Ah + ra);
                LDSM_X4(al[mt][0], al[mt][1], al[mt][2], al[mt][3], Al + ra);
            }
            uint32_t bh[4][4];
#pragma unroll
            for (int np = 0; np < 4; np++) {
                const uint32_t rb = (uint32_t)(wn * 64 + np * 16 + lr + 8 * lh16) * ROW_B
                                  + kb + 16 * lh8;
                LDSM_X4(bh[np][0], bh[np][1], bh[np][2], bh[np][3], Bh + rb);
            }
#pragma unroll
            for (int np = 0; np < 4; np++)
#pragma unroll
                for (int mt = 0; mt < 2; mt++) {
                    mma_bf16(c[mt][np * 2 + 0], ah[mt], bh[np][0], bh[np][1]);
                    mma_bf16(c[mt][np * 2 + 1], ah[mt], bh[np][2], bh[np][3]);
                }
#pragma unroll
            for (int np = 0; np < 4; np++)
#pragma unroll
                for (int mt = 0; mt < 2; mt++) {
                    mma_bf16(c[mt][np * 2 + 0], al[mt], bh[np][0], bh[np][1]);
                    mma_bf16(c[mt][np * 2 + 1], al[mt], bh[np][2], bh[np][3]);
                }
#pragma unroll
            for (int nh = 0; nh < 2; nh++) {
                uint32_t bl[2][4];
#pragma unroll
                for (int j = 0; j < 2; j++) {
                    const int np = nh * 2 + j;
                    const uint32_t rb = (uint32_t)(wn * 64 + np * 16 + lr + 8 * lh16) * ROW_B
                                      + kb + 16 * lh8;
                    LDSM_X4(bl[j][0], bl[j][1], bl[j][2], bl[j][3], Bl + rb);
                }
#pragma unroll
                for (int j = 0; j < 2; j++) {
                    const int np = nh * 2 + j;
#pragma unroll
                    for (int mt = 0; mt < 2; mt++) {
                        mma_bf16(c[mt][np * 2 + 0], ah[mt], bl[j][0], bl[j][1]);
                        mma_bf16(c[mt][np * 2 + 1], ah[mt], bl[j][2], bl[j][3]);
                    }
                }
            }
        }
        __syncthreads();
    }

    const int rg = lane >> 2;
    const int cg = (lane & 3) * 2;
    if (dst_sel == 3) {
#pragma unroll
        for (int mt = 0; mt < 2; mt++)
#pragma unroll
            for (int nt = 0; nt < 8; nt++) {
                const int row = bm + wm * 32 + mt * 16 + rg;
                const int col = bn + wn * 64 + nt * 8 + cg;
                const float b0 = bias[col], b1 = bias[col + 1];
                *(float2*)&Cext[(size_t)row * DMODEL + col] =
                    make_float2(c[mt][nt][0] + b0, c[mt][nt][1] + b1);
                *(float2*)&Cext[(size_t)(row + 8) * DMODEL + col] =
                    make_float2(c[mt][nt][2] + b0, c[mt][nt][3] + b1);
            }
    } else {
        __nv_bfloat16* H = (dst_sel == 0) ? g_qh : (dst_sel == 1) ? g_kh : g_vh;
        __nv_bfloat16* L = (dst_sel == 0) ? g_ql : (dst_sel == 1) ? g_kl : g_vl;
        const float scl = (dst_sel == 0) ? 0.125f * LOG2E : 1.f;
#pragma unroll
        for (int mt = 0; mt < 2; mt++)
#pragma unroll
            for (int nt = 0; nt < 8; nt++) {
                const int row = bm + wm * 32 + mt * 16 + rg;
                const int col = bn + wn * 64 + nt * 8 + cg;
                const float b0 = bias[col], b1 = bias[col + 1];
                float v0 = (c[mt][nt][0] + b0) * scl, v1 = (c[mt][nt][1] + b1) * scl;
                float v2 = (c[mt][nt][2] + b0) * scl, v3 = (c[mt][nt][3] + b1) * scl;
                size_t o0 = (size_t)row * DMODEL + col;
                size_t o1 = (size_t)(row + 8) * DMODEL + col;
                *(__nv_bfloat162*)&H[o0] = hi2(v0, v1);
                *(__nv_bfloat162*)&L[o0] = lo2(v0, v1);
                *(__nv_bfloat162*)&H[o1] = hi2(v2, v3);
                *(__nv_bfloat162*)&L[o1] = lo2(v2, v3);
            }
    }
}

// ---------------------------------------------------------------------------
// Tensor-core flash attention: register-resident P (truncation split +
// PRMT packing), exp2-domain softmax, mask fast path via ballot flags.
// ---------------------------------------------------------------------------
#define AROW    144
#define OFF_QH  0
#define OFF_QL  (128*AROW)
#define OFF_KH  (2*128*AROW)
#define OFF_MSK (OFF_KH + 4*64*AROW)
#define OFF_FLG (OFF_MSK + 512)           // 2 buffers x 2 warp-flag words
#define ATT_SMEM (OFF_FLG + 16)

__global__ __launch_bounds__(256, 2) void attn_mma(const int* __restrict__ mask)
{
    extern __shared__ char sm[];
    const uint32_t sb = smem_u32(sm);
    const int tid  = threadIdx.x;
    const int wid  = tid >> 5;
    const int lane = tid & 31;
    const int lr   = lane & 7;
    const int lh8  = (lane >> 3) & 1;
    const int lh16 = lane >> 4;
    const int g    = lane >> 2;
    const int t2   = (lane & 3) * 2;
    const int wm16 = wid * 16;

    const int nh = blockIdx.y;
    const int nb = nh >> 4;
    const int qt = blockIdx.x;
    const size_t hb = (size_t)nh * SEQ * DH;
    const size_t qoff = hb + (size_t)qt * 128 * DH;
    const int* mk = mask + nb * SEQ;

    auto issueK = [&](int kb) {
#pragma unroll
        for (int i = 0; i < 4; i++) {
            const int idx = i * 256 + tid;
            const int mat = idx >> 9;
            const int r = (idx >> 3) & 63;
            const int s = idx & 7;
            const __nv_bfloat16* gb = mat ? g_kl : g_kh;
            CP_ASYNC16(sb + OFF_KH + mat * 64 * AROW + r * AROW + s * 16,
                       gb + hb + (size_t)(kb * 64 + r) * DH + s * 8);
        }
    };
    auto issueV = [&](int kb) {
#pragma unroll
        for (int i = 0; i < 4; i++) {
            const int idx = i * 256 + tid;
            const int mat = idx >> 9;
            const int r = (idx >> 3) & 63;
            const int s = idx & 7;
            const __nv_bfloat16* gb = mat ? g_vl : g_vh;
            CP_ASYNC16(sb + OFF_KH + (2 + mat) * 64 * AROW + r * AROW + s * 16,
                       gb + hb + (size_t)(kb * 64 + r) * DH + s * 8);
        }
    };
    // store mask block + per-warp any-zero flags (warps 0,1; single writer per word)
    auto storeMask = [&](int kb, int buf) {
        if (tid < 64) {
            int v = mk[kb * 64 + tid];
            *(int*)(sm + OFF_MSK + buf * 256 + tid * 4) = v;
            uint32_t bal = __ballot_sync(0xffffffffu, v == 0);
            if (lane == 0)
                *(int*)(sm + OFF_FLG + buf * 8 + (tid >> 5) * 4) = (bal != 0);
        }
    };

    // ---- pre-loop: Q tile + K_0 + mask_0 ----
#pragma unroll
    for (int i = 0; i < 8; i++) {
        const int idx = i * 256 + tid;
        const int mat = idx >> 10;
        const int r = (idx >> 3) & 127;
        const int s = idx & 7;
        const __nv_bfloat16* gp = (mat ? g_ql : g_qh) + qoff + r * DH + s * 8;
        CP_ASYNC16(sb + (mat ? OFF_QL : OFF_QH) + r * AROW + s * 16, gp);
    }
    CP_COMMIT();
    storeMask(0, 0);
    issueK(0);
    CP_COMMIT();

    float m0 = -INFINITY, m1 = -INFINITY, l0 = 0.f, l1 = 0.f;
    float co[8][4];
#pragma unroll
    for (int nt = 0; nt < 8; nt++)
#pragma unroll
        for (int r = 0; r < 4; r++) co[nt][r] = 0.f;

    for (int kb = 0; kb < SEQ / 64; kb++) {
        CP_WAIT0();
        __syncthreads();

        issueV(kb);
        CP_COMMIT();

        // ---- S = Q K^T (exp2 domain; scale folded into Q) ----
        float cs[8][4];
#pragma unroll
        for (int nt = 0; nt < 8; nt++)
#pragma unroll
            for (int r = 0; r < 4; r++) cs[nt][r] = 0.f;

#pragma unroll
        for (int ks = 0; ks < 4; ks++) {
            const int kk2 = ks * 32;
            const uint32_t ra = (uint32_t)(wm16 + lr + 8 * lh8) * AROW + kk2 + 16 * lh16;
            uint32_t ah[4], al[4];
            LDSM_X4(ah[0], ah[1], ah[2], ah[3], sb + OFF_QH + ra);
            LDSM_X4(al[0], al[1], al[2], al[3], sb + OFF_QL + ra);
            uint32_t bh[4][4];
#pragma unroll
            for (int np = 0; np < 4; np++) {
                const uint32_t rb = (uint32_t)(np * 16 + lr + 8 * lh16) * AROW + kk2 + 16 * lh8;
                LDSM_X4(bh[np][0], bh[np][1], bh[np][2], bh[np][3], sb + OFF_KH + rb);
            }
#pragma unroll
            for (int np = 0; np < 4; np++) {
                mma_bf16(cs[np * 2 + 0], ah, bh[np][0], bh[np][1]);
                mma_bf16(cs[np * 2 + 1], ah, bh[np][2], bh[np][3]);
            }
#pragma unroll
            for (int np = 0; np < 4; np++) {
                mma_bf16(cs[np * 2 + 0], al, bh[np][0], bh[np][1]);
                mma_bf16(cs[np * 2 + 1], al, bh[np][2], bh[np][3]);
            }
#pragma unroll
            for (int nhh = 0; nhh < 2; nhh++) {
                uint32_t bl[2][4];
#pragma unroll
                for (int j = 0; j < 2; j++) {
                    const int np = nhh * 2 + j;
                    const uint32_t rb = (uint32_t)(np * 16 + lr + 8 * lh16) * AROW + kk2 + 16 * lh8;
                    LDSM_X4(bl[j][0], bl[j][1], bl[j][2], bl[j][3],
                            sb + OFF_KH + 64 * AROW + rb);
                }
#pragma unroll
                for (int j = 0; j < 2; j++) {
                    const int np = nhh * 2 + j;
                    mma_bf16(cs[np * 2 + 0], ah, bl[j][0], bl[j][1]);
                    mma_bf16(cs[np * 2 + 1], ah, bl[j][2], bl[j][3]);
                }
            }
        }

        // ---- mask (fast path: skip when block is all-ones) ----
        const int buf = kb & 1;
        const int masked = *(const int*)(sm + OFF_FLG + buf * 8)
                         | *(const int*)(sm + OFF_FLG + buf * 8 + 4);
        if (masked) {
            const uint32_t mbase = OFF_MSK + buf * 256;
#pragma unroll
            for (int nt = 0; nt < 8; nt++) {
                int2 mv = *(const int2*)(sm + mbase + (nt * 8 + t2) * 4);
                if (!mv.x) { cs[nt][0] = NEGINF; cs[nt][2] = NEGINF; }
                if (!mv.y) { cs[nt][1] = NEGINF; cs[nt][3] = NEGINF; }
            }
        }

        // ---- online softmax, exp2 domain; exp in place (cs becomes P) ----
        float mx0 = NEGINF, mx1 = NEGINF;
#pragma unroll
        for (int nt = 0; nt < 8; nt++) {
            mx0 = fmaxf(mx0, fmaxf(cs[nt][0], cs[nt][1]));
            mx1 = fmaxf(mx1, fmaxf(cs[nt][2], cs[nt][3]));
        }
        mx0 = fmaxf(mx0, __shfl_xor_sync(0xffffffffu, mx0, 1));
        mx0 = fmaxf(mx0, __shfl_xor_sync(0xffffffffu, mx0, 2));
        mx1 = fmaxf(mx1, __shfl_xor_sync(0xffffffffu, mx1, 1));
        mx1 = fmaxf(mx1, __shfl_xor_sync(0xffffffffu, mx1, 2));
        const float mn0 = fmaxf(m0, mx0), mn1 = fmaxf(m1, mx1);
        const float corr0 = exp2f(m0 - mn0), corr1 = exp2f(m1 - mn1);
        float s0 = 0.f, s1 = 0.f;
#pragma unroll
        for (int nt = 0; nt < 8; nt++) {
            cs[nt][0] = exp2f(cs[nt][0] - mn0);
            cs[nt][1] = exp2f(cs[nt][1] - mn0);
            cs[nt][2] = exp2f(cs[nt][2] - mn1);
            cs[nt][3] = exp2f(cs[nt][3] - mn1);
            s0 += cs[nt][0] + cs[nt][1];
            s1 += cs[nt][2] + cs[nt][3];
        }
        s0 += __shfl_xor_sync(0xffffffffu, s0, 1);
        s0 += __shfl_xor_sync(0xffffffffu, s0, 2);
        s1 += __shfl_xor_sync(0xffffffffu, s1, 1);
        s1 += __shfl_xor_sync(0xffffffffu, s1, 2);
        l0 = l0 * corr0 + s0; m0 = mn0;
        l1 = l1 * corr1 + s1; m1 = mn1;
#pragma unroll
        for (int nt = 0; nt < 8; nt++) {
            co[nt][0] *= corr0; co[nt][1] *= corr0;
            co[nt][2] *= corr1; co[nt][3] *= corr1;
        }

        CP_WAIT0();
        __syncthreads();

        if (kb + 1 < SEQ / 64) {
            issueK(kb + 1);
            storeMask(kb + 1, (kb + 1) & 1);
            CP_COMMIT();
        }

        // ---- O += P V (register-resident P, truncation split) ----
#pragma unroll
        for (int kf = 0; kf < 4; kf++) {
            const float p00 = cs[2 * kf][0],     p01 = cs[2 * kf][1];
            const float p02 = cs[2 * kf][2],     p03 = cs[2 * kf][3];
            const float p10 = cs[2 * kf + 1][0], p11 = cs[2 * kf + 1][1];
            const float p12 = cs[2 * kf + 1][2], p13 = cs[2 * kf + 1][3];
            uint32_t ph[4], pl[4];
            ph[0] = hitrunc2(p00, p01);
            ph[1] = hitrunc2(p02, p03);
            ph[2] = hitrunc2(p10, p11);
            ph[3] = hitrunc2(p12, p13);
            pl[0] = pack2(p00 - ftrunc(p00), p01 - ftrunc(p01));
            pl[1] = pack2(p02 - ftrunc(p02), p03 - ftrunc(p03));
            pl[2] = pack2(p10 - ftrunc(p10), p11 - ftrunc(p11));
            pl[3] = pack2(p12 - ftrunc(p12), p13 - ftrunc(p13));

            uint32_t vh[4][4];
#pragma unroll
            for (int np = 0; np < 4; np++) {
                const uint32_t rv = (uint32_t)(kf * 16 + lr + 8 * lh8) * AROW
                                  + np * 32 + 16 * lh16;
                LDSM_X4T(vh[np][0], vh[np][1], vh[np][2], vh[np][3],
                         sb + OFF_KH + 2 * 64 * AROW + rv);
            }
#pragma unroll
            for (int np = 0; np < 4; np++) {
                mma_bf16(co[np * 2 + 0], ph, vh[np][0], vh[np][1]);
                mma_bf16(co[np * 2 + 1], ph, vh[np][2], vh[np][3]);
            }
#pragma unroll
            for (int np = 0; np < 4; np++) {
                mma_bf16(co[np * 2 + 0], pl, vh[np][0], vh[np][1]);
                mma_bf16(co[np * 2 + 1], pl, vh[np][2], vh[np][3]);
            }
#pragma unroll
            for (int nhh = 0; nhh < 2; nhh++) {
                uint32_t vl[2][4];
#pragma unroll
                for (int j = 0; j < 2; j++) {
                    const int np = nhh * 2 + j;
                    const uint32_t rv = (uint32_t)(kf * 16 + lr + 8 * lh8) * AROW
                                      + np * 32 + 16 * lh16;
                    LDSM_X4T(vl[j][0], vl[j][1], vl[j][2], vl[j][3],
                             sb + OFF_KH + 3 * 64 * AROW + rv);
                }
#pragma unroll
                for (int j = 0; j < 2; j++) {
                    const int np = nhh * 2 + j;
                    mma_bf16(co[np * 2 + 0], ph, vl[j][0], vl[j][1]);
                    mma_bf16(co[np * 2 + 1], ph, vl[j][2], vl[j][3]);
                }
            }
        }
    }

    // ---- epilogue: normalize, split, write hi/lo to g_xh/g_xl ----
    const float i0 = 1.f / l0, i1 = 1.f / l1;
    const int r0 = wm16 + g, r1 = wm16 + g + 8;
#pragma unroll
    for (int nt = 0; nt < 8; nt++) {
        const int col = nt * 8 + t2;
        float v0 = co[nt][0] * i0, v1 = co[nt][1] * i0;
        float v2 = co[nt][2] * i1, v3 = co[nt][3] * i1;
        size_t o0 = qoff + (size_t)r0 * DH + col;
        size_t o1 = qoff + (size_t)r1 * DH + col;
        *(__nv_bfloat162*)&g_xh[o0] = hi2(v0, v1);
        *(__nv_bfloat162*)&g_xl[o0] = lo2(v0, v1);
        *(__nv_bfloat162*)&g_xh[o1] = hi2(v2, v3);
        *(__nv_bfloat162*)&g_xl[o1] = lo2(v2, v3);
    }
}

// ---------------------------------------------------------------------------
extern "C" void kernel_launch(void* const* d_in, const int* in_sizes, int n_in,
                              void* d_out, int out_size)
{
    const float* x   = (const float*)d_in[0];
    const int*  mask = (const int*)  d_in[1];
    const float* wq  = (const float*)d_in[2];
    const float* bq  = (const float*)d_in[3];
    const float* wk  = (const float*)d_in[4];
    const float* bk  = (const float*)d_in[5];
    const float* wv  = (const float*)d_in[6];
    const float* bv  = (const float*)d_in[7];
    const float* wo  = (const float*)d_in[8];
    const float* bo  = (const float*)d_in[9];
    float* out = (float*)d_out;

    const int gemm_smem = 2 * STG_BYTES;            // 81920 B
    cudaFuncSetAttribute(gemm_mma, cudaFuncAttributeMaxDynamicSharedMemorySize, gemm_smem);
    cudaFuncSetAttribute(attn_mma, cudaFuncAttributeMaxDynamicSharedMemorySize, ATT_SMEM);

    const int nsplit = (MROWS * DMODEL / 4 + 255) / 256;

    split_bf16<<<nsplit, 256>>>(x);
    transpose_split4<<<dim3(32, 32, 4), dim3(32, 8)>>>(wq, wk, wv, wo);

    // merged QKV projection
    gemm_mma<<<dim3(24, 64), 256, gemm_smem>>>(bq, bk, bv, bo, out, 0);

    attn_mma<<<dim3(SEQ / 128, NB * NHEADS), 256, ATT_SMEM>>>(mask);

    // output projection
    gemm_mma<<<dim3(8, 64), 256, gemm_smem>>>(bq, bk, bv, bo, out, 1);
}

// round 17
// speedup vs baseline: 3.6662x; 1.0142x over previous
#include <cuda_runtime.h>
#include <cuda_bf16.h>
#include <math.h>
#include <stdint.h>

#define NB     4
#define SEQ    2048
#define DMODEL 1024
#define NHEADS 16
#define DH     64
#define MROWS  8192
#define NEGINF -1e30f
#define LOG2E  1.4426950408889634f

// ---------------------------------------------------------------------------
// Static scratch (all projection outputs live as pre-split bf16 hi/lo)
// ---------------------------------------------------------------------------
__device__ __nv_bfloat16 g_xh[MROWS*DMODEL];     // activation hi (also attn out)
__device__ __nv_bfloat16 g_xl[MROWS*DMODEL];     // activation lo
__device__ __nv_bfloat16 g_wth4[4*DMODEL*DMODEL]; // weight^T hi [4][N][K]
__device__ __nv_bfloat16 g_wtl4[4*DMODEL*DMODEL]; // weight^T lo [4][N][K]
__device__ __nv_bfloat16 g_qh[MROWS*DMODEL];     // Q hi (0.125*log2e folded)
__device__ __nv_bfloat16 g_ql[MROWS*DMODEL];
__device__ __nv_bfloat16 g_kh[MROWS*DMODEL];
__device__ __nv_bfloat16 g_kl[MROWS*DMODEL];
__device__ __nv_bfloat16 g_vh[MROWS*DMODEL];
__device__ __nv_bfloat16 g_vl[MROWS*DMODEL];

// ---------------------------------------------------------------------------
// PTX helpers (sm_100 base target)
// ---------------------------------------------------------------------------
__device__ __forceinline__ uint32_t smem_u32(const void* p) {
    uint32_t a;
    asm("{ .reg .u64 t; cvta.to.shared.u64 t, %1; cvt.u32.u64 %0, t; }" : "=r"(a) : "l"(p));
    return a;
}
#define CP_ASYNC16(saddr, gptr) \
    asm volatile("cp.async.cg.shared.global [%0], [%1], 16;" :: "r"(saddr), "l"(gptr))
#define CP_COMMIT() asm volatile("cp.async.commit_group;" ::: "memory")
#define CP_WAIT1()  asm volatile("cp.async.wait_group 1;" ::: "memory")
#define CP_WAIT0()  asm volatile("cp.async.wait_group 0;" ::: "memory")

#define LDSM_X4(r0, r1, r2, r3, addr) \
    asm volatile("ldmatrix.sync.aligned.m8n8.x4.shared.b16 {%0,%1,%2,%3}, [%4];" \
        : "=r"(r0), "=r"(r1), "=r"(r2), "=r"(r3) : "r"(addr))
#define LDSM_X4T(r0, r1, r2, r3, addr) \
    asm volatile("ldmatrix.sync.aligned.m8n8.x4.trans.shared.b16 {%0,%1,%2,%3}, [%4];" \
        : "=r"(r0), "=r"(r1), "=r"(r2), "=r"(r3) : "r"(addr))

__device__ __forceinline__ void mma_bf16(float* c, const uint32_t* a,
                                         uint32_t b0, uint32_t b1) {
    asm volatile(
        "mma.sync.aligned.m16n8k16.row.col.f32.bf16.bf16.f32 "
        "{%0,%1,%2,%3}, {%4,%5,%6,%7}, {%8,%9}, {%0,%1,%2,%3};"
        : "+f"(c[0]), "+f"(c[1]), "+f"(c[2]), "+f"(c[3])
        : "r"(a[0]), "r"(a[1]), "r"(a[2]), "r"(a[3]), "r"(b0), "r"(b1));
}

__device__ __forceinline__ __nv_bfloat162 hi2(float a, float b) {
    return __halves2bfloat162(__float2bfloat16(a), __float2bfloat16(b));
}
__device__ __forceinline__ __nv_bfloat162 lo2(float a, float b) {
    __nv_bfloat16 ha = __float2bfloat16(a), hb = __float2bfloat16(b);
    return __halves2bfloat162(__float2bfloat16(a - __bfloat162float(ha)),
                              __float2bfloat16(b - __bfloat162float(hb)));
}

// Truncation split helpers (hot path): hi = bits&0xFFFF0000 (exact, Sterbenz
// makes lo = f - hi exact in fp32). One PRMT packs two hi's.
__device__ __forceinline__ uint32_t hitrunc2(float a, float b) {
    uint32_t r;
    asm("prmt.b32 %0, %1, %2, 0x7632;"
        : "=r"(r) : "r"(__float_as_uint(a)), "r"(__float_as_uint(b)));
    return r;
}
__device__ __forceinline__ float ftrunc(float a) {
    return __uint_as_float(__float_as_uint(a) & 0xFFFF0000u);
}
__device__ __forceinline__ uint32_t pack2(float a, float b) {  // {lo=a, hi=b}
    uint32_t r;
    asm("cvt.rn.bf16x2.f32 %0, %1, %2;" : "=r"(r) : "f"(b), "f"(a));
    return r;
}

// ---------------------------------------------------------------------------
// fp32 -> bf16 hi/lo split of x
// ---------------------------------------------------------------------------
__global__ __launch_bounds__(256) void split_bf16(const float* __restrict__ src) {
    size_t i4 = ((size_t)blockIdx.x * 256 + threadIdx.x) * 4;
    if (i4 >= (size_t)MROWS * DMODEL) return;
    float4 v = *(const float4*)(src + i4);
    float a[4] = {v.x, v.y, v.z, v.w};
#pragma unroll
    for (int j = 0; j < 4; j++) {
        __nv_bfloat16 hi = __float2bfloat16(a[j]);
        __nv_bfloat16 lo = __float2bfloat16(a[j] - __bfloat162float(hi));
        g_xh[i4 + j] = hi;
        g_xl[i4 + j] = lo;
    }
}

// ---------------------------------------------------------------------------
// All-four weight transpose + split
// ---------------------------------------------------------------------------
__global__ __launch_bounds__(256) void transpose_split4(
    const float* __restrict__ wq, const float* __restrict__ wk,
    const float* __restrict__ wv, const float* __restrict__ wo) {
    __shared__ float t[32][33];
    const int tx = threadIdx.x, ty = threadIdx.y;    // 32 x 8
    const int n0 = blockIdx.x * 32, k0 = blockIdx.y * 32;
    const int z = blockIdx.z;
    const float* w = (z == 0) ? wq : (z == 1) ? wk : (z == 2) ? wv : wo;
    __nv_bfloat16* H = g_wth4 + (size_t)z * DMODEL * DMODEL;
    __nv_bfloat16* L = g_wtl4 + (size_t)z * DMODEL * DMODEL;
#pragma unroll
    for (int i = 0; i < 4; i++)
        t[ty + i * 8][tx] = w[(size_t)(k0 + ty + i * 8) * DMODEL + n0 + tx];
    __syncthreads();
#pragma unroll
    for (int i = 0; i < 4; i++) {
        float v = t[tx][ty + i * 8];
        __nv_bfloat16 hi = __float2bfloat16(v);
        __nv_bfloat16 lo = __float2bfloat16(v - __bfloat162float(hi));
        size_t o = (size_t)(n0 + ty + i * 8) * DMODEL + (k0 + tx);
        H[o] = hi;
        L[o] = lo;
    }
}

// ---------------------------------------------------------------------------
// mma.sync bf16-split GEMM (unchanged from R15)
// ---------------------------------------------------------------------------
#define MAT_BYTES   10240
#define STG_BYTES   40960
#define ROW_B       80
#define NCHUNK      32

__global__ __launch_bounds__(256, 2) void gemm_mma(
    const float* __restrict__ biasQ, const float* __restrict__ biasK,
    const float* __restrict__ biasV, const float* __restrict__ biasO,
    float* __restrict__ Cext, int mode) {
    extern __shared__ char smem[];
    const uint32_t sb = smem_u32(smem);
    const int tid  = threadIdx.x;
    const int wid  = tid >> 5;
    const int lane = tid & 31;
    const int wm = wid & 3;
    const int wn = wid >> 2;
    const int wsel    = (mode == 0) ? (blockIdx.x >> 3) : 3;
    const int dst_sel = (mode == 0) ? wsel : 3;
    const float* bias = (mode == 1) ? biasO
                      : (wsel == 0) ? biasQ : (wsel == 1) ? biasK : biasV;
    const int bn = (mode == 0 ? (blockIdx.x & 7) : blockIdx.x) * 128;
    const int bm = blockIdx.y * 128;
    const __nv_bfloat16* WH = g_wth4 + (size_t)wsel * DMODEL * DMODEL;
    const __nv_bfloat16* WL = g_wtl4 + (size_t)wsel * DMODEL * DMODEL;

    float c[2][8][4];
#pragma unroll
    for (int mt = 0; mt < 2; mt++)
#pragma unroll
        for (int nt = 0; nt < 8; nt++)
#pragma unroll
            for (int r = 0; r < 4; r++) c[mt][nt][r] = 0.f;

    auto issue = [&](int chunk, int stage) {
        const int k0 = chunk * 32;
        const uint32_t stg = sb + stage * STG_BYTES;
#pragma unroll
        for (int i = 0; i < 8; i++) {
            const int idx = i * 256 + tid;
            const int mat = idx >> 9;
            const int row = (idx >> 2) & 127;
            const int seg = idx & 3;
            const uint32_t sa = stg + mat * MAT_BYTES + row * ROW_B + seg * 16;
            const __nv_bfloat16* gp;
            if (mat == 0)      gp = g_xh + (size_t)(bm + row) * DMODEL + k0 + seg * 8;
            else if (mat == 1) gp = g_xl + (size_t)(bm + row) * DMODEL + k0 + seg * 8;
            else if (mat == 2) gp = WH   + (size_t)(bn + row) * DMODEL + k0 + seg * 8;
            else               gp = WL   + (size_t)(bn + row) * DMODEL + k0 + seg * 8;
            CP_ASYNC16(sa, gp);
        }
        CP_COMMIT();
    };

    issue(0, 0);

    const int lr  = lane & 7;
    const int lh8 = (lane >> 3) & 1;
    const int lh16 = lane >> 4;

    for (int chunk = 0; chunk < NCHUNK; chunk++) {
        if (chunk + 1 < NCHUNK) issue(chunk + 1, (chunk + 1) & 1);
        if (chunk + 1 < NCHUNK) { CP_WAIT1(); } else { CP_WAIT0(); }
        __syncthreads();

        const uint32_t stg = sb + (chunk & 1) * STG_BYTES;
        const uint32_t Ah = stg;
        const uint32_t Al = stg + MAT_BYTES;
        const uint32_t Bh = stg + 2 * MAT_BYTES;
        const uint32_t Bl = stg + 3 * MAT_BYTES;

#pragma unroll
        for (int ks = 0; ks < 2; ks++) {
            const int kb = ks * 32;
            uint32_t ah[2][4], al[2][4];
#pragma unroll
            for (int mt = 0; mt < 2; mt++) {
                const uint32_t ra = (uint32_t)(wm * 32 + mt * 16 + lr + 8 * lh8) * ROW_B
                                  + kb + 16 * lh16;
                LDSM_X4(ah[mt][0], ah[mt][1], ah[mt][2], ah[mt][3], Ah + ra);
                LDSM_X4(al[mt][0], al[mt][1], al[mt][2], al[mt][3], Al + ra);
            }
            uint32_t bh[4][4];
#pragma unroll
            for (int np = 0; np < 4; np++) {
                const uint32_t rb = (uint32_t)(wn * 64 + np * 16 + lr + 8 * lh16) * ROW_B
                                  + kb + 16 * lh8;
                LDSM_X4(bh[np][0], bh[np][1], bh[np][2], bh[np][3], Bh + rb);
            }
#pragma unroll
            for (int np = 0; np < 4; np++)
#pragma unroll
                for (int mt = 0; mt < 2; mt++) {
                    mma_bf16(c[mt][np * 2 + 0], ah[mt], bh[np][0], bh[np][1]);
                    mma_bf16(c[mt][np * 2 + 1], ah[mt], bh[np][2], bh[np][3]);
                }
#pragma unroll
            for (int np = 0; np < 4; np++)
#pragma unroll
                for (int mt = 0; mt < 2; mt++) {
                    mma_bf16(c[mt][np * 2 + 0], al[mt], bh[np][0], bh[np][1]);
                    mma_bf16(c[mt][np * 2 + 1], al[mt], bh[np][2], bh[np][3]);
                }
#pragma unroll
            for (int nh = 0; nh < 2; nh++) {
                uint32_t bl[2][4];
#pragma unroll
                for (int j = 0; j < 2; j++) {
                    const int np = nh * 2 + j;
                    const uint32_t rb = (uint32_t)(wn * 64 + np * 16 + lr + 8 * lh16) * ROW_B
                                      + kb + 16 * lh8;
                    LDSM_X4(bl[j][0], bl[j][1], bl[j][2], bl[j][3], Bl + rb);
                }
#pragma unroll
                for (int j = 0; j < 2; j++) {
                    const int np = nh * 2 + j;
#pragma unroll
                    for (int mt = 0; mt < 2; mt++) {
                        mma_bf16(c[mt][np * 2 + 0], ah[mt], bl[j][0], bl[j][1]);
                        mma_bf16(c[mt][np * 2 + 1], ah[mt], bl[j][2], bl[j][3]);
                    }
                }
            }
        }
        __syncthreads();
    }

    const int rg = lane >> 2;
    const int cg = (lane & 3) * 2;
    if (dst_sel == 3) {
#pragma unroll
        for (int mt = 0; mt < 2; mt++)
#pragma unroll
            for (int nt = 0; nt < 8; nt++) {
                const int row = bm + wm * 32 + mt * 16 + rg;
                const int col = bn + wn * 64 + nt * 8 + cg;
                const float b0 = bias[col], b1 = bias[col + 1];
                *(float2*)&Cext[(size_t)row * DMODEL + col] =
                    make_float2(c[mt][nt][0] + b0, c[mt][nt][1] + b1);
                *(float2*)&Cext[(size_t)(row + 8) * DMODEL + col] =
                    make_float2(c[mt][nt][2] + b0, c[mt][nt][3] + b1);
            }
    } else {
        __nv_bfloat16* H = (dst_sel == 0) ? g_qh : (dst_sel == 1) ? g_kh : g_vh;
        __nv_bfloat16* L = (dst_sel == 0) ? g_ql : (dst_sel == 1) ? g_kl : g_vl;
        const float scl = (dst_sel == 0) ? 0.125f * LOG2E : 1.f;
#pragma unroll
        for (int mt = 0; mt < 2; mt++)
#pragma unroll
            for (int nt = 0; nt < 8; nt++) {
                const int row = bm + wm * 32 + mt * 16 + rg;
                const int col = bn + wn * 64 + nt * 8 + cg;
                const float b0 = bias[col], b1 = bias[col + 1];
                float v0 = (c[mt][nt][0] + b0) * scl, v1 = (c[mt][nt][1] + b1) * scl;
                float v2 = (c[mt][nt][2] + b0) * scl, v3 = (c[mt][nt][3] + b1) * scl;
                size_t o0 = (size_t)row * DMODEL + col;
                size_t o1 = (size_t)(row + 8) * DMODEL + col;
                *(__nv_bfloat162*)&H[o0] = hi2(v0, v1);
                *(__nv_bfloat162*)&L[o0] = lo2(v0, v1);
                *(__nv_bfloat162*)&H[o1] = hi2(v2, v3);
                *(__nv_bfloat162*)&L[o1] = lo2(v2, v3);
            }
    }
}

// ---------------------------------------------------------------------------
// Tensor-core flash attention: register-resident P, exp2 softmax with
// exp/pack INTERLEAVED into the PV MMA stream (fills the tensor-pipe bubble
// that the phase-locked softmax serial section created). Sum reductions and
// l/m updates deferred until after the PV loop.
// ---------------------------------------------------------------------------
#define AROW    144
#define OFF_QH  0
#define OFF_QL  (128*AROW)
#define OFF_KH  (2*128*AROW)
#define OFF_MSK (OFF_KH + 4*64*AROW)
#define OFF_FLG (OFF_MSK + 512)           // 2 buffers x 2 warp-flag words
#define ATT_SMEM (OFF_FLG + 16)

__global__ __launch_bounds__(256, 2) void attn_mma(const int* __restrict__ mask)
{
    extern __shared__ char sm[];
    const uint32_t sb = smem_u32(sm);
    const int tid  = threadIdx.x;
    const int wid  = tid >> 5;
    const int lane = tid & 31;
    const int lr   = lane & 7;
    const int lh8  = (lane >> 3) & 1;
    const int lh16 = lane >> 4;
    const int g    = lane >> 2;
    const int t2   = (lane & 3) * 2;
    const int wm16 = wid * 16;

    const int nh = blockIdx.y;
    const int nb = nh >> 4;
    const int qt = blockIdx.x;
    const size_t hb = (size_t)nh * SEQ * DH;
    const size_t qoff = hb + (size_t)qt * 128 * DH;
    const int* mk = mask + nb * SEQ;

    auto issueK = [&](int kb) {
#pragma unroll
        for (int i = 0; i < 4; i++) {
            const int idx = i * 256 + tid;
            const int mat = idx >> 9;
            const int r = (idx >> 3) & 63;
            const int s = idx & 7;
            const __nv_bfloat16* gb = mat ? g_kl : g_kh;
            CP_ASYNC16(sb + OFF_KH + mat * 64 * AROW + r * AROW + s * 16,
                       gb + hb + (size_t)(kb * 64 + r) * DH + s * 8);
        }
    };
    auto issueV = [&](int kb) {
#pragma unroll
        for (int i = 0; i < 4; i++) {
            const int idx = i * 256 + tid;
            const int mat = idx >> 9;
            const int r = (idx >> 3) & 63;
            const int s = idx & 7;
            const __nv_bfloat16* gb = mat ? g_vl : g_vh;
            CP_ASYNC16(sb + OFF_KH + (2 + mat) * 64 * AROW + r * AROW + s * 16,
                       gb + hb + (size_t)(kb * 64 + r) * DH + s * 8);
        }
    };
    auto storeMask = [&](int kb, int buf) {
        if (tid < 64) {
            int v = mk[kb * 64 + tid];
            *(int*)(sm + OFF_MSK + buf * 256 + tid * 4) = v;
            uint32_t bal = __ballot_sync(0xffffffffu, v == 0);
            if (lane == 0)
                *(int*)(sm + OFF_FLG + buf * 8 + (tid >> 5) * 4) = (bal != 0);
        }
    };

    // ---- pre-loop: Q tile + K_0 + mask_0 ----
#pragma unroll
    for (int i = 0; i < 8; i++) {
        const int idx = i * 256 + tid;
        const int mat = idx >> 10;
        const int r = (idx >> 3) & 127;
        const int s = idx & 7;
        const __nv_bfloat16* gp = (mat ? g_ql : g_qh) + qoff + r * DH + s * 8;
        CP_ASYNC16(sb + (mat ? OFF_QL : OFF_QH) + r * AROW + s * 16, gp);
    }
    CP_COMMIT();
    storeMask(0, 0);
    issueK(0);
    CP_COMMIT();

    float m0 = -INFINITY, m1 = -INFINITY, l0 = 0.f, l1 = 0.f;
    float co[8][4];
#pragma unroll
    for (int nt = 0; nt < 8; nt++)
#pragma unroll
        for (int r = 0; r < 4; r++) co[nt][r] = 0.f;

    for (int kb = 0; kb < SEQ / 64; kb++) {
        CP_WAIT0();
        __syncthreads();

        issueV(kb);
        CP_COMMIT();

        // ---- S = Q K^T ----
        float cs[8][4];
#pragma unroll
        for (int nt = 0; nt < 8; nt++)
#pragma unroll
            for (int r = 0; r < 4; r++) cs[nt][r] = 0.f;

#pragma unroll
        for (int ks = 0; ks < 4; ks++) {
            const int kk2 = ks * 32;
            const uint32_t ra = (uint32_t)(wm16 + lr + 8 * lh8) * AROW + kk2 + 16 * lh16;
            uint32_t ah[4], al[4];
            LDSM_X4(ah[0], ah[1], ah[2], ah[3], sb + OFF_QH + ra);
            LDSM_X4(al[0], al[1], al[2], al[3], sb + OFF_QL + ra);
            uint32_t bh[4][4];
#pragma unroll
            for (int np = 0; np < 4; np++) {
                const uint32_t rb = (uint32_t)(np * 16 + lr + 8 * lh16) * AROW + kk2 + 16 * lh8;
                LDSM_X4(bh[np][0], bh[np][1], bh[np][2], bh[np][3], sb + OFF_KH + rb);
            }
#pragma unroll
            for (int np = 0; np < 4; np++) {
                mma_bf16(cs[np * 2 + 0], ah, bh[np][0], bh[np][1]);
                mma_bf16(cs[np * 2 + 1], ah, bh[np][2], bh[np][3]);
            }
#pragma unroll
            for (int np = 0; np < 4; np++) {
                mma_bf16(cs[np * 2 + 0], al, bh[np][0], bh[np][1]);
                mma_bf16(cs[np * 2 + 1], al, bh[np][2], bh[np][3]);
            }
#pragma unroll
            for (int nhh = 0; nhh < 2; nhh++) {
                uint32_t bl[2][4];
#pragma unroll
                for (int j = 0; j < 2; j++) {
                    const int np = nhh * 2 + j;
                    const uint32_t rb = (uint32_t)(np * 16 + lr + 8 * lh16) * AROW + kk2 + 16 * lh8;
                    LDSM_X4(bl[j][0], bl[j][1], bl[j][2], bl[j][3],
                            sb + OFF_KH + 64 * AROW + rb);
                }
#pragma unroll
                for (int j = 0; j < 2; j++) {
                    const int np = nhh * 2 + j;
                    mma_bf16(cs[np * 2 + 0], ah, bl[j][0], bl[j][1]);
                    mma_bf16(cs[np * 2 + 1], ah, bl[j][2], bl[j][3]);
                }
            }
        }

        // ---- mask (fast path: skip when block is all-ones) ----
        const int buf = kb & 1;
        const int masked = *(const int*)(sm + OFF_FLG + buf * 8)
                         | *(const int*)(sm + OFF_FLG + buf * 8 + 4);
        if (masked) {
            const uint32_t mbase = OFF_MSK + buf * 256;
#pragma unroll
            for (int nt = 0; nt < 8; nt++) {
                int2 mv = *(const int2*)(sm + mbase + (nt * 8 + t2) * 4);
                if (!mv.x) { cs[nt][0] = NEGINF; cs[nt][2] = NEGINF; }
                if (!mv.y) { cs[nt][1] = NEGINF; cs[nt][3] = NEGINF; }
            }
        }

        // ---- max reduce + corr (the only part PV truly waits on) ----
        float mx0 = NEGINF, mx1 = NEGINF;
#pragma unroll
        for (int nt = 0; nt < 8; nt++) {
            mx0 = fmaxf(mx0, fmaxf(cs[nt][0], cs[nt][1]));
            mx1 = fmaxf(mx1, fmaxf(cs[nt][2], cs[nt][3]));
        }
        mx0 = fmaxf(mx0, __shfl_xor_sync(0xffffffffu, mx0, 1));
        mx0 = fmaxf(mx0, __shfl_xor_sync(0xffffffffu, mx0, 2));
        mx1 = fmaxf(mx1, __shfl_xor_sync(0xffffffffu, mx1, 1));
        mx1 = fmaxf(mx1, __shfl_xor_sync(0xffffffffu, mx1, 2));
        const float mn0 = fmaxf(m0, mx0), mn1 = fmaxf(m1, mx1);
        const float corr0 = exp2f(m0 - mn0), corr1 = exp2f(m1 - mn1);

        // ---- V ready; K consumers done; prefetch next K ----
        CP_WAIT0();
        __syncthreads();
        if (kb + 1 < SEQ / 64) {
            issueK(kb + 1);
            storeMask(kb + 1, (kb + 1) & 1);
            CP_COMMIT();
        }

        // ---- rescale O ----
#pragma unroll
        for (int nt = 0; nt < 8; nt++) {
            co[nt][0] *= corr0; co[nt][1] *= corr0;
            co[nt][2] *= corr1; co[nt][3] *= corr1;
        }

        // ---- interleaved exp2 + pack + PV: exp(kf+1) hides under MMA(kf) ----
        float s0 = 0.f, s1 = 0.f;
#pragma unroll
        for (int kf = 0; kf < 4; kf++) {
            float p00 = exp2f(cs[2 * kf][0] - mn0);
            float p01 = exp2f(cs[2 * kf][1] - mn0);
            float p02 = exp2f(cs[2 * kf][2] - mn1);
            float p03 = exp2f(cs[2 * kf][3] - mn1);
            float p10 = exp2f(cs[2 * kf + 1][0] - mn0);
            float p11 = exp2f(cs[2 * kf + 1][1] - mn0);
            float p12 = exp2f(cs[2 * kf + 1][2] - mn1);
            float p13 = exp2f(cs[2 * kf + 1][3] - mn1);
            s0 += p00 + p01 + p10 + p11;
            s1 += p02 + p03 + p12 + p13;

            uint32_t ph[4], pl[4];
            ph[0] = hitrunc2(p00, p01);
            ph[1] = hitrunc2(p02, p03);
            ph[2] = hitrunc2(p10, p11);
            ph[3] = hitrunc2(p12, p13);
            pl[0] = pack2(p00 - ftrunc(p00), p01 - ftrunc(p01));
            pl[1] = pack2(p02 - ftrunc(p02), p03 - ftrunc(p03));
            pl[2] = pack2(p10 - ftrunc(p10), p11 - ftrunc(p11));
            pl[3] = pack2(p12 - ftrunc(p12), p13 - ftrunc(p13));

            uint32_t vh[4][4];
#pragma unroll
            for (int np = 0; np < 4; np++) {
                const uint32_t rv = (uint32_t)(kf * 16 + lr + 8 * lh8) * AROW
                                  + np * 32 + 16 * lh16;
                LDSM_X4T(vh[np][0], vh[np][1], vh[np][2], vh[np][3],
                         sb + OFF_KH + 2 * 64 * AROW + rv);
            }
#pragma unroll
            for (int np = 0; np < 4; np++) {
                mma_bf16(co[np * 2 + 0], ph, vh[np][0], vh[np][1]);
                mma_bf16(co[np * 2 + 1], ph, vh[np][2], vh[np][3]);
            }
#pragma unroll
            for (int np = 0; np < 4; np++) {
                mma_bf16(co[np * 2 + 0], pl, vh[np][0], vh[np][1]);
                mma_bf16(co[np * 2 + 1], pl, vh[np][2], vh[np][3]);
            }
#pragma unroll
            for (int nhh = 0; nhh < 2; nhh++) {
                uint32_t vl[2][4];
#pragma unroll
                for (int j = 0; j < 2; j++) {
                    const int np = nhh * 2 + j;
                    const uint32_t rv = (uint32_t)(kf * 16 + lr + 8 * lh8) * AROW
                                      + np * 32 + 16 * lh16;
                    LDSM_X4T(vl[j][0], vl[j][1], vl[j][2], vl[j][3],
                             sb + OFF_KH + 3 * 64 * AROW + rv);
                }
#pragma unroll
                for (int j = 0; j < 2; j++) {
                    const int np = nhh * 2 + j;
                    mma_bf16(co[np * 2 + 0], ph, vl[j][0], vl[j][1]);
                    mma_bf16(co[np * 2 + 1], ph, vl[j][2], vl[j][3]);
                }
            }
        }

        // ---- deferred reductions and state update ----
        s0 += __shfl_xor_sync(0xffffffffu, s0, 1);
        s0 += __shfl_xor_sync(0xffffffffu, s0, 2);
        s1 += __shfl_xor_sync(0xffffffffu, s1, 1);
        s1 += __shfl_xor_sync(0xffffffffu, s1, 2);
        l0 = l0 * corr0 + s0; m0 = mn0;
        l1 = l1 * corr1 + s1; m1 = mn1;
    }

    // ---- epilogue: normalize, split, write hi/lo to g_xh/g_xl ----
    const float i0 = 1.f / l0, i1 = 1.f / l1;
    const int r0 = wm16 + g, r1 = wm16 + g + 8;
#pragma unroll
    for (int nt = 0; nt < 8; nt++) {
        const int col = nt * 8 + t2;
        float v0 = co[nt][0] * i0, v1 = co[nt][1] * i0;
        float v2 = co[nt][2] * i1, v3 = co[nt][3] * i1;
        size_t o0 = qoff + (size_t)r0 * DH + col;
        size_t o1 = qoff + (size_t)r1 * DH + col;
        *(__nv_bfloat162*)&g_xh[o0] = hi2(v0, v1);
        *(__nv_bfloat162*)&g_xl[o0] = lo2(v0, v1);
        *(__nv_bfloat162*)&g_xh[o1] = hi2(v2, v3);
        *(__nv_bfloat162*)&g_xl[o1] = lo2(v2, v3);
    }
}

// ---------------------------------------------------------------------------
extern "C" void kernel_launch(void* const* d_in, const int* in_sizes, int n_in,
                              void* d_out, int out_size)
{
    const float* x   = (const float*)d_in[0];
    const int*  mask = (const int*)  d_in[1];
    const float* wq  = (const float*)d_in[2];
    const float* bq  = (const float*)d_in[3];
    const float* wk  = (const float*)d_in[4];
    const float* bk  = (const float*)d_in[5];
    const float* wv  = (const float*)d_in[6];
    const float* bv  = (const float*)d_in[7];
    const float* wo  = (const float*)d_in[8];
    const float* bo  = (const float*)d_in[9];
    float* out = (float*)d_out;

    const int gemm_smem = 2 * STG_BYTES;            // 81920 B
    cudaFuncSetAttribute(gemm_mma, cudaFuncAttributeMaxDynamicSharedMemorySize, gemm_smem);
    cudaFuncSetAttribute(attn_mma, cudaFuncAttributeMaxDynamicSharedMemorySize, ATT_SMEM);

    const int nsplit = (MROWS * DMODEL / 4 + 255) / 256;

    split_bf16<<<nsplit, 256>>>(x);
    transpose_split4<<<dim3(32, 32, 4), dim3(32, 8)>>>(wq, wk, wv, wo);

    // merged QKV projection
    gemm_mma<<<dim3(24, 64), 256, gemm_smem>>>(bq, bk, bv, bo, out, 0);

    attn_mma<<<dim3(SEQ / 128, NB * NHEADS), 256, ATT_SMEM>>>(mask);

    // output projection
    gemm_mma<<<dim3(8, 64), 256, gemm_smem>>>(bq, bk, bv, bo, out, 1);
}